// round 1
// baseline (speedup 1.0000x reference)
#include <cuda_runtime.h>
#include <math.h>

// ---------------- problem constants ----------------
#define NB    2
#define SEQ   2048
#define TOK   4096          // NB*SEQ
#define DMODEL 1024
#define NH    16
#define HD    64
#define FFD   4096
#define LN_EPS 1e-5f

// ---------------- scratch (device globals; no allocation) ----------------
__device__ float g_h   [TOK * DMODEL];      // LN output         16 MB
__device__ float g_qkv [TOK * 3 * DMODEL];  // QKV               48 MB
__device__ float g_att [TOK * DMODEL];      // attention output  16 MB
__device__ float g_x1  [TOK * DMODEL];      // post-attn residual 16 MB
__device__ float g_ffh [TOK * FFD];         // MLP hidden        64 MB

// ====================================================================
// LayerNorm: one block per row (1024 floats), 256 threads, two-pass.
// ====================================================================
__global__ __launch_bounds__(256) void ln_kernel(
    const float* __restrict__ x, const float* __restrict__ g,
    const float* __restrict__ b, float* __restrict__ y)
{
    __shared__ float red[8];
    __shared__ float bc[2];
    const int r = blockIdx.x, tid = threadIdx.x;
    const int wid = tid >> 5, lane = tid & 31;

    const float4 v = ((const float4*)(x + (size_t)r * DMODEL))[tid];

    // pass 1: mean
    float s = v.x + v.y + v.z + v.w;
    #pragma unroll
    for (int o = 16; o; o >>= 1) s += __shfl_xor_sync(0xffffffffu, s, o);
    if (lane == 0) red[wid] = s;
    __syncthreads();
    if (tid == 0) {
        float t = 0.f;
        #pragma unroll
        for (int i = 0; i < 8; ++i) t += red[i];
        bc[0] = t * (1.0f / DMODEL);
    }
    __syncthreads();
    const float mean = bc[0];

    // pass 2: variance (population)
    const float dx = v.x - mean, dy = v.y - mean, dz = v.z - mean, dw = v.w - mean;
    float ss = dx * dx + dy * dy + dz * dz + dw * dw;
    #pragma unroll
    for (int o = 16; o; o >>= 1) ss += __shfl_xor_sync(0xffffffffu, ss, o);
    if (lane == 0) red[wid] = ss;
    __syncthreads();
    if (tid == 0) {
        float t = 0.f;
        #pragma unroll
        for (int i = 0; i < 8; ++i) t += red[i];
        bc[1] = rsqrtf(t * (1.0f / DMODEL) + LN_EPS);
    }
    __syncthreads();
    const float rs = bc[1];

    const float4 gv = ((const float4*)g)[tid];
    const float4 bv = ((const float4*)b)[tid];
    float4 o4;
    o4.x = dx * rs * gv.x + bv.x;
    o4.y = dy * rs * gv.y + bv.y;
    o4.z = dz * rs * gv.z + bv.z;
    o4.w = dw * rs * gv.w + bv.w;
    ((float4*)(y + (size_t)r * DMODEL))[tid] = o4;
}

// ====================================================================
// SGEMM (NT): C[M,N] = A[M,K] * B[N,K]^T + bias[N]  (+residual, +GELU)
// 128x128 tile, BK=16, 256 threads, 8x8 per thread, float4 everywhere.
// All dims are multiples of 128/16 here, so no bounds checks.
// ====================================================================
template<bool GELU, bool RES>
__global__ __launch_bounds__(256) void sgemm_nt(
    const float* __restrict__ A, const float* __restrict__ B,
    const float* __restrict__ bias, const float* __restrict__ res,
    float* __restrict__ C, int M, int N, int K)
{
    __shared__ float As[16][128];
    __shared__ float Bs[16][128];

    const int tid = threadIdx.x;
    const int m0 = blockIdx.y << 7;
    const int n0 = blockIdx.x << 7;
    const int ra = (tid >> 4) << 2;   // thread row base (0..60)
    const int cb = (tid & 15) << 2;   // thread col base (0..60)

    const int lrow = tid >> 2;        // 0..63
    const int lk   = (tid & 3) << 2;  // 0,4,8,12

    const float* Ap = A + (size_t)(m0 + lrow) * K + lk;
    const float* Bp = B + (size_t)(n0 + lrow) * K + lk;

    float acc[8][8];
    #pragma unroll
    for (int i = 0; i < 8; ++i)
        #pragma unroll
        for (int j = 0; j < 8; ++j) acc[i][j] = 0.f;

    for (int kt = 0; kt < K; kt += 16) {
        const float4 a0 = *(const float4*)(Ap + kt);
        const float4 a1 = *(const float4*)(Ap + (size_t)64 * K + kt);
        const float4 b0 = *(const float4*)(Bp + kt);
        const float4 b1 = *(const float4*)(Bp + (size_t)64 * K + kt);
        __syncthreads();
        As[lk + 0][lrow] = a0.x; As[lk + 1][lrow] = a0.y;
        As[lk + 2][lrow] = a0.z; As[lk + 3][lrow] = a0.w;
        As[lk + 0][lrow + 64] = a1.x; As[lk + 1][lrow + 64] = a1.y;
        As[lk + 2][lrow + 64] = a1.z; As[lk + 3][lrow + 64] = a1.w;
        Bs[lk + 0][lrow] = b0.x; Bs[lk + 1][lrow] = b0.y;
        Bs[lk + 2][lrow] = b0.z; Bs[lk + 3][lrow] = b0.w;
        Bs[lk + 0][lrow + 64] = b1.x; Bs[lk + 1][lrow + 64] = b1.y;
        Bs[lk + 2][lrow + 64] = b1.z; Bs[lk + 3][lrow + 64] = b1.w;
        __syncthreads();

        #pragma unroll
        for (int kk = 0; kk < 16; ++kk) {
            const float4 xa0 = *(const float4*)&As[kk][ra];
            const float4 xa1 = *(const float4*)&As[kk][ra + 64];
            const float4 xb0 = *(const float4*)&Bs[kk][cb];
            const float4 xb1 = *(const float4*)&Bs[kk][cb + 64];
            const float av[8] = {xa0.x, xa0.y, xa0.z, xa0.w, xa1.x, xa1.y, xa1.z, xa1.w};
            const float bv[8] = {xb0.x, xb0.y, xb0.z, xb0.w, xb1.x, xb1.y, xb1.z, xb1.w};
            #pragma unroll
            for (int i = 0; i < 8; ++i)
                #pragma unroll
                for (int j = 0; j < 8; ++j)
                    acc[i][j] += av[i] * bv[j];
        }
    }

    // epilogue
    #pragma unroll
    for (int ii = 0; ii < 2; ++ii) {
        #pragma unroll
        for (int i = 0; i < 4; ++i) {
            const int r = ii * 4 + i;
            const int gm = m0 + ra + ii * 64 + i;
            #pragma unroll
            for (int jj = 0; jj < 2; ++jj) {
                const int gn = n0 + cb + jj * 64;
                float4 o;
                o.x = acc[r][jj * 4 + 0] + bias[gn + 0];
                o.y = acc[r][jj * 4 + 1] + bias[gn + 1];
                o.z = acc[r][jj * 4 + 2] + bias[gn + 2];
                o.w = acc[r][jj * 4 + 3] + bias[gn + 3];
                if (RES) {
                    const float4 rv = *(const float4*)&res[(size_t)gm * N + gn];
                    o.x += rv.x; o.y += rv.y; o.z += rv.z; o.w += rv.w;
                }
                if (GELU) {
                    o.x = 0.5f * o.x * (1.0f + erff(o.x * 0.70710678118654752f));
                    o.y = 0.5f * o.y * (1.0f + erff(o.y * 0.70710678118654752f));
                    o.z = 0.5f * o.z * (1.0f + erff(o.z * 0.70710678118654752f));
                    o.w = 0.5f * o.w * (1.0f + erff(o.w * 0.70710678118654752f));
                }
                *(float4*)&C[(size_t)gm * N + gn] = o;
            }
        }
    }
}

// ====================================================================
// Flash attention (fp32, online softmax).
// qkv layout per token: [H][192] = [q(64) | k(64) | v(64)]
// grid (SEQ/64, NH, NB); 256 threads; each block: 64 q-rows x HD=64.
// Thread (ty,tx) ty=tid/16, tx=tid%15 owns 4x4 of each 64x64 tile.
// ====================================================================
#define SQP 68   // padded row stride (multiple of 4 -> float4-aligned)

__global__ __launch_bounds__(256) void attn_kernel(
    const float* __restrict__ qkv, float* __restrict__ out)
{
    extern __shared__ float sm[];
    float* Qt = sm;               // [64][SQP]  Qt[d][r]   (pre-scaled by 1/8)
    float* Kt = Qt + 64 * SQP;    // [64][SQP]  Kt[d][c]
    float* Vs = Kt + 64 * SQP;    // [64][SQP]  Vs[c][d]
    float* Ps = Vs + 64 * SQP;    // [64][SQP]  Ps[r][c]

    const int tid = threadIdx.x;
    const int ty4 = (tid >> 4) << 2;   // 4*ty
    const int tx4 = (tid & 15) << 2;   // 4*tx
    const int b = blockIdx.z, h = blockIdx.y;
    const int q0 = blockIdx.x << 6;

    const int lr  = tid >> 2;          // 0..63 load row
    const int ld0 = (tid & 3) << 4;    // 0,16,32,48

    // load + transpose Q (scaled by 1/sqrt(64) = 0.125)
    {
        const float* qb = qkv + ((size_t)(b * SEQ + q0 + lr)) * (3 * DMODEL) + h * 192 + ld0;
        #pragma unroll
        for (int u = 0; u < 4; ++u) {
            const float4 v = *(const float4*)(qb + 4 * u);
            const int d = ld0 + 4 * u;
            Qt[(d + 0) * SQP + lr] = v.x * 0.125f;
            Qt[(d + 1) * SQP + lr] = v.y * 0.125f;
            Qt[(d + 2) * SQP + lr] = v.z * 0.125f;
            Qt[(d + 3) * SQP + lr] = v.w * 0.125f;
        }
    }

    float acc[4][4];
    float m_[4], l_[4];
    #pragma unroll
    for (int i = 0; i < 4; ++i) {
        m_[i] = -INFINITY; l_[i] = 0.f;
        #pragma unroll
        for (int j = 0; j < 4; ++j) acc[i][j] = 0.f;
    }

    for (int kv0 = 0; kv0 < SEQ; kv0 += 64) {
        const float* kb = qkv + ((size_t)(b * SEQ + kv0 + lr)) * (3 * DMODEL) + h * 192 + 64 + ld0;
        __syncthreads();   // previous tile's compute done before overwrite
        #pragma unroll
        for (int u = 0; u < 4; ++u) {
            const float4 v = *(const float4*)(kb + 4 * u);
            const int d = ld0 + 4 * u;
            Kt[(d + 0) * SQP + lr] = v.x;
            Kt[(d + 1) * SQP + lr] = v.y;
            Kt[(d + 2) * SQP + lr] = v.z;
            Kt[(d + 3) * SQP + lr] = v.w;
        }
        #pragma unroll
        for (int u = 0; u < 4; ++u) {
            const float4 v = *(const float4*)(kb + 64 + 4 * u);
            *(float4*)&Vs[lr * SQP + ld0 + 4 * u] = v;
        }
        __syncthreads();

        // S = Q K^T (64x64), each thread 4x4
        float s_[4][4];
        #pragma unroll
        for (int i = 0; i < 4; ++i)
            #pragma unroll
            for (int j = 0; j < 4; ++j) s_[i][j] = 0.f;

        #pragma unroll 8
        for (int kk = 0; kk < 64; ++kk) {
            const float4 a = *(const float4*)(Qt + kk * SQP + ty4);
            const float4 c = *(const float4*)(Kt + kk * SQP + tx4);
            const float av[4] = {a.x, a.y, a.z, a.w};
            const float cv[4] = {c.x, c.y, c.z, c.w};
            #pragma unroll
            for (int i = 0; i < 4; ++i)
                #pragma unroll
                for (int j = 0; j < 4; ++j)
                    s_[i][j] += av[i] * cv[j];
        }

        // online softmax per q-row; row reduction across the 16 tx lanes
        #pragma unroll
        for (int i = 0; i < 4; ++i) {
            float tm = fmaxf(fmaxf(s_[i][0], s_[i][1]), fmaxf(s_[i][2], s_[i][3]));
            #pragma unroll
            for (int o = 1; o <= 8; o <<= 1)
                tm = fmaxf(tm, __shfl_xor_sync(0xffffffffu, tm, o));
            const float mn = fmaxf(m_[i], tm);
            const float p0 = __expf(s_[i][0] - mn);
            const float p1 = __expf(s_[i][1] - mn);
            const float p2 = __expf(s_[i][2] - mn);
            const float p3 = __expf(s_[i][3] - mn);
            float ts = p0 + p1 + p2 + p3;
            #pragma unroll
            for (int o = 1; o <= 8; o <<= 1)
                ts += __shfl_xor_sync(0xffffffffu, ts, o);
            const float al = __expf(m_[i] - mn);   // first tile: exp(-inf)=0
            l_[i] = l_[i] * al + ts;
            m_[i] = mn;
            acc[i][0] *= al; acc[i][1] *= al; acc[i][2] *= al; acc[i][3] *= al;
            float4 pw = {p0, p1, p2, p3};
            *(float4*)&Ps[(ty4 + i) * SQP + tx4] = pw;
        }
        __syncwarp();  // Ps rows are produced/consumed within one warp

        // O += P V  (64x64 @ 64x64)
        #pragma unroll 8
        for (int kk = 0; kk < 64; ++kk) {
            const float4 v4 = *(const float4*)&Vs[kk * SQP + tx4];
            #pragma unroll
            for (int i = 0; i < 4; ++i) {
                const float p = Ps[(ty4 + i) * SQP + kk];
                acc[i][0] += p * v4.x;
                acc[i][1] += p * v4.y;
                acc[i][2] += p * v4.z;
                acc[i][3] += p * v4.w;
            }
        }
    }

    // normalize + write [B,S,H*HD]
    #pragma unroll
    for (int i = 0; i < 4; ++i) {
        const float inv = 1.0f / l_[i];
        float4 o;
        o.x = acc[i][0] * inv; o.y = acc[i][1] * inv;
        o.z = acc[i][2] * inv; o.w = acc[i][3] * inv;
        const size_t off = ((size_t)(b * SEQ + q0 + ty4 + i)) * DMODEL + h * HD + tx4;
        *(float4*)&out[off] = o;
    }
}

// ====================================================================
// launch
// ====================================================================
extern "C" void kernel_launch(void* const* d_in, const int* in_sizes, int n_in,
                              void* d_out, int out_size)
{
    (void)in_sizes; (void)n_in; (void)out_size;
    const float* x    = (const float*)d_in[0];
    const float* g1   = (const float*)d_in[1];
    const float* b1   = (const float*)d_in[2];
    const float* Wqkv = (const float*)d_in[3];
    const float* bqkv = (const float*)d_in[4];
    const float* Wo   = (const float*)d_in[5];
    const float* bo   = (const float*)d_in[6];
    const float* g2   = (const float*)d_in[7];
    const float* b2   = (const float*)d_in[8];
    const float* W1   = (const float*)d_in[9];
    const float* b1m  = (const float*)d_in[10];
    const float* W2   = (const float*)d_in[11];
    const float* b2m  = (const float*)d_in[12];
    float* out = (float*)d_out;

    float *h, *qkvb, *att, *x1, *ffh;
    cudaGetSymbolAddress((void**)&h,    g_h);
    cudaGetSymbolAddress((void**)&qkvb, g_qkv);
    cudaGetSymbolAddress((void**)&att,  g_att);
    cudaGetSymbolAddress((void**)&x1,   g_x1);
    cudaGetSymbolAddress((void**)&ffh,  g_ffh);

    const int attn_smem = 4 * 64 * SQP * (int)sizeof(float);  // 69632 B
    cudaFuncSetAttribute(attn_kernel, cudaFuncAttributeMaxDynamicSharedMemorySize, attn_smem);

    // 1) h = LN1(x)
    ln_kernel<<<TOK, 256>>>(x, g1, b1, h);
    // 2) qkv = h @ Wqkv^T + bqkv
    sgemm_nt<false, false><<<dim3(3 * DMODEL / 128, TOK / 128), 256>>>(
        h, Wqkv, bqkv, nullptr, qkvb, TOK, 3 * DMODEL, DMODEL);
    // 3) attention
    attn_kernel<<<dim3(SEQ / 64, NH, NB), 256, attn_smem>>>(qkvb, att);
    // 4) x1 = x + att @ Wo^T + bo
    sgemm_nt<false, true><<<dim3(DMODEL / 128, TOK / 128), 256>>>(
        att, Wo, bo, x, x1, TOK, DMODEL, DMODEL);
    // 5) h = LN2(x1)
    ln_kernel<<<TOK, 256>>>(x1, g2, b2, h);
    // 6) ffh = gelu(h @ W1^T + b1m)
    sgemm_nt<true, false><<<dim3(FFD / 128, TOK / 128), 256>>>(
        h, W1, b1m, nullptr, ffh, TOK, FFD, DMODEL);
    // 7) out = x1 + ffh @ W2^T + b2m
    sgemm_nt<false, true><<<dim3(DMODEL / 128, TOK / 128), 256>>>(
        ffh, W2, b2m, x1, out, TOK, DMODEL, FFD);
}

// round 4
// speedup vs baseline: 1.5475x; 1.5475x over previous
#include <cuda_runtime.h>
#include <cuda_bf16.h>
#include <stdint.h>
#include <math.h>

// ---------------- problem constants ----------------
#define NB     2
#define SEQ    2048
#define TOK    4096
#define DMODEL 1024
#define NH     16
#define HD     64
#define FFD    4096
#define LN_EPS 1e-5f

// ---------------- scratch (device globals; no allocation) ----------------
__device__ float g_qkv[TOK * 3 * DMODEL];
__device__ float g_x1 [TOK * DMODEL];
__device__ __nv_bfloat16 g_hh[TOK * DMODEL], g_hl[TOK * DMODEL];
__device__ __nv_bfloat16 g_ah[TOK * DMODEL], g_al[TOK * DMODEL];
__device__ __nv_bfloat16 g_fh[TOK * FFD],    g_fl[TOK * FFD];
#define WTOT (12 * 1024 * 1024)
__device__ __nv_bfloat16 g_wh[WTOT], g_wl[WTOT];

#define WQKV_OFF 0
#define WO_OFF   3145728
#define W1_OFF   4194304
#define W2_OFF   8388608

// ==================== helpers ====================
static __device__ __forceinline__ uint32_t smem_u32(const void* p) {
    uint32_t a;
    asm("{ .reg .u64 t; cvta.to.shared.u64 t, %1; cvt.u32.u64 %0, t; }"
        : "=r"(a) : "l"(p));
    return a;
}

static __device__ __forceinline__ void cpasync16(uint32_t s, const void* g) {
    asm volatile(
        "{ .reg .u64 p; cvta.to.global.u64 p, %1; "
        "cp.async.cg.shared.global [%0], [p], 16; }"
        :: "r"(s), "l"(g) : "memory");
}
#define CP_COMMIT() asm volatile("cp.async.commit_group;" ::: "memory")
#define CP_WAIT1()  asm volatile("cp.async.wait_group 1;" ::: "memory")
#define CP_WAIT0()  asm volatile("cp.async.wait_group 0;" ::: "memory")

static __device__ __forceinline__ void ldm4(uint32_t* r, uint32_t addr) {
    asm volatile("ldmatrix.sync.aligned.m8n8.x4.shared.b16 {%0,%1,%2,%3}, [%4];"
        : "=r"(r[0]), "=r"(r[1]), "=r"(r[2]), "=r"(r[3]) : "r"(addr));
}

static __device__ __forceinline__ void mma_bf16(float* c, const uint32_t* a,
                                                uint32_t b0, uint32_t b1) {
    asm volatile(
        "mma.sync.aligned.m16n8k16.row.col.f32.bf16.bf16.f32 "
        "{%0,%1,%2,%3}, {%4,%5,%6,%7}, {%8,%9}, {%0,%1,%2,%3};"
        : "+f"(c[0]), "+f"(c[1]), "+f"(c[2]), "+f"(c[3])
        : "r"(a[0]), "r"(a[1]), "r"(a[2]), "r"(a[3]), "r"(b0), "r"(b1));
}

// ==================== weight hi/lo split ====================
__global__ __launch_bounds__(256) void split_kernel(
    const float* __restrict__ w, __nv_bfloat16* __restrict__ hi,
    __nv_bfloat16* __restrict__ lo, int n)
{
    int i = blockIdx.x * 256 + threadIdx.x;
    if (i < n) {
        float v = w[i];
        __nv_bfloat16 h = __float2bfloat16(v);
        hi[i] = h;
        lo[i] = __float2bfloat16(v - __bfloat162float(h));
    }
}

// ==================== LayerNorm -> bf16 hi/lo ====================
__global__ __launch_bounds__(256) void ln_kernel(
    const float* __restrict__ x, const float* __restrict__ g,
    const float* __restrict__ b, __nv_bfloat16* __restrict__ yh,
    __nv_bfloat16* __restrict__ yl)
{
    __shared__ float red[8];
    __shared__ float bc[2];
    const int r = blockIdx.x, tid = threadIdx.x;
    const int wid = tid >> 5, lane = tid & 31;

    const float4 v = ((const float4*)(x + (size_t)r * DMODEL))[tid];

    float s = v.x + v.y + v.z + v.w;
    #pragma unroll
    for (int o = 16; o; o >>= 1) s += __shfl_xor_sync(0xffffffffu, s, o);
    if (lane == 0) red[wid] = s;
    __syncthreads();
    if (tid == 0) {
        float t = 0.f;
        #pragma unroll
        for (int i = 0; i < 8; ++i) t += red[i];
        bc[0] = t * (1.0f / DMODEL);
    }
    __syncthreads();
    const float mean = bc[0];

    const float dx = v.x - mean, dy = v.y - mean, dz = v.z - mean, dw = v.w - mean;
    float ss = dx * dx + dy * dy + dz * dz + dw * dw;
    #pragma unroll
    for (int o = 16; o; o >>= 1) ss += __shfl_xor_sync(0xffffffffu, ss, o);
    if (lane == 0) red[wid] = ss;
    __syncthreads();
    if (tid == 0) {
        float t = 0.f;
        #pragma unroll
        for (int i = 0; i < 8; ++i) t += red[i];
        bc[1] = rsqrtf(t * (1.0f / DMODEL) + LN_EPS);
    }
    __syncthreads();
    const float rs = bc[1];

    const float4 gv = ((const float4*)g)[tid];
    const float4 bv = ((const float4*)b)[tid];
    float o4[4];
    o4[0] = dx * rs * gv.x + bv.x;
    o4[1] = dy * rs * gv.y + bv.y;
    o4[2] = dz * rs * gv.z + bv.z;
    o4[3] = dw * rs * gv.w + bv.w;
    const size_t off = (size_t)r * DMODEL + tid * 4;
    #pragma unroll
    for (int e = 0; e < 4; ++e) {
        __nv_bfloat16 h = __float2bfloat16(o4[e]);
        yh[off + e] = h;
        yl[off + e] = __float2bfloat16(o4[e] - __bfloat162float(h));
    }
}

// ==================== mma.sync GEMM (NT, bf16x3 split) ====================
// C[M,N] = (Ah+Al)[M,K] * (Bh+Bl)[N,K]^T + bias (+res) (+gelu) (+split-out)
// CTA tile 128x128, BK=32, 256 threads (8 warps, 2x4), warp tile 64x32.
// smem per stage: 4 tiles of 128 rows x 32 bf16, padded stride 40 (80B/row)
#define TILE_B   10240              // 128*80
#define STAGE_B  (4 * TILE_B)       // 40960
#define GEMM_SMEM (2 * STAGE_B)     // 81920

static __device__ __forceinline__ void stage_load(
    uint32_t s0,
    const __nv_bfloat16* gAh, const __nv_bfloat16* gAl,
    const __nv_bfloat16* gBh, const __nv_bfloat16* gBl,
    int m0, int n0, int K, int kt, int tid)
{
    #pragma unroll
    for (int half = 0; half < 2; ++half) {
        const int u   = tid + half * 256;   // 0..511
        const int row = u >> 2;
        const int seg = u & 3;
        const uint32_t soff = row * 80 + seg * 16;
        const size_t ga = (size_t)(m0 + row) * K + kt + seg * 8;
        const size_t gb = (size_t)(n0 + row) * K + kt + seg * 8;
        cpasync16(s0 +              soff, gAh + ga);
        cpasync16(s0 + TILE_B     + soff, gAl + ga);
        cpasync16(s0 + 2 * TILE_B + soff, gBh + gb);
        cpasync16(s0 + 3 * TILE_B + soff, gBl + gb);
    }
}

template<bool GELU_F, bool RES_F, bool SPLIT_F>
__global__ __launch_bounds__(256, 2)
void gemm_mma(
    const __nv_bfloat16* __restrict__ Ah, const __nv_bfloat16* __restrict__ Al,
    const __nv_bfloat16* __restrict__ Bh, const __nv_bfloat16* __restrict__ Bl,
    const float* __restrict__ bias, const float* __restrict__ res,
    float* __restrict__ Cf, __nv_bfloat16* __restrict__ Ch,
    __nv_bfloat16* __restrict__ Cl, int M, int N, int K)
{
    extern __shared__ char dsm[];
    const uint32_t sb = smem_u32(dsm);

    const int tid  = threadIdx.x;
    const int wid  = tid >> 5, lane = tid & 31;
    const int wm   = wid & 1;          // 2 warps along M
    const int wn   = wid >> 1;         // 4 warps along N
    const int m0   = blockIdx.y << 7;
    const int n0   = blockIdx.x << 7;

    float acc[4][4][4];
    #pragma unroll
    for (int i = 0; i < 4; ++i)
        #pragma unroll
        for (int j = 0; j < 4; ++j) {
            acc[i][j][0] = 0.f; acc[i][j][1] = 0.f;
            acc[i][j][2] = 0.f; acc[i][j][3] = 0.f;
        }

    // per-lane ldmatrix row/col components
    const int lr   = lane & 15;          // fragment row (0..15)
    const int cof  = (lane >> 4) << 3;   // 0 or 8 (k offset)
    const uint32_t aRowByte = (uint32_t)(wm * 64 + lr) * 80;  // A row base bytes
    const uint32_t bRowByte = (uint32_t)(wn * 32 + lr) * 80;  // B row base bytes

    const int NC = K >> 5;   // K / 32

    stage_load(sb, Ah, Al, Bh, Bl, m0, n0, K, 0, tid);
    CP_COMMIT();

    for (int c = 0; c < NC; ++c) {
        if (c + 1 < NC) {
            stage_load(sb + ((c + 1) & 1) * STAGE_B, Ah, Al, Bh, Bl,
                       m0, n0, K, (c + 1) << 5, tid);
            CP_COMMIT();
            CP_WAIT1();
        } else {
            CP_WAIT0();
        }
        __syncthreads();

        const uint32_t s0  = sb + (c & 1) * STAGE_B;
        const uint32_t aAh = s0;
        const uint32_t aAl = s0 + TILE_B;
        const uint32_t aBh = s0 + 2 * TILE_B;
        const uint32_t aBl = s0 + 3 * TILE_B;

        #pragma unroll
        for (int ks = 0; ks < 2; ++ks) {
            const uint32_t kbyte = (uint32_t)(ks * 16 + cof) * 2;

            uint32_t ah[4][4];
            #pragma unroll
            for (int mi = 0; mi < 4; ++mi)
                ldm4(ah[mi], aAh + aRowByte + (uint32_t)(mi * 16) * 80 + kbyte);

            uint32_t bh[2][4];
            #pragma unroll
            for (int nt = 0; nt < 2; ++nt)
                ldm4(bh[nt], aBh + bRowByte + (uint32_t)(nt * 16) * 80 + kbyte);

            // term 1: Ah * Bh
            #pragma unroll
            for (int mi = 0; mi < 4; ++mi)
                #pragma unroll
                for (int ni = 0; ni < 4; ++ni)
                    mma_bf16(acc[mi][ni], ah[mi],
                             bh[ni >> 1][ni & 1], bh[ni >> 1][2 + (ni & 1)]);

            uint32_t bl[2][4];
            #pragma unroll
            for (int nt = 0; nt < 2; ++nt)
                ldm4(bl[nt], aBl + bRowByte + (uint32_t)(nt * 16) * 80 + kbyte);

            // term 2: Ah * Bl
            #pragma unroll
            for (int mi = 0; mi < 4; ++mi)
                #pragma unroll
                for (int ni = 0; ni < 4; ++ni)
                    mma_bf16(acc[mi][ni], ah[mi],
                             bl[ni >> 1][ni & 1], bl[ni >> 1][2 + (ni & 1)]);

            uint32_t al2[4][4];
            #pragma unroll
            for (int mi = 0; mi < 4; ++mi)
                ldm4(al2[mi], aAl + aRowByte + (uint32_t)(mi * 16) * 80 + kbyte);

            // term 3: Al * Bh
            #pragma unroll
            for (int mi = 0; mi < 4; ++mi)
                #pragma unroll
                for (int ni = 0; ni < 4; ++ni)
                    mma_bf16(acc[mi][ni], al2[mi],
                             bh[ni >> 1][ni & 1], bh[ni >> 1][2 + (ni & 1)]);
        }
        __syncthreads();
    }

    // ---- epilogue ----
    const int tr = lane >> 2;          // 0..7
    const int tc = (lane & 3) << 1;    // 0,2,4,6
    #pragma unroll
    for (int mi = 0; mi < 4; ++mi) {
        #pragma unroll
        for (int ni = 0; ni < 4; ++ni) {
            const int col = n0 + wn * 32 + ni * 8 + tc;
            #pragma unroll
            for (int half = 0; half < 2; ++half) {
                const int row = m0 + wm * 64 + mi * 16 + tr + half * 8;
                float vx = acc[mi][ni][half * 2 + 0] + bias[col + 0];
                float vy = acc[mi][ni][half * 2 + 1] + bias[col + 1];
                if (RES_F) {
                    const float2 rv = *(const float2*)&res[(size_t)row * N + col];
                    vx += rv.x; vy += rv.y;
                }
                if (GELU_F) {
                    vx = 0.5f * vx * (1.0f + erff(vx * 0.70710678f));
                    vy = 0.5f * vy * (1.0f + erff(vy * 0.70710678f));
                }
                const size_t off = (size_t)row * N + col;
                if (SPLIT_F) {
                    __nv_bfloat16 h0 = __float2bfloat16(vx);
                    __nv_bfloat16 h1 = __float2bfloat16(vy);
                    __nv_bfloat16 l0 = __float2bfloat16(vx - __bfloat162float(h0));
                    __nv_bfloat16 l1 = __float2bfloat16(vy - __bfloat162float(h1));
                    *(__nv_bfloat162*)(Ch + off) = __halves2bfloat162(h0, h1);
                    *(__nv_bfloat162*)(Cl + off) = __halves2bfloat162(l0, l1);
                } else {
                    float2 o; o.x = vx; o.y = vy;
                    *(float2*)&Cf[off] = o;
                }
            }
        }
    }
}

// ==================== Flash attention (fp32) -> bf16 hi/lo ====================
#define SQP 68

__global__ __launch_bounds__(256) void attn_kernel(
    const float* __restrict__ qkv, __nv_bfloat16* __restrict__ oh,
    __nv_bfloat16* __restrict__ ol)
{
    extern __shared__ float sm[];
    float* Qt = sm;
    float* Kt = Qt + 64 * SQP;
    float* Vs = Kt + 64 * SQP;
    float* Ps = Vs + 64 * SQP;

    const int tid = threadIdx.x;
    const int ty4 = (tid >> 4) << 2;
    const int tx4 = (tid & 15) << 2;
    const int b = blockIdx.z, h = blockIdx.y;
    const int q0 = blockIdx.x << 6;

    const int lr  = tid >> 2;
    const int ld0 = (tid & 3) << 4;

    {
        const float* qb = qkv + ((size_t)(b * SEQ + q0 + lr)) * (3 * DMODEL) + h * 192 + ld0;
        #pragma unroll
        for (int u = 0; u < 4; ++u) {
            const float4 v = *(const float4*)(qb + 4 * u);
            const int d = ld0 + 4 * u;
            Qt[(d + 0) * SQP + lr] = v.x * 0.125f;
            Qt[(d + 1) * SQP + lr] = v.y * 0.125f;
            Qt[(d + 2) * SQP + lr] = v.z * 0.125f;
            Qt[(d + 3) * SQP + lr] = v.w * 0.125f;
        }
    }

    float acc[4][4];
    float m_[4], l_[4];
    #pragma unroll
    for (int i = 0; i < 4; ++i) {
        m_[i] = -INFINITY; l_[i] = 0.f;
        #pragma unroll
        for (int j = 0; j < 4; ++j) acc[i][j] = 0.f;
    }

    for (int kv0 = 0; kv0 < SEQ; kv0 += 64) {
        const float* kb = qkv + ((size_t)(b * SEQ + kv0 + lr)) * (3 * DMODEL) + h * 192 + 64 + ld0;
        __syncthreads();
        #pragma unroll
        for (int u = 0; u < 4; ++u) {
            const float4 v = *(const float4*)(kb + 4 * u);
            const int d = ld0 + 4 * u;
            Kt[(d + 0) * SQP + lr] = v.x;
            Kt[(d + 1) * SQP + lr] = v.y;
            Kt[(d + 2) * SQP + lr] = v.z;
            Kt[(d + 3) * SQP + lr] = v.w;
        }
        #pragma unroll
        for (int u = 0; u < 4; ++u) {
            const float4 v = *(const float4*)(kb + 64 + 4 * u);
            *(float4*)&Vs[lr * SQP + ld0 + 4 * u] = v;
        }
        __syncthreads();

        float s_[4][4];
        #pragma unroll
        for (int i = 0; i < 4; ++i)
            #pragma unroll
            for (int j = 0; j < 4; ++j) s_[i][j] = 0.f;

        #pragma unroll 8
        for (int kk = 0; kk < 64; ++kk) {
            const float4 a = *(const float4*)(Qt + kk * SQP + ty4);
            const float4 c = *(const float4*)(Kt + kk * SQP + tx4);
            const float av[4] = {a.x, a.y, a.z, a.w};
            const float cv[4] = {c.x, c.y, c.z, c.w};
            #pragma unroll
            for (int i = 0; i < 4; ++i)
                #pragma unroll
                for (int j = 0; j < 4; ++j)
                    s_[i][j] += av[i] * cv[j];
        }

        #pragma unroll
        for (int i = 0; i < 4; ++i) {
            float tm = fmaxf(fmaxf(s_[i][0], s_[i][1]), fmaxf(s_[i][2], s_[i][3]));
            #pragma unroll
            for (int o = 1; o <= 8; o <<= 1)
                tm = fmaxf(tm, __shfl_xor_sync(0xffffffffu, tm, o));
            const float mn = fmaxf(m_[i], tm);
            const float p0 = __expf(s_[i][0] - mn);
            const float p1 = __expf(s_[i][1] - mn);
            const float p2 = __expf(s_[i][2] - mn);
            const float p3 = __expf(s_[i][3] - mn);
            float ts = p0 + p1 + p2 + p3;
            #pragma unroll
            for (int o = 1; o <= 8; o <<= 1)
                ts += __shfl_xor_sync(0xffffffffu, ts, o);
            const float al = __expf(m_[i] - mn);
            l_[i] = l_[i] * al + ts;
            m_[i] = mn;
            acc[i][0] *= al; acc[i][1] *= al; acc[i][2] *= al; acc[i][3] *= al;
            float4 pw = {p0, p1, p2, p3};
            *(float4*)&Ps[(ty4 + i) * SQP + tx4] = pw;
        }
        __syncwarp();

        #pragma unroll 8
        for (int kk = 0; kk < 64; ++kk) {
            const float4 v4 = *(const float4*)&Vs[kk * SQP + tx4];
            #pragma unroll
            for (int i = 0; i < 4; ++i) {
                const float p = Ps[(ty4 + i) * SQP + kk];
                acc[i][0] += p * v4.x;
                acc[i][1] += p * v4.y;
                acc[i][2] += p * v4.z;
                acc[i][3] += p * v4.w;
            }
        }
    }

    #pragma unroll
    for (int i = 0; i < 4; ++i) {
        const float inv = 1.0f / l_[i];
        float o[4] = {acc[i][0] * inv, acc[i][1] * inv, acc[i][2] * inv, acc[i][3] * inv};
        const size_t off = ((size_t)(b * SEQ + q0 + ty4 + i)) * DMODEL + h * HD + tx4;
        __nv_bfloat16 hh[4], ll[4];
        #pragma unroll
        for (int e = 0; e < 4; ++e) {
            hh[e] = __float2bfloat16(o[e]);
            ll[e] = __float2bfloat16(o[e] - __bfloat162float(hh[e]));
        }
        *(__nv_bfloat162*)(oh + off)     = __halves2bfloat162(hh[0], hh[1]);
        *(__nv_bfloat162*)(oh + off + 2) = __halves2bfloat162(hh[2], hh[3]);
        *(__nv_bfloat162*)(ol + off)     = __halves2bfloat162(ll[0], ll[1]);
        *(__nv_bfloat162*)(ol + off + 2) = __halves2bfloat162(ll[2], ll[3]);
    }
}

// ==================== launch ====================
extern "C" void kernel_launch(void* const* d_in, const int* in_sizes, int n_in,
                              void* d_out, int out_size)
{
    (void)in_sizes; (void)n_in; (void)out_size;
    const float* x    = (const float*)d_in[0];
    const float* g1   = (const float*)d_in[1];
    const float* b1   = (const float*)d_in[2];
    const float* Wqkv = (const float*)d_in[3];
    const float* bqkv = (const float*)d_in[4];
    const float* Wo   = (const float*)d_in[5];
    const float* bo   = (const float*)d_in[6];
    const float* g2   = (const float*)d_in[7];
    const float* b2   = (const float*)d_in[8];
    const float* W1   = (const float*)d_in[9];
    const float* b1m  = (const float*)d_in[10];
    const float* W2   = (const float*)d_in[11];
    const float* b2m  = (const float*)d_in[12];
    float* out = (float*)d_out;

    float *qkv, *x1;
    __nv_bfloat16 *hh, *hl, *ah, *al, *fh, *fl, *wh, *wl;
    cudaGetSymbolAddress((void**)&qkv, g_qkv);
    cudaGetSymbolAddress((void**)&x1,  g_x1);
    cudaGetSymbolAddress((void**)&hh,  g_hh);
    cudaGetSymbolAddress((void**)&hl,  g_hl);
    cudaGetSymbolAddress((void**)&ah,  g_ah);
    cudaGetSymbolAddress((void**)&al,  g_al);
    cudaGetSymbolAddress((void**)&fh,  g_fh);
    cudaGetSymbolAddress((void**)&fl,  g_fl);
    cudaGetSymbolAddress((void**)&wh,  g_wh);
    cudaGetSymbolAddress((void**)&wl,  g_wl);

    cudaFuncSetAttribute(gemm_mma<false, false, false>,
                         cudaFuncAttributeMaxDynamicSharedMemorySize, GEMM_SMEM);
    cudaFuncSetAttribute(gemm_mma<false, true, false>,
                         cudaFuncAttributeMaxDynamicSharedMemorySize, GEMM_SMEM);
    cudaFuncSetAttribute(gemm_mma<true, false, true>,
                         cudaFuncAttributeMaxDynamicSharedMemorySize, GEMM_SMEM);
    const int attn_smem = 4 * 64 * SQP * (int)sizeof(float);
    cudaFuncSetAttribute(attn_kernel, cudaFuncAttributeMaxDynamicSharedMemorySize, attn_smem);

    // 0) split weights to bf16 hi/lo
    split_kernel<<<(3 * DMODEL * DMODEL + 255) / 256, 256>>>(Wqkv, wh + WQKV_OFF, wl + WQKV_OFF, 3 * DMODEL * DMODEL);
    split_kernel<<<(DMODEL * DMODEL + 255) / 256, 256>>>(Wo, wh + WO_OFF, wl + WO_OFF, DMODEL * DMODEL);
    split_kernel<<<(FFD * DMODEL + 255) / 256, 256>>>(W1, wh + W1_OFF, wl + W1_OFF, FFD * DMODEL);
    split_kernel<<<(DMODEL * FFD + 255) / 256, 256>>>(W2, wh + W2_OFF, wl + W2_OFF, DMODEL * FFD);

    // 1) h = LN1(x)
    ln_kernel<<<TOK, 256>>>(x, g1, b1, hh, hl);
    // 2) qkv = h @ Wqkv^T + bqkv
    gemm_mma<false, false, false><<<dim3(3 * DMODEL / 128, TOK / 128), 256, GEMM_SMEM>>>(
        hh, hl, wh + WQKV_OFF, wl + WQKV_OFF, bqkv, nullptr,
        qkv, nullptr, nullptr, TOK, 3 * DMODEL, DMODEL);
    // 3) attention -> bf16 hi/lo
    attn_kernel<<<dim3(SEQ / 64, NH, NB), 256, attn_smem>>>(qkv, ah, al);
    // 4) x1 = x + att @ Wo^T + bo
    gemm_mma<false, true, false><<<dim3(DMODEL / 128, TOK / 128), 256, GEMM_SMEM>>>(
        ah, al, wh + WO_OFF, wl + WO_OFF, bo, x,
        x1, nullptr, nullptr, TOK, DMODEL, DMODEL);
    // 5) h = LN2(x1)
    ln_kernel<<<TOK, 256>>>(x1, g2, b2, hh, hl);
    // 6) ffh = gelu(h @ W1^T + b1m) -> bf16 hi/lo
    gemm_mma<true, false, true><<<dim3(FFD / 128, TOK / 128), 256, GEMM_SMEM>>>(
        hh, hl, wh + W1_OFF, wl + W1_OFF, b1m, nullptr,
        nullptr, fh, fl, TOK, FFD, DMODEL);
    // 7) out = x1 + ffh @ W2^T + b2m
    gemm_mma<false, true, false><<<dim3(DMODEL / 128, TOK / 128), 256, GEMM_SMEM>>>(
        fh, fl, wh + W2_OFF, wl + W2_OFF, b2m, x1,
        out, nullptr, nullptr, TOK, DMODEL, FFD);
}

// round 5
// speedup vs baseline: 2.3792x; 1.5374x over previous
#include <cuda_runtime.h>
#include <cuda_bf16.h>
#include <stdint.h>
#include <math.h>

// ---------------- problem constants ----------------
#define NB     2
#define SEQ    2048
#define TOK    4096
#define DMODEL 1024
#define NH     16
#define HD     64
#define FFD    4096
#define LN_EPS 1e-5f

// ---------------- scratch (device globals; no allocation) ----------------
__device__ float g_qkv[TOK * 3 * DMODEL];
__device__ float g_x1 [TOK * DMODEL];
__device__ __nv_bfloat16 g_hh[TOK * DMODEL], g_hl[TOK * DMODEL];
__device__ __nv_bfloat16 g_ah[TOK * DMODEL], g_al[TOK * DMODEL];
__device__ __nv_bfloat16 g_fh[TOK * FFD],    g_fl[TOK * FFD];
#define WTOT (12 * 1024 * 1024)
__device__ __nv_bfloat16 g_wh[WTOT], g_wl[WTOT];

#define WQKV_OFF 0
#define WO_OFF   3145728
#define W1_OFF   4194304
#define W2_OFF   8388608

// ==================== helpers ====================
static __device__ __forceinline__ uint32_t smem_u32(const void* p) {
    uint32_t a;
    asm("{ .reg .u64 t; cvta.to.shared.u64 t, %1; cvt.u32.u64 %0, t; }"
        : "=r"(a) : "l"(p));
    return a;
}

static __device__ __forceinline__ void cpasync16(uint32_t s, const void* g) {
    asm volatile(
        "{ .reg .u64 p; cvta.to.global.u64 p, %1; "
        "cp.async.cg.shared.global [%0], [p], 16; }"
        :: "r"(s), "l"(g) : "memory");
}
#define CP_COMMIT() asm volatile("cp.async.commit_group;" ::: "memory")
#define CP_WAIT1()  asm volatile("cp.async.wait_group 1;" ::: "memory")
#define CP_WAIT0()  asm volatile("cp.async.wait_group 0;" ::: "memory")

static __device__ __forceinline__ void ldm4(uint32_t* r, uint32_t addr) {
    asm volatile("ldmatrix.sync.aligned.m8n8.x4.shared.b16 {%0,%1,%2,%3}, [%4];"
        : "=r"(r[0]), "=r"(r[1]), "=r"(r[2]), "=r"(r[3]) : "r"(addr));
}
static __device__ __forceinline__ void ldm4t(uint32_t* r, uint32_t addr) {
    asm volatile("ldmatrix.sync.aligned.m8n8.x4.trans.shared.b16 {%0,%1,%2,%3}, [%4];"
        : "=r"(r[0]), "=r"(r[1]), "=r"(r[2]), "=r"(r[3]) : "r"(addr));
}

static __device__ __forceinline__ void mma_bf16(float* c, const uint32_t* a,
                                                uint32_t b0, uint32_t b1) {
    asm volatile(
        "mma.sync.aligned.m16n8k16.row.col.f32.bf16.bf16.f32 "
        "{%0,%1,%2,%3}, {%4,%5,%6,%7}, {%8,%9}, {%0,%1,%2,%3};"
        : "+f"(c[0]), "+f"(c[1]), "+f"(c[2]), "+f"(c[3])
        : "r"(a[0]), "r"(a[1]), "r"(a[2]), "r"(a[3]), "r"(b0), "r"(b1));
}

// pack two fp32 -> bf16x2 register (lo in low half)
static __device__ __forceinline__ uint32_t pack_bf2(float lo, float hi) {
    uint32_t r;
    asm("cvt.rn.bf16x2.f32 %0, %1, %2;" : "=r"(r) : "f"(hi), "f"(lo));
    return r;
}

// ==================== weight hi/lo split ====================
__global__ __launch_bounds__(256) void split_kernel(
    const float* __restrict__ w, __nv_bfloat16* __restrict__ hi,
    __nv_bfloat16* __restrict__ lo, int n)
{
    int i = blockIdx.x * 256 + threadIdx.x;
    if (i < n) {
        float v = w[i];
        __nv_bfloat16 h = __float2bfloat16(v);
        hi[i] = h;
        lo[i] = __float2bfloat16(v - __bfloat162float(h));
    }
}

// ==================== LayerNorm -> bf16 hi/lo ====================
__global__ __launch_bounds__(256) void ln_kernel(
    const float* __restrict__ x, const float* __restrict__ g,
    const float* __restrict__ b, __nv_bfloat16* __restrict__ yh,
    __nv_bfloat16* __restrict__ yl)
{
    __shared__ float red[8];
    __shared__ float bc[2];
    const int r = blockIdx.x, tid = threadIdx.x;
    const int wid = tid >> 5, lane = tid & 31;

    const float4 v = ((const float4*)(x + (size_t)r * DMODEL))[tid];

    float s = v.x + v.y + v.z + v.w;
    #pragma unroll
    for (int o = 16; o; o >>= 1) s += __shfl_xor_sync(0xffffffffu, s, o);
    if (lane == 0) red[wid] = s;
    __syncthreads();
    if (tid == 0) {
        float t = 0.f;
        #pragma unroll
        for (int i = 0; i < 8; ++i) t += red[i];
        bc[0] = t * (1.0f / DMODEL);
    }
    __syncthreads();
    const float mean = bc[0];

    const float dx = v.x - mean, dy = v.y - mean, dz = v.z - mean, dw = v.w - mean;
    float ss = dx * dx + dy * dy + dz * dz + dw * dw;
    #pragma unroll
    for (int o = 16; o; o >>= 1) ss += __shfl_xor_sync(0xffffffffu, ss, o);
    if (lane == 0) red[wid] = ss;
    __syncthreads();
    if (tid == 0) {
        float t = 0.f;
        #pragma unroll
        for (int i = 0; i < 8; ++i) t += red[i];
        bc[1] = rsqrtf(t * (1.0f / DMODEL) + LN_EPS);
    }
    __syncthreads();
    const float rs = bc[1];

    const float4 gv = ((const float4*)g)[tid];
    const float4 bv = ((const float4*)b)[tid];
    float o4[4];
    o4[0] = dx * rs * gv.x + bv.x;
    o4[1] = dy * rs * gv.y + bv.y;
    o4[2] = dz * rs * gv.z + bv.z;
    o4[3] = dw * rs * gv.w + bv.w;
    const size_t off = (size_t)r * DMODEL + tid * 4;
    #pragma unroll
    for (int e = 0; e < 4; ++e) {
        __nv_bfloat16 h = __float2bfloat16(o4[e]);
        yh[off + e] = h;
        yl[off + e] = __float2bfloat16(o4[e] - __bfloat162float(h));
    }
}

// ==================== mma.sync GEMM (NT, bf16x3 split) ====================
#define TILE_B   10240              // 128*80
#define STAGE_B  (4 * TILE_B)       // 40960
#define GEMM_SMEM (2 * STAGE_B)     // 81920

static __device__ __forceinline__ void stage_load(
    uint32_t s0,
    const __nv_bfloat16* gAh, const __nv_bfloat16* gAl,
    const __nv_bfloat16* gBh, const __nv_bfloat16* gBl,
    int m0, int n0, int K, int kt, int tid)
{
    #pragma unroll
    for (int half = 0; half < 2; ++half) {
        const int u   = tid + half * 256;
        const int row = u >> 2;
        const int seg = u & 3;
        const uint32_t soff = row * 80 + seg * 16;
        const size_t ga = (size_t)(m0 + row) * K + kt + seg * 8;
        const size_t gb = (size_t)(n0 + row) * K + kt + seg * 8;
        cpasync16(s0 +              soff, gAh + ga);
        cpasync16(s0 + TILE_B     + soff, gAl + ga);
        cpasync16(s0 + 2 * TILE_B + soff, gBh + gb);
        cpasync16(s0 + 3 * TILE_B + soff, gBl + gb);
    }
}

template<bool GELU_F, bool RES_F, bool SPLIT_F>
__global__ __launch_bounds__(256, 2)
void gemm_mma(
    const __nv_bfloat16* __restrict__ Ah, const __nv_bfloat16* __restrict__ Al,
    const __nv_bfloat16* __restrict__ Bh, const __nv_bfloat16* __restrict__ Bl,
    const float* __restrict__ bias, const float* __restrict__ res,
    float* __restrict__ Cf, __nv_bfloat16* __restrict__ Ch,
    __nv_bfloat16* __restrict__ Cl, int M, int N, int K)
{
    extern __shared__ char dsm[];
    const uint32_t sb = smem_u32(dsm);

    const int tid  = threadIdx.x;
    const int wid  = tid >> 5, lane = tid & 31;
    const int wm   = wid & 1;
    const int wn   = wid >> 1;
    const int m0   = blockIdx.y << 7;
    const int n0   = blockIdx.x << 7;

    float acc[4][4][4];
    #pragma unroll
    for (int i = 0; i < 4; ++i)
        #pragma unroll
        for (int j = 0; j < 4; ++j) {
            acc[i][j][0] = 0.f; acc[i][j][1] = 0.f;
            acc[i][j][2] = 0.f; acc[i][j][3] = 0.f;
        }

    const int lr   = lane & 15;
    const int cof  = (lane >> 4) << 3;
    const uint32_t aRowByte = (uint32_t)(wm * 64 + lr) * 80;
    const uint32_t bRowByte = (uint32_t)(wn * 32 + lr) * 80;

    const int NC = K >> 5;

    stage_load(sb, Ah, Al, Bh, Bl, m0, n0, K, 0, tid);
    CP_COMMIT();

    for (int c = 0; c < NC; ++c) {
        if (c + 1 < NC) {
            stage_load(sb + ((c + 1) & 1) * STAGE_B, Ah, Al, Bh, Bl,
                       m0, n0, K, (c + 1) << 5, tid);
            CP_COMMIT();
            CP_WAIT1();
        } else {
            CP_WAIT0();
        }
        __syncthreads();

        const uint32_t s0  = sb + (c & 1) * STAGE_B;
        const uint32_t aAh = s0;
        const uint32_t aAl = s0 + TILE_B;
        const uint32_t aBh = s0 + 2 * TILE_B;
        const uint32_t aBl = s0 + 3 * TILE_B;

        #pragma unroll
        for (int ks = 0; ks < 2; ++ks) {
            const uint32_t kbyte = (uint32_t)(ks * 16 + cof) * 2;

            uint32_t ah[4][4];
            #pragma unroll
            for (int mi = 0; mi < 4; ++mi)
                ldm4(ah[mi], aAh + aRowByte + (uint32_t)(mi * 16) * 80 + kbyte);

            uint32_t bh[2][4];
            #pragma unroll
            for (int nt = 0; nt < 2; ++nt)
                ldm4(bh[nt], aBh + bRowByte + (uint32_t)(nt * 16) * 80 + kbyte);

            #pragma unroll
            for (int mi = 0; mi < 4; ++mi)
                #pragma unroll
                for (int ni = 0; ni < 4; ++ni)
                    mma_bf16(acc[mi][ni], ah[mi],
                             bh[ni >> 1][ni & 1], bh[ni >> 1][2 + (ni & 1)]);

            uint32_t bl[2][4];
            #pragma unroll
            for (int nt = 0; nt < 2; ++nt)
                ldm4(bl[nt], aBl + bRowByte + (uint32_t)(nt * 16) * 80 + kbyte);

            #pragma unroll
            for (int mi = 0; mi < 4; ++mi)
                #pragma unroll
                for (int ni = 0; ni < 4; ++ni)
                    mma_bf16(acc[mi][ni], ah[mi],
                             bl[ni >> 1][ni & 1], bl[ni >> 1][2 + (ni & 1)]);

            uint32_t al2[4][4];
            #pragma unroll
            for (int mi = 0; mi < 4; ++mi)
                ldm4(al2[mi], aAl + aRowByte + (uint32_t)(mi * 16) * 80 + kbyte);

            #pragma unroll
            for (int mi = 0; mi < 4; ++mi)
                #pragma unroll
                for (int ni = 0; ni < 4; ++ni)
                    mma_bf16(acc[mi][ni], al2[mi],
                             bh[ni >> 1][ni & 1], bh[ni >> 1][2 + (ni & 1)]);
        }
        __syncthreads();
    }

    const int tr = lane >> 2;
    const int tc = (lane & 3) << 1;
    #pragma unroll
    for (int mi = 0; mi < 4; ++mi) {
        #pragma unroll
        for (int ni = 0; ni < 4; ++ni) {
            const int col = n0 + wn * 32 + ni * 8 + tc;
            #pragma unroll
            for (int half = 0; half < 2; ++half) {
                const int row = m0 + wm * 64 + mi * 16 + tr + half * 8;
                float vx = acc[mi][ni][half * 2 + 0] + bias[col + 0];
                float vy = acc[mi][ni][half * 2 + 1] + bias[col + 1];
                if (RES_F) {
                    const float2 rv = *(const float2*)&res[(size_t)row * N + col];
                    vx += rv.x; vy += rv.y;
                }
                if (GELU_F) {
                    vx = 0.5f * vx * (1.0f + erff(vx * 0.70710678f));
                    vy = 0.5f * vy * (1.0f + erff(vy * 0.70710678f));
                }
                const size_t off = (size_t)row * N + col;
                if (SPLIT_F) {
                    __nv_bfloat16 h0 = __float2bfloat16(vx);
                    __nv_bfloat16 h1 = __float2bfloat16(vy);
                    __nv_bfloat16 l0 = __float2bfloat16(vx - __bfloat162float(h0));
                    __nv_bfloat16 l1 = __float2bfloat16(vy - __bfloat162float(h1));
                    *(__nv_bfloat162*)(Ch + off) = __halves2bfloat162(h0, h1);
                    *(__nv_bfloat162*)(Cl + off) = __halves2bfloat162(l0, l1);
                } else {
                    float2 o; o.x = vx; o.y = vy;
                    *(float2*)&Cf[off] = o;
                }
            }
        }
    }
}

// ==================== Tensor-core flash attention (bf16 mma) ====================
// CTA: 128 q-rows, 8 warps (16 q-rows each, full 128-kv width).
// grid (SEQ/128, NH, NB). smem: K,V tiles 128x64 bf16, row stride 72.
#define AQ   128
#define AKV  128
#define ASTR 72     // bf16 elements per smem row (144 B, conflict-free ldmatrix)

__global__ __launch_bounds__(256) void attn_mma(
    const float* __restrict__ qkv, __nv_bfloat16* __restrict__ oh,
    __nv_bfloat16* __restrict__ ol)
{
    __shared__ __nv_bfloat16 Ks[AKV * ASTR];
    __shared__ __nv_bfloat16 Vs[AKV * ASTR];
    const uint32_t ksB = smem_u32(Ks);
    const uint32_t vsB = smem_u32(Vs);

    const int tid = threadIdx.x;
    const int w = tid >> 5, lane = tid & 31;
    const int g = lane >> 2, t = lane & 3;
    const int b = blockIdx.z, h = blockIdx.y;
    const int q0 = blockIdx.x * AQ;

    const int lrow = tid >> 1;        // 0..127 (load row)
    const int lhf  = tid & 1;         // column half (32 floats)

    // ---- stage Q (scaled 1/8) as bf16 into Ks, ldmatrix into registers ----
    {
        const float4* qp = (const float4*)(qkv +
            ((size_t)(b * SEQ + q0 + lrow)) * (3 * DMODEL) + h * 192 + lhf * 32);
        char* sp = (char*)Ks + lrow * 144 + lhf * 64;
        #pragma unroll
        for (int s = 0; s < 4; ++s) {
            const float4 u = qp[2 * s], v = qp[2 * s + 1];
            uint4 o;
            o.x = pack_bf2(u.x * 0.125f, u.y * 0.125f);
            o.y = pack_bf2(u.z * 0.125f, u.w * 0.125f);
            o.z = pack_bf2(v.x * 0.125f, v.y * 0.125f);
            o.w = pack_bf2(v.z * 0.125f, v.w * 0.125f);
            *(uint4*)(sp + s * 16) = o;
        }
    }
    __syncthreads();

    uint32_t qf[4][4];
    {
        const uint32_t rb = ksB + (uint32_t)(w * 16 + (lane & 15)) * 144
                          + (uint32_t)(((lane >> 4) & 1) * 8) * 2;
        #pragma unroll
        for (int ks = 0; ks < 4; ++ks)
            ldm4(qf[ks], rb + ks * 32);
    }
    __syncthreads();

    float oc[8][4];
    #pragma unroll
    for (int i = 0; i < 8; ++i) {
        oc[i][0] = 0.f; oc[i][1] = 0.f; oc[i][2] = 0.f; oc[i][3] = 0.f;
    }
    float mrow[2] = {-INFINITY, -INFINITY};
    float lrow_[2] = {0.f, 0.f};

    for (int kv0 = 0; kv0 < SEQ; kv0 += AKV) {
        // ---- load K,V tiles fp32 -> bf16 ----
        {
            const float4* kp = (const float4*)(qkv +
                ((size_t)(b * SEQ + kv0 + lrow)) * (3 * DMODEL) + h * 192 + 64 + lhf * 32);
            const float4* vp = kp + 16;   // +64 floats
            char* ksp = (char*)Ks + lrow * 144 + lhf * 64;
            char* vsp = (char*)Vs + lrow * 144 + lhf * 64;
            #pragma unroll
            for (int s = 0; s < 4; ++s) {
                const float4 u = kp[2 * s], v = kp[2 * s + 1];
                uint4 o;
                o.x = pack_bf2(u.x, u.y); o.y = pack_bf2(u.z, u.w);
                o.z = pack_bf2(v.x, v.y); o.w = pack_bf2(v.z, v.w);
                *(uint4*)(ksp + s * 16) = o;
                const float4 a = vp[2 * s], c = vp[2 * s + 1];
                uint4 p;
                p.x = pack_bf2(a.x, a.y); p.y = pack_bf2(a.z, a.w);
                p.z = pack_bf2(c.x, c.y); p.w = pack_bf2(c.z, c.w);
                *(uint4*)(vsp + s * 16) = p;
            }
        }
        __syncthreads();

        // ---- S = Q K^T  (m16 x n128, fp32) ----
        float sc[16][4];
        #pragma unroll
        for (int nt2 = 0; nt2 < 8; ++nt2) {
            #pragma unroll
            for (int q2 = 0; q2 < 4; ++q2) {
                sc[2 * nt2][q2] = 0.f; sc[2 * nt2 + 1][q2] = 0.f;
            }
            #pragma unroll
            for (int ks = 0; ks < 4; ++ks) {
                uint32_t bf[4];
                const uint32_t addr = ksB
                    + (uint32_t)(nt2 * 16 + (lane & 7) + ((lane >> 4) & 1) * 8) * 144
                    + (uint32_t)(ks * 16 + ((lane >> 3) & 1) * 8) * 2;
                ldm4(bf, addr);
                mma_bf16(sc[2 * nt2],     qf[ks], bf[0], bf[1]);
                mma_bf16(sc[2 * nt2 + 1], qf[ks], bf[2], bf[3]);
            }
        }

        // ---- online softmax (rows g, g+8) ----
        float alpha[2];
        #pragma unroll
        for (int r = 0; r < 2; ++r) {
            float mx = -INFINITY;
            #pragma unroll
            for (int nt = 0; nt < 16; ++nt)
                mx = fmaxf(mx, fmaxf(sc[nt][2 * r], sc[nt][2 * r + 1]));
            mx = fmaxf(mx, __shfl_xor_sync(0xffffffffu, mx, 1));
            mx = fmaxf(mx, __shfl_xor_sync(0xffffffffu, mx, 2));
            const float mn = fmaxf(mrow[r], mx);
            alpha[r] = __expf(mrow[r] - mn);
            mrow[r] = mn;
            float rs = 0.f;
            #pragma unroll
            for (int nt = 0; nt < 16; ++nt) {
                const float e0 = __expf(sc[nt][2 * r]     - mn);
                const float e1 = __expf(sc[nt][2 * r + 1] - mn);
                sc[nt][2 * r] = e0; sc[nt][2 * r + 1] = e1;
                rs += e0 + e1;
            }
            rs += __shfl_xor_sync(0xffffffffu, rs, 1);
            rs += __shfl_xor_sync(0xffffffffu, rs, 2);
            lrow_[r] = lrow_[r] * alpha[r] + rs;
        }
        #pragma unroll
        for (int dt = 0; dt < 8; ++dt) {
            oc[dt][0] *= alpha[0]; oc[dt][1] *= alpha[0];
            oc[dt][2] *= alpha[1]; oc[dt][3] *= alpha[1];
        }

        // ---- P fragments (C layout -> A layout, registers only) ----
        uint32_t pf[8][4];
        #pragma unroll
        for (int ks = 0; ks < 8; ++ks) {
            pf[ks][0] = pack_bf2(sc[2 * ks][0],     sc[2 * ks][1]);
            pf[ks][1] = pack_bf2(sc[2 * ks][2],     sc[2 * ks][3]);
            pf[ks][2] = pack_bf2(sc[2 * ks + 1][0], sc[2 * ks + 1][1]);
            pf[ks][3] = pack_bf2(sc[2 * ks + 1][2], sc[2 * ks + 1][3]);
        }

        // ---- O += P V  (k = kv 128, n = d 64) ----
        #pragma unroll
        for (int ks = 0; ks < 8; ++ks) {
            #pragma unroll
            for (int dt2 = 0; dt2 < 4; ++dt2) {
                uint32_t bv[4];
                const uint32_t addr = vsB
                    + (uint32_t)(ks * 16 + (lane & 7) + ((lane >> 3) & 1) * 8) * 144
                    + (uint32_t)(dt2 * 16 + ((lane >> 4) & 1) * 8) * 2;
                ldm4t(bv, addr);
                mma_bf16(oc[2 * dt2],     pf[ks], bv[0], bv[1]);
                mma_bf16(oc[2 * dt2 + 1], pf[ks], bv[2], bv[3]);
            }
        }
        __syncthreads();
    }

    // ---- normalize + write hi/lo bf16 ----
    #pragma unroll
    for (int r = 0; r < 2; ++r) {
        const float inv = 1.0f / lrow_[r];
        const int row = q0 + w * 16 + g + r * 8;
        const size_t base = (size_t)(b * SEQ + row) * DMODEL + h * HD + t * 2;
        #pragma unroll
        for (int dt = 0; dt < 8; ++dt) {
            const float vx = oc[dt][2 * r]     * inv;
            const float vy = oc[dt][2 * r + 1] * inv;
            __nv_bfloat16 h0 = __float2bfloat16(vx);
            __nv_bfloat16 h1 = __float2bfloat16(vy);
            __nv_bfloat16 l0 = __float2bfloat16(vx - __bfloat162float(h0));
            __nv_bfloat16 l1 = __float2bfloat16(vy - __bfloat162float(h1));
            *(__nv_bfloat162*)(oh + base + dt * 8) = __halves2bfloat162(h0, h1);
            *(__nv_bfloat162*)(ol + base + dt * 8) = __halves2bfloat162(l0, l1);
        }
    }
}

// ==================== launch ====================
extern "C" void kernel_launch(void* const* d_in, const int* in_sizes, int n_in,
                              void* d_out, int out_size)
{
    (void)in_sizes; (void)n_in; (void)out_size;
    const float* x    = (const float*)d_in[0];
    const float* g1   = (const float*)d_in[1];
    const float* b1   = (const float*)d_in[2];
    const float* Wqkv = (const float*)d_in[3];
    const float* bqkv = (const float*)d_in[4];
    const float* Wo   = (const float*)d_in[5];
    const float* bo   = (const float*)d_in[6];
    const float* g2   = (const float*)d_in[7];
    const float* b2   = (const float*)d_in[8];
    const float* W1   = (const float*)d_in[9];
    const float* b1m  = (const float*)d_in[10];
    const float* W2   = (const float*)d_in[11];
    const float* b2m  = (const float*)d_in[12];
    float* out = (float*)d_out;

    float *qkv, *x1;
    __nv_bfloat16 *hh, *hl, *ah, *al, *fh, *fl, *wh, *wl;
    cudaGetSymbolAddress((void**)&qkv, g_qkv);
    cudaGetSymbolAddress((void**)&x1,  g_x1);
    cudaGetSymbolAddress((void**)&hh,  g_hh);
    cudaGetSymbolAddress((void**)&hl,  g_hl);
    cudaGetSymbolAddress((void**)&ah,  g_ah);
    cudaGetSymbolAddress((void**)&al,  g_al);
    cudaGetSymbolAddress((void**)&fh,  g_fh);
    cudaGetSymbolAddress((void**)&fl,  g_fl);
    cudaGetSymbolAddress((void**)&wh,  g_wh);
    cudaGetSymbolAddress((void**)&wl,  g_wl);

    cudaFuncSetAttribute(gemm_mma<false, false, false>,
                         cudaFuncAttributeMaxDynamicSharedMemorySize, GEMM_SMEM);
    cudaFuncSetAttribute(gemm_mma<false, true, false>,
                         cudaFuncAttributeMaxDynamicSharedMemorySize, GEMM_SMEM);
    cudaFuncSetAttribute(gemm_mma<true, false, true>,
                         cudaFuncAttributeMaxDynamicSharedMemorySize, GEMM_SMEM);

    // 0) split weights to bf16 hi/lo
    split_kernel<<<(3 * DMODEL * DMODEL + 255) / 256, 256>>>(Wqkv, wh + WQKV_OFF, wl + WQKV_OFF, 3 * DMODEL * DMODEL);
    split_kernel<<<(DMODEL * DMODEL + 255) / 256, 256>>>(Wo, wh + WO_OFF, wl + WO_OFF, DMODEL * DMODEL);
    split_kernel<<<(FFD * DMODEL + 255) / 256, 256>>>(W1, wh + W1_OFF, wl + W1_OFF, FFD * DMODEL);
    split_kernel<<<(DMODEL * FFD + 255) / 256, 256>>>(W2, wh + W2_OFF, wl + W2_OFF, DMODEL * FFD);

    // 1) h = LN1(x)
    ln_kernel<<<TOK, 256>>>(x, g1, b1, hh, hl);
    // 2) qkv = h @ Wqkv^T + bqkv
    gemm_mma<false, false, false><<<dim3(3 * DMODEL / 128, TOK / 128), 256, GEMM_SMEM>>>(
        hh, hl, wh + WQKV_OFF, wl + WQKV_OFF, bqkv, nullptr,
        qkv, nullptr, nullptr, TOK, 3 * DMODEL, DMODEL);
    // 3) attention (tensor cores) -> bf16 hi/lo
    attn_mma<<<dim3(SEQ / AQ, NH, NB), 256>>>(qkv, ah, al);
    // 4) x1 = x + att @ Wo^T + bo
    gemm_mma<false, true, false><<<dim3(DMODEL / 128, TOK / 128), 256, GEMM_SMEM>>>(
        ah, al, wh + WO_OFF, wl + WO_OFF, bo, x,
        x1, nullptr, nullptr, TOK, DMODEL, DMODEL);
    // 5) h = LN2(x1)
    ln_kernel<<<TOK, 256>>>(x1, g2, b2, hh, hl);
    // 6) ffh = gelu(h @ W1^T + b1m) -> bf16 hi/lo
    gemm_mma<true, false, true><<<dim3(FFD / 128, TOK / 128), 256, GEMM_SMEM>>>(
        hh, hl, wh + W1_OFF, wl + W1_OFF, b1m, nullptr,
        nullptr, fh, fl, TOK, FFD, DMODEL);
    // 7) out = x1 + ffh @ W2^T + b2m
    gemm_mma<false, true, false><<<dim3(DMODEL / 128, TOK / 128), 256, GEMM_SMEM>>>(
        fh, fl, wh + W2_OFF, wl + W2_OFF, b2m, x1,
        out, nullptr, nullptr, TOK, DMODEL, FFD);
}

// round 6
// speedup vs baseline: 3.5494x; 1.4918x over previous
#include <cuda_runtime.h>
#include <cuda_fp16.h>
#include <stdint.h>
#include <math.h>

// ---------------- problem constants ----------------
#define NB     2
#define SEQ    2048
#define TOK    4096
#define DMODEL 1024
#define NH     16
#define HD     64
#define FFD    4096
#define LN_EPS 1e-5f

// ---------------- scratch (device globals; no allocation) ----------------
__device__ float  g_x1 [TOK * DMODEL];          // post-attn residual (fp32)
__device__ __half g_qkvh[TOK * 3 * DMODEL];     // QKV (fp16)
__device__ __half g_hh [TOK * DMODEL];          // LN output (fp16)
__device__ __half g_ah [TOK * DMODEL];          // attention output (fp16)
__device__ __half g_fh [TOK * FFD];             // MLP hidden (fp16)
#define WTOT (12 * 1024 * 1024)
__device__ __half g_wh[WTOT], g_wl[WTOT];       // weights hi/lo fp16

#define WQKV_OFF 0
#define WO_OFF   3145728
#define W1_OFF   4194304
#define W2_OFF   8388608

// ==================== helpers ====================
static __device__ __forceinline__ uint32_t smem_u32(const void* p) {
    uint32_t a;
    asm("{ .reg .u64 t; cvta.to.shared.u64 t, %1; cvt.u32.u64 %0, t; }"
        : "=r"(a) : "l"(p));
    return a;
}

static __device__ __forceinline__ void cpasync16(uint32_t s, const void* g) {
    asm volatile(
        "{ .reg .u64 p; cvta.to.global.u64 p, %1; "
        "cp.async.cg.shared.global [%0], [p], 16; }"
        :: "r"(s), "l"(g) : "memory");
}
#define CP_COMMIT() asm volatile("cp.async.commit_group;" ::: "memory")
#define CP_WAIT1()  asm volatile("cp.async.wait_group 1;" ::: "memory")
#define CP_WAIT0()  asm volatile("cp.async.wait_group 0;" ::: "memory")

static __device__ __forceinline__ void ldm4(uint32_t* r, uint32_t addr) {
    asm volatile("ldmatrix.sync.aligned.m8n8.x4.shared.b16 {%0,%1,%2,%3}, [%4];"
        : "=r"(r[0]), "=r"(r[1]), "=r"(r[2]), "=r"(r[3]) : "r"(addr));
}
static __device__ __forceinline__ void ldm4t(uint32_t* r, uint32_t addr) {
    asm volatile("ldmatrix.sync.aligned.m8n8.x4.trans.shared.b16 {%0,%1,%2,%3}, [%4];"
        : "=r"(r[0]), "=r"(r[1]), "=r"(r[2]), "=r"(r[3]) : "r"(addr));
}

static __device__ __forceinline__ void mma_f16(float* c, const uint32_t* a,
                                               uint32_t b0, uint32_t b1) {
    asm volatile(
        "mma.sync.aligned.m16n8k16.row.col.f32.f16.f16.f32 "
        "{%0,%1,%2,%3}, {%4,%5,%6,%7}, {%8,%9}, {%0,%1,%2,%3};"
        : "+f"(c[0]), "+f"(c[1]), "+f"(c[2]), "+f"(c[3])
        : "r"(a[0]), "r"(a[1]), "r"(a[2]), "r"(a[3]), "r"(b0), "r"(b1));
}

// pack two fp32 -> f16x2 register (first arg -> low half)
static __device__ __forceinline__ uint32_t pack_h2(float lo, float hi) {
    uint32_t r;
    asm("cvt.rn.f16x2.f32 %0, %1, %2;" : "=r"(r) : "f"(hi), "f"(lo));
    return r;
}

// ==================== weight hi/lo split (fp16) ====================
__global__ __launch_bounds__(256) void split_kernel(
    const float* __restrict__ w, __half* __restrict__ hi,
    __half* __restrict__ lo, int n)
{
    int i = blockIdx.x * 256 + threadIdx.x;
    if (i < n) {
        float v = w[i];
        __half h = __float2half_rn(v);
        hi[i] = h;
        lo[i] = __float2half_rn(v - __half2float(h));
    }
}

// ==================== LayerNorm -> fp16 ====================
__global__ __launch_bounds__(256) void ln_kernel(
    const float* __restrict__ x, const float* __restrict__ g,
    const float* __restrict__ b, __half* __restrict__ y)
{
    __shared__ float red[8];
    __shared__ float bc[2];
    const int r = blockIdx.x, tid = threadIdx.x;
    const int wid = tid >> 5, lane = tid & 31;

    const float4 v = ((const float4*)(x + (size_t)r * DMODEL))[tid];

    float s = v.x + v.y + v.z + v.w;
    #pragma unroll
    for (int o = 16; o; o >>= 1) s += __shfl_xor_sync(0xffffffffu, s, o);
    if (lane == 0) red[wid] = s;
    __syncthreads();
    if (tid == 0) {
        float t = 0.f;
        #pragma unroll
        for (int i = 0; i < 8; ++i) t += red[i];
        bc[0] = t * (1.0f / DMODEL);
    }
    __syncthreads();
    const float mean = bc[0];

    const float dx = v.x - mean, dy = v.y - mean, dz = v.z - mean, dw = v.w - mean;
    float ss = dx * dx + dy * dy + dz * dz + dw * dw;
    #pragma unroll
    for (int o = 16; o; o >>= 1) ss += __shfl_xor_sync(0xffffffffu, ss, o);
    if (lane == 0) red[wid] = ss;
    __syncthreads();
    if (tid == 0) {
        float t = 0.f;
        #pragma unroll
        for (int i = 0; i < 8; ++i) t += red[i];
        bc[1] = rsqrtf(t * (1.0f / DMODEL) + LN_EPS);
    }
    __syncthreads();
    const float rs = bc[1];

    const float4 gv = ((const float4*)g)[tid];
    const float4 bv = ((const float4*)b)[tid];
    uint2 o2;
    o2.x = pack_h2(dx * rs * gv.x + bv.x, dy * rs * gv.y + bv.y);
    o2.y = pack_h2(dz * rs * gv.z + bv.z, dw * rs * gv.w + bv.w);
    *(uint2*)(y + (size_t)r * DMODEL + tid * 4) = o2;
}

// ==================== mma.sync GEMM (NT, fp16: A * (Bh+Bl)^T) ====================
// CTA tile 128x128, BK=32, 256 threads (8 warps 2x4), warp tile 64x32.
// smem per stage: 3 tiles of 128 rows x 32 fp16, padded stride 40 (80B/row).
#define TILE_B   10240              // 128*80
#define STAGE_B  (3 * TILE_B)       // 30720
#define GEMM_SMEM (2 * STAGE_B)     // 61440

static __device__ __forceinline__ void stage_load(
    uint32_t s0,
    const __half* gA, const __half* gBh, const __half* gBl,
    int m0, int n0, int K, int kt, int tid)
{
    #pragma unroll
    for (int half_ = 0; half_ < 2; ++half_) {
        const int u   = tid + half_ * 256;      // 0..511
        const int row = u >> 2;
        const int seg = u & 3;
        const uint32_t soff = row * 80 + seg * 16;
        const size_t ga = (size_t)(m0 + row) * K + kt + seg * 8;
        const size_t gb = (size_t)(n0 + row) * K + kt + seg * 8;
        cpasync16(s0 +              soff, gA  + ga);
        cpasync16(s0 + TILE_B     + soff, gBh + gb);
        cpasync16(s0 + 2 * TILE_B + soff, gBl + gb);
    }
}

template<bool GELU_F, bool RES_F, bool OUTH_F>
__global__ __launch_bounds__(256, 2)
void gemm_mma(
    const __half* __restrict__ A,
    const __half* __restrict__ Bh, const __half* __restrict__ Bl,
    const float* __restrict__ bias, const float* __restrict__ res,
    float* __restrict__ Cf, __half* __restrict__ Ch,
    int M, int N, int K)
{
    extern __shared__ char dsm[];
    const uint32_t sb = smem_u32(dsm);

    const int tid  = threadIdx.x;
    const int wid  = tid >> 5, lane = tid & 31;
    const int wm   = wid & 1;
    const int wn   = wid >> 1;
    const int m0   = blockIdx.y << 7;
    const int n0   = blockIdx.x << 7;

    float acc[4][4][4];
    #pragma unroll
    for (int i = 0; i < 4; ++i)
        #pragma unroll
        for (int j = 0; j < 4; ++j) {
            acc[i][j][0] = 0.f; acc[i][j][1] = 0.f;
            acc[i][j][2] = 0.f; acc[i][j][3] = 0.f;
        }

    const int lr   = lane & 15;
    const int cof  = (lane >> 4) << 3;
    const uint32_t aRowByte = (uint32_t)(wm * 64 + lr) * 80;
    const uint32_t bRowByte = (uint32_t)(wn * 32 + lr) * 80;

    const int NC = K >> 5;

    stage_load(sb, A, Bh, Bl, m0, n0, K, 0, tid);
    CP_COMMIT();

    for (int c = 0; c < NC; ++c) {
        if (c + 1 < NC) {
            stage_load(sb + ((c + 1) & 1) * STAGE_B, A, Bh, Bl,
                       m0, n0, K, (c + 1) << 5, tid);
            CP_COMMIT();
            CP_WAIT1();
        } else {
            CP_WAIT0();
        }
        __syncthreads();

        const uint32_t s0  = sb + (c & 1) * STAGE_B;
        const uint32_t aA  = s0;
        const uint32_t aBh = s0 + TILE_B;
        const uint32_t aBl = s0 + 2 * TILE_B;

        #pragma unroll
        for (int ks = 0; ks < 2; ++ks) {
            const uint32_t kbyte = (uint32_t)(ks * 16 + cof) * 2;

            uint32_t af[4][4];
            #pragma unroll
            for (int mi = 0; mi < 4; ++mi)
                ldm4(af[mi], aA + aRowByte + (uint32_t)(mi * 16) * 80 + kbyte);

            uint32_t bh[2][4];
            #pragma unroll
            for (int nt = 0; nt < 2; ++nt)
                ldm4(bh[nt], aBh + bRowByte + (uint32_t)(nt * 16) * 80 + kbyte);

            #pragma unroll
            for (int mi = 0; mi < 4; ++mi)
                #pragma unroll
                for (int ni = 0; ni < 4; ++ni)
                    mma_f16(acc[mi][ni], af[mi],
                            bh[ni >> 1][ni & 1], bh[ni >> 1][2 + (ni & 1)]);

            uint32_t bl[2][4];
            #pragma unroll
            for (int nt = 0; nt < 2; ++nt)
                ldm4(bl[nt], aBl + bRowByte + (uint32_t)(nt * 16) * 80 + kbyte);

            #pragma unroll
            for (int mi = 0; mi < 4; ++mi)
                #pragma unroll
                for (int ni = 0; ni < 4; ++ni)
                    mma_f16(acc[mi][ni], af[mi],
                            bl[ni >> 1][ni & 1], bl[ni >> 1][2 + (ni & 1)]);
        }
        __syncthreads();
    }

    const int tr = lane >> 2;
    const int tc = (lane & 3) << 1;
    #pragma unroll
    for (int mi = 0; mi < 4; ++mi) {
        #pragma unroll
        for (int ni = 0; ni < 4; ++ni) {
            const int col = n0 + wn * 32 + ni * 8 + tc;
            #pragma unroll
            for (int half_ = 0; half_ < 2; ++half_) {
                const int row = m0 + wm * 64 + mi * 16 + tr + half_ * 8;
                float vx = acc[mi][ni][half_ * 2 + 0] + bias[col + 0];
                float vy = acc[mi][ni][half_ * 2 + 1] + bias[col + 1];
                if (RES_F) {
                    const float2 rv = *(const float2*)&res[(size_t)row * N + col];
                    vx += rv.x; vy += rv.y;
                }
                if (GELU_F) {
                    vx = 0.5f * vx * (1.0f + erff(vx * 0.70710678f));
                    vy = 0.5f * vy * (1.0f + erff(vy * 0.70710678f));
                }
                const size_t off = (size_t)row * N + col;
                if (OUTH_F) {
                    *(uint32_t*)(Ch + off) = pack_h2(vx, vy);
                } else {
                    float2 o; o.x = vx; o.y = vy;
                    *(float2*)&Cf[off] = o;
                }
            }
        }
    }
}

// ==================== Tensor-core flash attention (fp16, cp.async) ====================
// CTA: 128 q-rows, 8 warps. grid (SEQ/128, NH, NB).
// dyn smem: Q (128x72 fp16 = 18KB) + 2 KV stages (each K+V = 36KB) = 90KB.
#define AQ    128
#define AKV   128
#define ASTRB 144                 // bytes per smem row (72 fp16)
#define Q_OFF 0
#define KV_OFF 18432
#define KV_STG 36864
#define ATTN_SMEM (KV_OFF + 2 * KV_STG)   // 92160

__global__ __launch_bounds__(256) void attn_mma(
    const __half* __restrict__ qkv, __half* __restrict__ oh)
{
    extern __shared__ char asm_[];
    const uint32_t sB = smem_u32(asm_);

    const int tid = threadIdx.x;
    const int w = tid >> 5, lane = tid & 31;
    const int g = lane >> 2, t = lane & 3;
    const int b = blockIdx.z, h = blockIdx.y;
    const int q0 = blockIdx.x * AQ;

    const int lrow = tid >> 1;        // 0..127
    const int lhf  = tid & 1;         // 64-byte half-row

    const __half* tokbase = qkv + (size_t)(b * SEQ) * (3 * DMODEL) + h * 192;

    // ---- stage Q via cp.async ----
    {
        const __half* qp = tokbase + (size_t)(q0 + lrow) * (3 * DMODEL) + lhf * 32;
        const uint32_t sq = sB + Q_OFF + lrow * ASTRB + lhf * 64;
        #pragma unroll
        for (int s = 0; s < 4; ++s)
            cpasync16(sq + s * 16, qp + s * 8);
    }
    CP_COMMIT();
    CP_WAIT0();
    __syncthreads();

    uint32_t qf[4][4];
    {
        const uint32_t rb = sB + Q_OFF + (uint32_t)(w * 16 + (lane & 15)) * ASTRB
                          + (uint32_t)(((lane >> 4) & 1) * 8) * 2;
        #pragma unroll
        for (int ks = 0; ks < 4; ++ks)
            ldm4(qf[ks], rb + ks * 32);
    }
    __syncthreads();

    float oc[8][4];
    #pragma unroll
    for (int i = 0; i < 8; ++i) {
        oc[i][0] = 0.f; oc[i][1] = 0.f; oc[i][2] = 0.f; oc[i][3] = 0.f;
    }
    float mrow[2] = {-INFINITY, -INFINITY};
    float lsum[2] = {0.f, 0.f};

    const int NT = SEQ / AKV;   // 16

    // prefetch KV tile 0
    {
        const __half* kp = tokbase + (size_t)lrow * (3 * DMODEL) + 64 + lhf * 32;
        const uint32_t sk = sB + KV_OFF + lrow * ASTRB + lhf * 64;
        #pragma unroll
        for (int s = 0; s < 4; ++s) cpasync16(sk + s * 16, kp + s * 8);
        const uint32_t sv = sk + 18432;
        #pragma unroll
        for (int s = 0; s < 4; ++s) cpasync16(sv + s * 16, kp + 64 + s * 8);
    }
    CP_COMMIT();

    for (int tI = 0; tI < NT; ++tI) {
        if (tI + 1 < NT) {
            const int kv1 = (tI + 1) * AKV;
            const __half* kp = tokbase + (size_t)(kv1 + lrow) * (3 * DMODEL) + 64 + lhf * 32;
            const uint32_t sk = sB + KV_OFF + ((tI + 1) & 1) * KV_STG + lrow * ASTRB + lhf * 64;
            #pragma unroll
            for (int s = 0; s < 4; ++s) cpasync16(sk + s * 16, kp + s * 8);
            const uint32_t sv = sk + 18432;
            #pragma unroll
            for (int s = 0; s < 4; ++s) cpasync16(sv + s * 16, kp + 64 + s * 8);
            CP_COMMIT();
            CP_WAIT1();
        } else {
            CP_WAIT0();
        }
        __syncthreads();

        const uint32_t ksB = sB + KV_OFF + (tI & 1) * KV_STG;
        const uint32_t vsB = ksB + 18432;

        // ---- S = Q K^T (raw, scale folded into softmax) ----
        float sc[16][4];
        #pragma unroll
        for (int nt2 = 0; nt2 < 8; ++nt2) {
            #pragma unroll
            for (int q2 = 0; q2 < 4; ++q2) {
                sc[2 * nt2][q2] = 0.f; sc[2 * nt2 + 1][q2] = 0.f;
            }
            #pragma unroll
            for (int ks = 0; ks < 4; ++ks) {
                uint32_t bf[4];
                const uint32_t addr = ksB
                    + (uint32_t)(nt2 * 16 + (lane & 7) + ((lane >> 4) & 1) * 8) * ASTRB
                    + (uint32_t)(ks * 16 + ((lane >> 3) & 1) * 8) * 2;
                ldm4(bf, addr);
                mma_f16(sc[2 * nt2],     qf[ks], bf[0], bf[1]);
                mma_f16(sc[2 * nt2 + 1], qf[ks], bf[2], bf[3]);
            }
        }

        // ---- online softmax over scaled scores (x0.125) ----
        float alpha[2];
        #pragma unroll
        for (int r = 0; r < 2; ++r) {
            float mx = -INFINITY;
            #pragma unroll
            for (int nt = 0; nt < 16; ++nt)
                mx = fmaxf(mx, fmaxf(sc[nt][2 * r], sc[nt][2 * r + 1]));
            mx = fmaxf(mx, __shfl_xor_sync(0xffffffffu, mx, 1));
            mx = fmaxf(mx, __shfl_xor_sync(0xffffffffu, mx, 2));
            const float mn = fmaxf(mrow[r], mx);
            alpha[r] = __expf((mrow[r] - mn) * 0.125f);
            mrow[r] = mn;
            float rs = 0.f;
            #pragma unroll
            for (int nt = 0; nt < 16; ++nt) {
                const float e0 = __expf((sc[nt][2 * r]     - mn) * 0.125f);
                const float e1 = __expf((sc[nt][2 * r + 1] - mn) * 0.125f);
                sc[nt][2 * r] = e0; sc[nt][2 * r + 1] = e1;
                rs += e0 + e1;
            }
            rs += __shfl_xor_sync(0xffffffffu, rs, 1);
            rs += __shfl_xor_sync(0xffffffffu, rs, 2);
            lsum[r] = lsum[r] * alpha[r] + rs;
        }
        #pragma unroll
        for (int dt = 0; dt < 8; ++dt) {
            oc[dt][0] *= alpha[0]; oc[dt][1] *= alpha[0];
            oc[dt][2] *= alpha[1]; oc[dt][3] *= alpha[1];
        }

        // ---- P fragments (registers only) ----
        uint32_t pf[8][4];
        #pragma unroll
        for (int ks = 0; ks < 8; ++ks) {
            pf[ks][0] = pack_h2(sc[2 * ks][0],     sc[2 * ks][1]);
            pf[ks][1] = pack_h2(sc[2 * ks][2],     sc[2 * ks][3]);
            pf[ks][2] = pack_h2(sc[2 * ks + 1][0], sc[2 * ks + 1][1]);
            pf[ks][3] = pack_h2(sc[2 * ks + 1][2], sc[2 * ks + 1][3]);
        }

        // ---- O += P V ----
        #pragma unroll
        for (int ks = 0; ks < 8; ++ks) {
            #pragma unroll
            for (int dt2 = 0; dt2 < 4; ++dt2) {
                uint32_t bv[4];
                const uint32_t addr = vsB
                    + (uint32_t)(ks * 16 + (lane & 7) + ((lane >> 3) & 1) * 8) * ASTRB
                    + (uint32_t)(dt2 * 16 + ((lane >> 4) & 1) * 8) * 2;
                ldm4t(bv, addr);
                mma_f16(oc[2 * dt2],     pf[ks], bv[0], bv[1]);
                mma_f16(oc[2 * dt2 + 1], pf[ks], bv[2], bv[3]);
            }
        }
        __syncthreads();
    }

    // ---- normalize + write fp16 ----
    #pragma unroll
    for (int r = 0; r < 2; ++r) {
        const float inv = 1.0f / lsum[r];
        const int row = q0 + w * 16 + g + r * 8;
        const size_t base = (size_t)(b * SEQ + row) * DMODEL + h * HD + t * 2;
        #pragma unroll
        for (int dt = 0; dt < 8; ++dt) {
            *(uint32_t*)(oh + base + dt * 8) =
                pack_h2(oc[dt][2 * r] * inv, oc[dt][2 * r + 1] * inv);
        }
    }
}

// ==================== launch ====================
extern "C" void kernel_launch(void* const* d_in, const int* in_sizes, int n_in,
                              void* d_out, int out_size)
{
    (void)in_sizes; (void)n_in; (void)out_size;
    const float* x    = (const float*)d_in[0];
    const float* g1   = (const float*)d_in[1];
    const float* b1   = (const float*)d_in[2];
    const float* Wqkv = (const float*)d_in[3];
    const float* bqkv = (const float*)d_in[4];
    const float* Wo   = (const float*)d_in[5];
    const float* bo   = (const float*)d_in[6];
    const float* g2   = (const float*)d_in[7];
    const float* b2   = (const float*)d_in[8];
    const float* W1   = (const float*)d_in[9];
    const float* b1m  = (const float*)d_in[10];
    const float* W2   = (const float*)d_in[11];
    const float* b2m  = (const float*)d_in[12];
    float* out = (float*)d_out;

    float* x1;
    __half *qkvh, *hh, *ah, *fh, *wh, *wl;
    cudaGetSymbolAddress((void**)&x1,   g_x1);
    cudaGetSymbolAddress((void**)&qkvh, g_qkvh);
    cudaGetSymbolAddress((void**)&hh,   g_hh);
    cudaGetSymbolAddress((void**)&ah,   g_ah);
    cudaGetSymbolAddress((void**)&fh,   g_fh);
    cudaGetSymbolAddress((void**)&wh,   g_wh);
    cudaGetSymbolAddress((void**)&wl,   g_wl);

    cudaFuncSetAttribute(gemm_mma<false, false, true>,
                         cudaFuncAttributeMaxDynamicSharedMemorySize, GEMM_SMEM);
    cudaFuncSetAttribute(gemm_mma<false, true, false>,
                         cudaFuncAttributeMaxDynamicSharedMemorySize, GEMM_SMEM);
    cudaFuncSetAttribute(gemm_mma<true, false, true>,
                         cudaFuncAttributeMaxDynamicSharedMemorySize, GEMM_SMEM);
    cudaFuncSetAttribute(attn_mma,
                         cudaFuncAttributeMaxDynamicSharedMemorySize, ATTN_SMEM);

    // 0) split weights to fp16 hi/lo
    split_kernel<<<(3 * DMODEL * DMODEL + 255) / 256, 256>>>(Wqkv, wh + WQKV_OFF, wl + WQKV_OFF, 3 * DMODEL * DMODEL);
    split_kernel<<<(DMODEL * DMODEL + 255) / 256, 256>>>(Wo, wh + WO_OFF, wl + WO_OFF, DMODEL * DMODEL);
    split_kernel<<<(FFD * DMODEL + 255) / 256, 256>>>(W1, wh + W1_OFF, wl + W1_OFF, FFD * DMODEL);
    split_kernel<<<(DMODEL * FFD + 255) / 256, 256>>>(W2, wh + W2_OFF, wl + W2_OFF, DMODEL * FFD);

    // 1) h = LN1(x) (fp16)
    ln_kernel<<<TOK, 256>>>(x, g1, b1, hh);
    // 2) qkv = h @ Wqkv^T + bqkv (fp16 out)
    gemm_mma<false, false, true><<<dim3(3 * DMODEL / 128, TOK / 128), 256, GEMM_SMEM>>>(
        hh, wh + WQKV_OFF, wl + WQKV_OFF, bqkv, nullptr,
        nullptr, qkvh, TOK, 3 * DMODEL, DMODEL);
    // 3) attention (fp16 in/out)
    attn_mma<<<dim3(SEQ / AQ, NH, NB), 256, ATTN_SMEM>>>(qkvh, ah);
    // 4) x1 = x + att @ Wo^T + bo (fp32 out)
    gemm_mma<false, true, false><<<dim3(DMODEL / 128, TOK / 128), 256, GEMM_SMEM>>>(
        ah, wh + WO_OFF, wl + WO_OFF, bo, x,
        x1, nullptr, TOK, DMODEL, DMODEL);
    // 5) h = LN2(x1)
    ln_kernel<<<TOK, 256>>>(x1, g2, b2, hh);
    // 6) ffh = gelu(h @ W1^T + b1m) (fp16 out)
    gemm_mma<true, false, true><<<dim3(FFD / 128, TOK / 128), 256, GEMM_SMEM>>>(
        hh, wh + W1_OFF, wl + W1_OFF, b1m, nullptr,
        nullptr, fh, TOK, FFD, DMODEL);
    // 7) out = x1 + ffh @ W2^T + b2m (fp32 out)
    gemm_mma<false, true, false><<<dim3(DMODEL / 128, TOK / 128), 256, GEMM_SMEM>>>(
        fh, wh + W2_OFF, wl + W2_OFF, b2m, x1,
        out, nullptr, TOK, DMODEL, FFD);
}

// round 7
// speedup vs baseline: 4.0945x; 1.1536x over previous
#include <cuda_runtime.h>
#include <cuda_fp16.h>
#include <stdint.h>
#include <math.h>

// ---------------- problem constants ----------------
#define NB     2
#define SEQ    2048
#define TOK    4096
#define DMODEL 1024
#define NH     16
#define HD     64
#define FFD    4096
#define LN_EPS 1e-5f

// ---------------- scratch (device globals; no allocation) ----------------
__device__ float  g_x1 [TOK * DMODEL];          // post-attn residual (fp32)
__device__ __half g_qkvh[TOK * 3 * DMODEL];     // QKV (fp16)
__device__ __half g_hh [TOK * DMODEL];          // LN output (fp16)
__device__ __half g_ah [TOK * DMODEL];          // attention output (fp16)
__device__ __half g_fh [TOK * FFD];             // MLP hidden (fp16)
#define WTOT (12 * 1024 * 1024)
__device__ __half g_wh[WTOT], g_wl[WTOT];       // weights hi (all) / lo (W1,W2)

#define WQKV_OFF 0
#define WO_OFF   3145728
#define W1_OFF   4194304
#define W2_OFF   8388608

// ==================== helpers ====================
static __device__ __forceinline__ uint32_t smem_u32(const void* p) {
    uint32_t a;
    asm("{ .reg .u64 t; cvta.to.shared.u64 t, %1; cvt.u32.u64 %0, t; }"
        : "=r"(a) : "l"(p));
    return a;
}

static __device__ __forceinline__ void cpasync16(uint32_t s, const void* g) {
    asm volatile(
        "{ .reg .u64 p; cvta.to.global.u64 p, %1; "
        "cp.async.cg.shared.global [%0], [p], 16; }"
        :: "r"(s), "l"(g) : "memory");
}
#define CP_COMMIT() asm volatile("cp.async.commit_group;" ::: "memory")
#define CP_WAIT1()  asm volatile("cp.async.wait_group 1;" ::: "memory")
#define CP_WAIT0()  asm volatile("cp.async.wait_group 0;" ::: "memory")

static __device__ __forceinline__ void ldm4(uint32_t* r, uint32_t addr) {
    asm volatile("ldmatrix.sync.aligned.m8n8.x4.shared.b16 {%0,%1,%2,%3}, [%4];"
        : "=r"(r[0]), "=r"(r[1]), "=r"(r[2]), "=r"(r[3]) : "r"(addr));
}
static __device__ __forceinline__ void ldm4t(uint32_t* r, uint32_t addr) {
    asm volatile("ldmatrix.sync.aligned.m8n8.x4.trans.shared.b16 {%0,%1,%2,%3}, [%4];"
        : "=r"(r[0]), "=r"(r[1]), "=r"(r[2]), "=r"(r[3]) : "r"(addr));
}

static __device__ __forceinline__ void mma_f16(float* c, const uint32_t* a,
                                               uint32_t b0, uint32_t b1) {
    asm volatile(
        "mma.sync.aligned.m16n8k16.row.col.f32.f16.f16.f32 "
        "{%0,%1,%2,%3}, {%4,%5,%6,%7}, {%8,%9}, {%0,%1,%2,%3};"
        : "+f"(c[0]), "+f"(c[1]), "+f"(c[2]), "+f"(c[3])
        : "r"(a[0]), "r"(a[1]), "r"(a[2]), "r"(a[3]), "r"(b0), "r"(b1));
}

// pack two fp32 -> f16x2 register (first arg -> low half)
static __device__ __forceinline__ uint32_t pack_h2(float lo, float hi) {
    uint32_t r;
    asm("cvt.rn.f16x2.f32 %0, %1, %2;" : "=r"(r) : "f"(hi), "f"(lo));
    return r;
}
static __device__ __forceinline__ uint32_t ex2_h2(uint32_t x) {
    uint32_t r;
    asm("ex2.approx.f16x2 %0, %1;" : "=r"(r) : "r"(x));
    return r;
}

// ==================== weight conversion kernels ====================
__global__ __launch_bounds__(256) void conv_kernel(
    const float4* __restrict__ w, uint2* __restrict__ hi, int n4)
{
    int i = blockIdx.x * 256 + threadIdx.x;
    if (i < n4) {
        const float4 v = w[i];
        uint2 o;
        o.x = pack_h2(v.x, v.y);
        o.y = pack_h2(v.z, v.w);
        hi[i] = o;
    }
}
__global__ __launch_bounds__(256) void split_kernel(
    const float4* __restrict__ w, uint2* __restrict__ hi,
    uint2* __restrict__ lo, int n4)
{
    int i = blockIdx.x * 256 + threadIdx.x;
    if (i < n4) {
        const float4 v = w[i];
        __half h0 = __float2half_rn(v.x), h1 = __float2half_rn(v.y);
        __half h2 = __float2half_rn(v.z), h3 = __float2half_rn(v.w);
        uint2 oh, ol;
        oh.x = ((uint32_t)__half_as_ushort(h1) << 16) | __half_as_ushort(h0);
        oh.y = ((uint32_t)__half_as_ushort(h3) << 16) | __half_as_ushort(h2);
        ol.x = pack_h2(v.x - __half2float(h0), v.y - __half2float(h1));
        ol.y = pack_h2(v.z - __half2float(h2), v.w - __half2float(h3));
        hi[i] = oh;
        lo[i] = ol;
    }
}

// ==================== LayerNorm -> fp16 ====================
__global__ __launch_bounds__(256) void ln_kernel(
    const float* __restrict__ x, const float* __restrict__ g,
    const float* __restrict__ b, __half* __restrict__ y)
{
    __shared__ float red[8];
    __shared__ float bc[2];
    const int r = blockIdx.x, tid = threadIdx.x;
    const int wid = tid >> 5, lane = tid & 31;

    const float4 v = ((const float4*)(x + (size_t)r * DMODEL))[tid];

    float s = v.x + v.y + v.z + v.w;
    #pragma unroll
    for (int o = 16; o; o >>= 1) s += __shfl_xor_sync(0xffffffffu, s, o);
    if (lane == 0) red[wid] = s;
    __syncthreads();
    if (tid == 0) {
        float t = 0.f;
        #pragma unroll
        for (int i = 0; i < 8; ++i) t += red[i];
        bc[0] = t * (1.0f / DMODEL);
    }
    __syncthreads();
    const float mean = bc[0];

    const float dx = v.x - mean, dy = v.y - mean, dz = v.z - mean, dw = v.w - mean;
    float ss = dx * dx + dy * dy + dz * dz + dw * dw;
    #pragma unroll
    for (int o = 16; o; o >>= 1) ss += __shfl_xor_sync(0xffffffffu, ss, o);
    if (lane == 0) red[wid] = ss;
    __syncthreads();
    if (tid == 0) {
        float t = 0.f;
        #pragma unroll
        for (int i = 0; i < 8; ++i) t += red[i];
        bc[1] = rsqrtf(t * (1.0f / DMODEL) + LN_EPS);
    }
    __syncthreads();
    const float rs = bc[1];

    const float4 gv = ((const float4*)g)[tid];
    const float4 bv = ((const float4*)b)[tid];
    uint2 o2;
    o2.x = pack_h2(dx * rs * gv.x + bv.x, dy * rs * gv.y + bv.y);
    o2.y = pack_h2(dz * rs * gv.z + bv.z, dw * rs * gv.w + bv.w);
    *(uint2*)(y + (size_t)r * DMODEL + tid * 4) = o2;
}

// ==================== mma.sync GEMM (NT, fp16, 1 or 2 weight terms) ====================
#define TILE_B   10240              // 128*80

template<int TERMS>
static __device__ __forceinline__ void stage_load(
    uint32_t s0,
    const __half* gA, const __half* gBh, const __half* gBl,
    int m0, int n0, int K, int kt, int tid)
{
    #pragma unroll
    for (int half_ = 0; half_ < 2; ++half_) {
        const int u   = tid + half_ * 256;
        const int row = u >> 2;
        const int seg = u & 3;
        const uint32_t soff = row * 80 + seg * 16;
        const size_t ga = (size_t)(m0 + row) * K + kt + seg * 8;
        const size_t gb = (size_t)(n0 + row) * K + kt + seg * 8;
        cpasync16(s0 +          soff, gA  + ga);
        cpasync16(s0 + TILE_B + soff, gBh + gb);
        if (TERMS == 2)
            cpasync16(s0 + 2 * TILE_B + soff, gBl + gb);
    }
}

template<int TERMS, bool GELU_F, bool RES_F, bool OUTH_F>
__global__ __launch_bounds__(256, 2)
void gemm_mma(
    const __half* __restrict__ A,
    const __half* __restrict__ Bh, const __half* __restrict__ Bl,
    const float* __restrict__ bias, const float* __restrict__ res,
    float* __restrict__ Cf, __half* __restrict__ Ch,
    int M, int N, int K)
{
    constexpr uint32_t STG = (1 + TERMS) * TILE_B;
    extern __shared__ char dsm[];
    const uint32_t sb = smem_u32(dsm);

    const int tid  = threadIdx.x;
    const int wid  = tid >> 5, lane = tid & 31;
    const int wm   = wid & 1;
    const int wn   = wid >> 1;
    const int m0   = blockIdx.y << 7;
    const int n0   = blockIdx.x << 7;

    float acc[4][4][4];
    #pragma unroll
    for (int i = 0; i < 4; ++i)
        #pragma unroll
        for (int j = 0; j < 4; ++j) {
            acc[i][j][0] = 0.f; acc[i][j][1] = 0.f;
            acc[i][j][2] = 0.f; acc[i][j][3] = 0.f;
        }

    const int lr   = lane & 15;
    const int cof  = (lane >> 4) << 3;
    const uint32_t aRowByte = (uint32_t)(wm * 64 + lr) * 80;
    const uint32_t bRowByte = (uint32_t)(wn * 32 + lr) * 80;

    const int NC = K >> 5;

    stage_load<TERMS>(sb, A, Bh, Bl, m0, n0, K, 0, tid);
    CP_COMMIT();

    for (int c = 0; c < NC; ++c) {
        if (c + 1 < NC) {
            stage_load<TERMS>(sb + ((c + 1) & 1) * STG, A, Bh, Bl,
                              m0, n0, K, (c + 1) << 5, tid);
            CP_COMMIT();
            CP_WAIT1();
        } else {
            CP_WAIT0();
        }
        __syncthreads();

        const uint32_t s0  = sb + (c & 1) * STG;
        const uint32_t aA  = s0;
        const uint32_t aBh = s0 + TILE_B;
        const uint32_t aBl = s0 + 2 * TILE_B;

        #pragma unroll
        for (int ks = 0; ks < 2; ++ks) {
            const uint32_t kbyte = (uint32_t)(ks * 16 + cof) * 2;

            uint32_t af[4][4];
            #pragma unroll
            for (int mi = 0; mi < 4; ++mi)
                ldm4(af[mi], aA + aRowByte + (uint32_t)(mi * 16) * 80 + kbyte);

            uint32_t bh[2][4];
            #pragma unroll
            for (int nt = 0; nt < 2; ++nt)
                ldm4(bh[nt], aBh + bRowByte + (uint32_t)(nt * 16) * 80 + kbyte);

            #pragma unroll
            for (int mi = 0; mi < 4; ++mi)
                #pragma unroll
                for (int ni = 0; ni < 4; ++ni)
                    mma_f16(acc[mi][ni], af[mi],
                            bh[ni >> 1][ni & 1], bh[ni >> 1][2 + (ni & 1)]);

            if (TERMS == 2) {
                uint32_t bl[2][4];
                #pragma unroll
                for (int nt = 0; nt < 2; ++nt)
                    ldm4(bl[nt], aBl + bRowByte + (uint32_t)(nt * 16) * 80 + kbyte);

                #pragma unroll
                for (int mi = 0; mi < 4; ++mi)
                    #pragma unroll
                    for (int ni = 0; ni < 4; ++ni)
                        mma_f16(acc[mi][ni], af[mi],
                                bl[ni >> 1][ni & 1], bl[ni >> 1][2 + (ni & 1)]);
            }
        }
        __syncthreads();
    }

    const int tr = lane >> 2;
    const int tc = (lane & 3) << 1;
    #pragma unroll
    for (int mi = 0; mi < 4; ++mi) {
        #pragma unroll
        for (int ni = 0; ni < 4; ++ni) {
            const int col = n0 + wn * 32 + ni * 8 + tc;
            #pragma unroll
            for (int half_ = 0; half_ < 2; ++half_) {
                const int row = m0 + wm * 64 + mi * 16 + tr + half_ * 8;
                float vx = acc[mi][ni][half_ * 2 + 0] + bias[col + 0];
                float vy = acc[mi][ni][half_ * 2 + 1] + bias[col + 1];
                if (RES_F) {
                    const float2 rv = *(const float2*)&res[(size_t)row * N + col];
                    vx += rv.x; vy += rv.y;
                }
                if (GELU_F) {
                    vx = 0.5f * vx * (1.0f + erff(vx * 0.70710678f));
                    vy = 0.5f * vy * (1.0f + erff(vy * 0.70710678f));
                }
                const size_t off = (size_t)row * N + col;
                if (OUTH_F) {
                    *(uint32_t*)(Ch + off) = pack_h2(vx, vy);
                } else {
                    float2 o; o.x = vx; o.y = vy;
                    *(float2*)&Cf[off] = o;
                }
            }
        }
    }
}

// ==================== Tensor-core flash attention (fp16, cp.async) ====================
#define AQ    128
#define AKV   128
#define ASTRB 144
#define Q_OFF 0
#define KV_OFF 18432
#define KV_STG 36864
#define ATTN_SMEM (KV_OFF + 2 * KV_STG)   // 92160

__global__ __launch_bounds__(256) void attn_mma(
    const __half* __restrict__ qkv, __half* __restrict__ oh)
{
    extern __shared__ char asm_[];
    const uint32_t sB = smem_u32(asm_);

    const int tid = threadIdx.x;
    const int w = tid >> 5, lane = tid & 31;
    const int g = lane >> 2, t = lane & 3;
    const int b = blockIdx.z, h = blockIdx.y;
    const int q0 = blockIdx.x * AQ;

    const int lrow = tid >> 1;
    const int lhf  = tid & 1;

    const __half* tokbase = qkv + (size_t)(b * SEQ) * (3 * DMODEL) + h * 192;

    // ---- stage Q via cp.async ----
    {
        const __half* qp = tokbase + (size_t)(q0 + lrow) * (3 * DMODEL) + lhf * 32;
        const uint32_t sq = sB + Q_OFF + lrow * ASTRB + lhf * 64;
        #pragma unroll
        for (int s = 0; s < 4; ++s)
            cpasync16(sq + s * 16, qp + s * 8);
    }
    CP_COMMIT();
    CP_WAIT0();
    __syncthreads();

    uint32_t qf[4][4];
    {
        const uint32_t rb = sB + Q_OFF + (uint32_t)(w * 16 + (lane & 15)) * ASTRB
                          + (uint32_t)(((lane >> 4) & 1) * 8) * 2;
        #pragma unroll
        for (int ks = 0; ks < 4; ++ks)
            ldm4(qf[ks], rb + ks * 32);
    }
    __syncthreads();

    float oc[8][4];
    #pragma unroll
    for (int i = 0; i < 8; ++i) {
        oc[i][0] = 0.f; oc[i][1] = 0.f; oc[i][2] = 0.f; oc[i][3] = 0.f;
    }
    float mrow[2] = {-INFINITY, -INFINITY};
    float lsum[2] = {0.f, 0.f};

    const int NT = SEQ / AKV;
    const float K1 = 0.125f * 1.4426950408889634f;   // log2(e)/8

    // prefetch KV tile 0
    {
        const __half* kp = tokbase + (size_t)lrow * (3 * DMODEL) + 64 + lhf * 32;
        const uint32_t sk = sB + KV_OFF + lrow * ASTRB + lhf * 64;
        #pragma unroll
        for (int s = 0; s < 4; ++s) cpasync16(sk + s * 16, kp + s * 8);
        const uint32_t sv = sk + 18432;
        #pragma unroll
        for (int s = 0; s < 4; ++s) cpasync16(sv + s * 16, kp + 64 + s * 8);
    }
    CP_COMMIT();

    for (int tI = 0; tI < NT; ++tI) {
        if (tI + 1 < NT) {
            const int kv1 = (tI + 1) * AKV;
            const __half* kp = tokbase + (size_t)(kv1 + lrow) * (3 * DMODEL) + 64 + lhf * 32;
            const uint32_t sk = sB + KV_OFF + ((tI + 1) & 1) * KV_STG + lrow * ASTRB + lhf * 64;
            #pragma unroll
            for (int s = 0; s < 4; ++s) cpasync16(sk + s * 16, kp + s * 8);
            const uint32_t sv = sk + 18432;
            #pragma unroll
            for (int s = 0; s < 4; ++s) cpasync16(sv + s * 16, kp + 64 + s * 8);
            CP_COMMIT();
            CP_WAIT1();
        } else {
            CP_WAIT0();
        }
        __syncthreads();

        const uint32_t ksB = sB + KV_OFF + (tI & 1) * KV_STG;
        const uint32_t vsB = ksB + 18432;

        // ---- S = Q K^T ----
        float sc[16][4];
        #pragma unroll
        for (int nt2 = 0; nt2 < 8; ++nt2) {
            #pragma unroll
            for (int q2 = 0; q2 < 4; ++q2) {
                sc[2 * nt2][q2] = 0.f; sc[2 * nt2 + 1][q2] = 0.f;
            }
            #pragma unroll
            for (int ks = 0; ks < 4; ++ks) {
                uint32_t bf[4];
                const uint32_t addr = ksB
                    + (uint32_t)(nt2 * 16 + (lane & 7) + ((lane >> 4) & 1) * 8) * ASTRB
                    + (uint32_t)(ks * 16 + ((lane >> 3) & 1) * 8) * 2;
                ldm4(bf, addr);
                mma_f16(sc[2 * nt2],     qf[ks], bf[0], bf[1]);
                mma_f16(sc[2 * nt2 + 1], qf[ks], bf[2], bf[3]);
            }
        }

        // ---- online softmax, exp via ex2.approx.f16x2 ----
        uint32_t pf[8][4];
        float alpha[2];
        #pragma unroll
        for (int r = 0; r < 2; ++r) {
            float mx = -INFINITY;
            #pragma unroll
            for (int nt = 0; nt < 16; ++nt)
                mx = fmaxf(mx, fmaxf(sc[nt][2 * r], sc[nt][2 * r + 1]));
            mx = fmaxf(mx, __shfl_xor_sync(0xffffffffu, mx, 1));
            mx = fmaxf(mx, __shfl_xor_sync(0xffffffffu, mx, 2));
            const float mn = fmaxf(mrow[r], mx);
            alpha[r] = __expf((mrow[r] - mn) * 0.125f);
            mrow[r] = mn;
            const float c2 = -mn * K1;
            float rs = 0.f;
            #pragma unroll
            for (int nt = 0; nt < 16; ++nt) {
                const float t0 = fmaf(sc[nt][2 * r],     K1, c2);
                const float t1 = fmaf(sc[nt][2 * r + 1], K1, c2);
                const uint32_t pe = ex2_h2(pack_h2(t0, t1));
                pf[nt >> 1][((nt & 1) << 1) + r] = pe;
                const float2 f2 = __half22float2(*(const __half2*)&pe);
                rs += f2.x + f2.y;
            }
            rs += __shfl_xor_sync(0xffffffffu, rs, 1);
            rs += __shfl_xor_sync(0xffffffffu, rs, 2);
            lsum[r] = lsum[r] * alpha[r] + rs;
        }
        #pragma unroll
        for (int dt = 0; dt < 8; ++dt) {
            oc[dt][0] *= alpha[0]; oc[dt][1] *= alpha[0];
            oc[dt][2] *= alpha[1]; oc[dt][3] *= alpha[1];
        }

        // ---- O += P V ----
        #pragma unroll
        for (int ks = 0; ks < 8; ++ks) {
            #pragma unroll
            for (int dt2 = 0; dt2 < 4; ++dt2) {
                uint32_t bv[4];
                const uint32_t addr = vsB
                    + (uint32_t)(ks * 16 + (lane & 7) + ((lane >> 3) & 1) * 8) * ASTRB
                    + (uint32_t)(dt2 * 16 + ((lane >> 4) & 1) * 8) * 2;
                ldm4t(bv, addr);
                mma_f16(oc[2 * dt2],     pf[ks], bv[0], bv[1]);
                mma_f16(oc[2 * dt2 + 1], pf[ks], bv[2], bv[3]);
            }
        }
        __syncthreads();
    }

    // ---- normalize + write fp16 ----
    #pragma unroll
    for (int r = 0; r < 2; ++r) {
        const float inv = 1.0f / lsum[r];
        const int row = q0 + w * 16 + g + r * 8;
        const size_t base = (size_t)(b * SEQ + row) * DMODEL + h * HD + t * 2;
        #pragma unroll
        for (int dt = 0; dt < 8; ++dt) {
            *(uint32_t*)(oh + base + dt * 8) =
                pack_h2(oc[dt][2 * r] * inv, oc[dt][2 * r + 1] * inv);
        }
    }
}

// ==================== launch ====================
extern "C" void kernel_launch(void* const* d_in, const int* in_sizes, int n_in,
                              void* d_out, int out_size)
{
    (void)in_sizes; (void)n_in; (void)out_size;
    const float* x    = (const float*)d_in[0];
    const float* g1   = (const float*)d_in[1];
    const float* b1   = (const float*)d_in[2];
    const float* Wqkv = (const float*)d_in[3];
    const float* bqkv = (const float*)d_in[4];
    const float* Wo   = (const float*)d_in[5];
    const float* bo   = (const float*)d_in[6];
    const float* g2   = (const float*)d_in[7];
    const float* b2   = (const float*)d_in[8];
    const float* W1   = (const float*)d_in[9];
    const float* b1m  = (const float*)d_in[10];
    const float* W2   = (const float*)d_in[11];
    const float* b2m  = (const float*)d_in[12];
    float* out = (float*)d_out;

    float* x1;
    __half *qkvh, *hh, *ah, *fh, *wh, *wl;
    cudaGetSymbolAddress((void**)&x1,   g_x1);
    cudaGetSymbolAddress((void**)&qkvh, g_qkvh);
    cudaGetSymbolAddress((void**)&hh,   g_hh);
    cudaGetSymbolAddress((void**)&ah,   g_ah);
    cudaGetSymbolAddress((void**)&fh,   g_fh);
    cudaGetSymbolAddress((void**)&wh,   g_wh);
    cudaGetSymbolAddress((void**)&wl,   g_wl);

    const int SM1 = 2 * 2 * TILE_B;   // 40960
    const int SM2 = 2 * 3 * TILE_B;   // 61440
    cudaFuncSetAttribute(gemm_mma<1, false, false, true>,
                         cudaFuncAttributeMaxDynamicSharedMemorySize, SM1);
    cudaFuncSetAttribute(gemm_mma<1, false, true, false>,
                         cudaFuncAttributeMaxDynamicSharedMemorySize, SM1);
    cudaFuncSetAttribute(gemm_mma<2, true, false, true>,
                         cudaFuncAttributeMaxDynamicSharedMemorySize, SM2);
    cudaFuncSetAttribute(gemm_mma<2, false, true, false>,
                         cudaFuncAttributeMaxDynamicSharedMemorySize, SM2);
    cudaFuncSetAttribute(attn_mma,
                         cudaFuncAttributeMaxDynamicSharedMemorySize, ATTN_SMEM);

    // 0) weight prep
    conv_kernel<<<(3 * DMODEL * DMODEL / 4 + 255) / 256, 256>>>(
        (const float4*)Wqkv, (uint2*)(wh + WQKV_OFF), 3 * DMODEL * DMODEL / 4);
    conv_kernel<<<(DMODEL * DMODEL / 4 + 255) / 256, 256>>>(
        (const float4*)Wo, (uint2*)(wh + WO_OFF), DMODEL * DMODEL / 4);
    split_kernel<<<(FFD * DMODEL / 4 + 255) / 256, 256>>>(
        (const float4*)W1, (uint2*)(wh + W1_OFF), (uint2*)(wl + W1_OFF), FFD * DMODEL / 4);
    split_kernel<<<(DMODEL * FFD / 4 + 255) / 256, 256>>>(
        (const float4*)W2, (uint2*)(wh + W2_OFF), (uint2*)(wl + W2_OFF), DMODEL * FFD / 4);

    // 1) h = LN1(x)
    ln_kernel<<<TOK, 256>>>(x, g1, b1, hh);
    // 2) qkv = h @ Wqkv^T + bqkv (1-term)
    gemm_mma<1, false, false, true><<<dim3(3 * DMODEL / 128, TOK / 128), 256, SM1>>>(
        hh, wh + WQKV_OFF, nullptr, bqkv, nullptr,
        nullptr, qkvh, TOK, 3 * DMODEL, DMODEL);
    // 3) attention
    attn_mma<<<dim3(SEQ / AQ, NH, NB), 256, ATTN_SMEM>>>(qkvh, ah);
    // 4) x1 = x + att @ Wo^T + bo (1-term)
    gemm_mma<1, false, true, false><<<dim3(DMODEL / 128, TOK / 128), 256, SM1>>>(
        ah, wh + WO_OFF, nullptr, bo, x,
        x1, nullptr, TOK, DMODEL, DMODEL);
    // 5) h = LN2(x1)
    ln_kernel<<<TOK, 256>>>(x1, g2, b2, hh);
    // 6) ffh = gelu(h @ W1^T + b1m) (2-term)
    gemm_mma<2, true, false, true><<<dim3(FFD / 128, TOK / 128), 256, SM2>>>(
        hh, wh + W1_OFF, wl + W1_OFF, b1m, nullptr,
        nullptr, fh, TOK, FFD, DMODEL);
    // 7) out = x1 + ffh @ W2^T + b2m (2-term)
    gemm_mma<2, false, true, false><<<dim3(DMODEL / 128, TOK / 128), 256, SM2>>>(
        fh, wh + W2_OFF, wl + W2_OFF, b2m, x1,
        out, nullptr, TOK, DMODEL, FFD);
}

// round 8
// speedup vs baseline: 5.3428x; 1.3049x over previous
#include <cuda_runtime.h>
#include <cuda_fp16.h>
#include <stdint.h>
#include <math.h>

// ---------------- problem constants ----------------
#define NB     2
#define SEQ    2048
#define TOK    4096
#define DMODEL 1024
#define NH     16
#define HD     64
#define FFD    4096
#define LN_EPS 1e-5f

// ---------------- scratch (device globals; no allocation) ----------------
__device__ float  g_x1 [TOK * DMODEL];          // post-attn residual (fp32)
__device__ __half g_qkvh[TOK * 3 * DMODEL];     // QKV (fp16)
__device__ __half g_hh [TOK * DMODEL];          // LN output (fp16)
__device__ __half g_ah [TOK * DMODEL];          // attention output (fp16)
__device__ __half g_fh [TOK * FFD];             // MLP hidden (fp16)
#define WTOT (12 * 1024 * 1024)
__device__ __half g_wh[WTOT];                   // all weights fp16

#define WQKV_OFF 0
#define WO_OFF   3145728
#define W1_OFF   4194304
#define W2_OFF   8388608

// ==================== helpers ====================
static __device__ __forceinline__ uint32_t smem_u32(const void* p) {
    uint32_t a;
    asm("{ .reg .u64 t; cvta.to.shared.u64 t, %1; cvt.u32.u64 %0, t; }"
        : "=r"(a) : "l"(p));
    return a;
}

static __device__ __forceinline__ void cpasync16(uint32_t s, const void* g) {
    asm volatile(
        "{ .reg .u64 p; cvta.to.global.u64 p, %1; "
        "cp.async.cg.shared.global [%0], [p], 16; }"
        :: "r"(s), "l"(g) : "memory");
}
#define CP_COMMIT() asm volatile("cp.async.commit_group;" ::: "memory")
#define CP_WAIT1()  asm volatile("cp.async.wait_group 1;" ::: "memory")
#define CP_WAIT0()  asm volatile("cp.async.wait_group 0;" ::: "memory")

static __device__ __forceinline__ void ldm4(uint32_t* r, uint32_t addr) {
    asm volatile("ldmatrix.sync.aligned.m8n8.x4.shared.b16 {%0,%1,%2,%3}, [%4];"
        : "=r"(r[0]), "=r"(r[1]), "=r"(r[2]), "=r"(r[3]) : "r"(addr));
}
static __device__ __forceinline__ void ldm4t(uint32_t* r, uint32_t addr) {
    asm volatile("ldmatrix.sync.aligned.m8n8.x4.trans.shared.b16 {%0,%1,%2,%3}, [%4];"
        : "=r"(r[0]), "=r"(r[1]), "=r"(r[2]), "=r"(r[3]) : "r"(addr));
}

static __device__ __forceinline__ void mma_f16(float* c, const uint32_t* a,
                                               uint32_t b0, uint32_t b1) {
    asm volatile(
        "mma.sync.aligned.m16n8k16.row.col.f32.f16.f16.f32 "
        "{%0,%1,%2,%3}, {%4,%5,%6,%7}, {%8,%9}, {%0,%1,%2,%3};"
        : "+f"(c[0]), "+f"(c[1]), "+f"(c[2]), "+f"(c[3])
        : "r"(a[0]), "r"(a[1]), "r"(a[2]), "r"(a[3]), "r"(b0), "r"(b1));
}

// pack two fp32 -> f16x2 register (first arg -> low half)
static __device__ __forceinline__ uint32_t pack_h2(float lo, float hi) {
    uint32_t r;
    asm("cvt.rn.f16x2.f32 %0, %1, %2;" : "=r"(r) : "f"(hi), "f"(lo));
    return r;
}
static __device__ __forceinline__ uint32_t ex2_h2(uint32_t x) {
    uint32_t r;
    asm("ex2.approx.f16x2 %0, %1;" : "=r"(r) : "r"(x));
    return r;
}

// ==================== weight conversion (fp32 -> fp16) ====================
__global__ __launch_bounds__(256) void conv_kernel(
    const float4* __restrict__ w, uint2* __restrict__ hi, int n4)
{
    int i = blockIdx.x * 256 + threadIdx.x;
    if (i < n4) {
        const float4 v = w[i];
        uint2 o;
        o.x = pack_h2(v.x, v.y);
        o.y = pack_h2(v.z, v.w);
        hi[i] = o;
    }
}

// ==================== LayerNorm -> fp16 ====================
__global__ __launch_bounds__(256) void ln_kernel(
    const float* __restrict__ x, const float* __restrict__ g,
    const float* __restrict__ b, __half* __restrict__ y)
{
    __shared__ float red[8];
    __shared__ float bc[2];
    const int r = blockIdx.x, tid = threadIdx.x;
    const int wid = tid >> 5, lane = tid & 31;

    const float4 v = ((const float4*)(x + (size_t)r * DMODEL))[tid];

    float s = v.x + v.y + v.z + v.w;
    #pragma unroll
    for (int o = 16; o; o >>= 1) s += __shfl_xor_sync(0xffffffffu, s, o);
    if (lane == 0) red[wid] = s;
    __syncthreads();
    if (tid == 0) {
        float t = 0.f;
        #pragma unroll
        for (int i = 0; i < 8; ++i) t += red[i];
        bc[0] = t * (1.0f / DMODEL);
    }
    __syncthreads();
    const float mean = bc[0];

    const float dx = v.x - mean, dy = v.y - mean, dz = v.z - mean, dw = v.w - mean;
    float ss = dx * dx + dy * dy + dz * dz + dw * dw;
    #pragma unroll
    for (int o = 16; o; o >>= 1) ss += __shfl_xor_sync(0xffffffffu, ss, o);
    if (lane == 0) red[wid] = ss;
    __syncthreads();
    if (tid == 0) {
        float t = 0.f;
        #pragma unroll
        for (int i = 0; i < 8; ++i) t += red[i];
        bc[1] = rsqrtf(t * (1.0f / DMODEL) + LN_EPS);
    }
    __syncthreads();
    const float rs = bc[1];

    const float4 gv = ((const float4*)g)[tid];
    const float4 bv = ((const float4*)b)[tid];
    uint2 o2;
    o2.x = pack_h2(dx * rs * gv.x + bv.x, dy * rs * gv.y + bv.y);
    o2.y = pack_h2(dz * rs * gv.z + bv.z, dw * rs * gv.w + bv.w);
    *(uint2*)(y + (size_t)r * DMODEL + tid * 4) = o2;
}

// ==================== mma.sync GEMM (NT, fp16, single term) ====================
// CTA tile 128x128, BK=32, 256 threads (8 warps 2x4), warp tile 64x32.
#define TILE_B   10240              // 128*80
#define STAGE_B  (2 * TILE_B)       // A + B
#define GEMM_SMEM (2 * STAGE_B)     // 40960

static __device__ __forceinline__ void stage_load(
    uint32_t s0, const __half* gA, const __half* gB,
    int m0, int n0, int K, int kt, int tid)
{
    #pragma unroll
    for (int half_ = 0; half_ < 2; ++half_) {
        const int u   = tid + half_ * 256;
        const int row = u >> 2;
        const int seg = u & 3;
        const uint32_t soff = row * 80 + seg * 16;
        const size_t ga = (size_t)(m0 + row) * K + kt + seg * 8;
        const size_t gb = (size_t)(n0 + row) * K + kt + seg * 8;
        cpasync16(s0 +          soff, gA + ga);
        cpasync16(s0 + TILE_B + soff, gB + gb);
    }
}

template<bool GELU_F, bool RES_F, bool OUTH_F>
__global__ __launch_bounds__(256, 2)
void gemm_mma(
    const __half* __restrict__ A, const __half* __restrict__ B,
    const float* __restrict__ bias, const float* __restrict__ res,
    float* __restrict__ Cf, __half* __restrict__ Ch,
    int M, int N, int K)
{
    extern __shared__ char dsm[];
    const uint32_t sb = smem_u32(dsm);

    const int tid  = threadIdx.x;
    const int wid  = tid >> 5, lane = tid & 31;
    const int wm   = wid & 1;
    const int wn   = wid >> 1;
    const int m0   = blockIdx.y << 7;
    const int n0   = blockIdx.x << 7;

    float acc[4][4][4];
    #pragma unroll
    for (int i = 0; i < 4; ++i)
        #pragma unroll
        for (int j = 0; j < 4; ++j) {
            acc[i][j][0] = 0.f; acc[i][j][1] = 0.f;
            acc[i][j][2] = 0.f; acc[i][j][3] = 0.f;
        }

    const int lr   = lane & 15;
    const int cof  = (lane >> 4) << 3;
    const uint32_t aRowByte = (uint32_t)(wm * 64 + lr) * 80;
    const uint32_t bRowByte = (uint32_t)(wn * 32 + lr) * 80;

    const int NC = K >> 5;

    stage_load(sb, A, B, m0, n0, K, 0, tid);
    CP_COMMIT();

    for (int c = 0; c < NC; ++c) {
        if (c + 1 < NC) {
            stage_load(sb + ((c + 1) & 1) * STAGE_B, A, B,
                       m0, n0, K, (c + 1) << 5, tid);
            CP_COMMIT();
            CP_WAIT1();
        } else {
            CP_WAIT0();
        }
        __syncthreads();

        const uint32_t s0 = sb + (c & 1) * STAGE_B;
        const uint32_t aA = s0;
        const uint32_t aB = s0 + TILE_B;

        #pragma unroll
        for (int ks = 0; ks < 2; ++ks) {
            const uint32_t kbyte = (uint32_t)(ks * 16 + cof) * 2;

            uint32_t af[4][4];
            #pragma unroll
            for (int mi = 0; mi < 4; ++mi)
                ldm4(af[mi], aA + aRowByte + (uint32_t)(mi * 16) * 80 + kbyte);

            uint32_t bf[2][4];
            #pragma unroll
            for (int nt = 0; nt < 2; ++nt)
                ldm4(bf[nt], aB + bRowByte + (uint32_t)(nt * 16) * 80 + kbyte);

            #pragma unroll
            for (int mi = 0; mi < 4; ++mi)
                #pragma unroll
                for (int ni = 0; ni < 4; ++ni)
                    mma_f16(acc[mi][ni], af[mi],
                            bf[ni >> 1][ni & 1], bf[ni >> 1][2 + (ni & 1)]);
        }
        __syncthreads();
    }

    const int tr = lane >> 2;
    const int tc = (lane & 3) << 1;
    #pragma unroll
    for (int mi = 0; mi < 4; ++mi) {
        #pragma unroll
        for (int ni = 0; ni < 4; ++ni) {
            const int col = n0 + wn * 32 + ni * 8 + tc;
            #pragma unroll
            for (int half_ = 0; half_ < 2; ++half_) {
                const int row = m0 + wm * 64 + mi * 16 + tr + half_ * 8;
                float vx = acc[mi][ni][half_ * 2 + 0] + bias[col + 0];
                float vy = acc[mi][ni][half_ * 2 + 1] + bias[col + 1];
                if (RES_F) {
                    const float2 rv = *(const float2*)&res[(size_t)row * N + col];
                    vx += rv.x; vy += rv.y;
                }
                if (GELU_F) {
                    vx = 0.5f * vx * (1.0f + erff(vx * 0.70710678f));
                    vy = 0.5f * vy * (1.0f + erff(vy * 0.70710678f));
                }
                const size_t off = (size_t)row * N + col;
                if (OUTH_F) {
                    *(uint32_t*)(Ch + off) = pack_h2(vx, vy);
                } else {
                    float2 o; o.x = vx; o.y = vy;
                    *(float2*)&Cf[off] = o;
                }
            }
        }
    }
}

// ==================== Tensor-core flash attention (fp16, cp.async) ====================
#define AQ    128
#define AKV   128
#define ASTRB 144
#define Q_OFF 0
#define KV_OFF 18432
#define KV_STG 36864
#define ATTN_SMEM (KV_OFF + 2 * KV_STG)   // 92160

__global__ __launch_bounds__(256) void attn_mma(
    const __half* __restrict__ qkv, __half* __restrict__ oh)
{
    extern __shared__ char asm_[];
    const uint32_t sB = smem_u32(asm_);

    const int tid = threadIdx.x;
    const int w = tid >> 5, lane = tid & 31;
    const int g = lane >> 2, t = lane & 3;
    const int b = blockIdx.z, h = blockIdx.y;
    const int q0 = blockIdx.x * AQ;

    const int lrow = tid >> 1;
    const int lhf  = tid & 1;

    const __half* tokbase = qkv + (size_t)(b * SEQ) * (3 * DMODEL) + h * 192;

    // ---- stage Q via cp.async ----
    {
        const __half* qp = tokbase + (size_t)(q0 + lrow) * (3 * DMODEL) + lhf * 32;
        const uint32_t sq = sB + Q_OFF + lrow * ASTRB + lhf * 64;
        #pragma unroll
        for (int s = 0; s < 4; ++s)
            cpasync16(sq + s * 16, qp + s * 8);
    }
    CP_COMMIT();
    CP_WAIT0();
    __syncthreads();

    uint32_t qf[4][4];
    {
        const uint32_t rb = sB + Q_OFF + (uint32_t)(w * 16 + (lane & 15)) * ASTRB
                          + (uint32_t)(((lane >> 4) & 1) * 8) * 2;
        #pragma unroll
        for (int ks = 0; ks < 4; ++ks)
            ldm4(qf[ks], rb + ks * 32);
    }
    __syncthreads();

    float oc[8][4];
    #pragma unroll
    for (int i = 0; i < 8; ++i) {
        oc[i][0] = 0.f; oc[i][1] = 0.f; oc[i][2] = 0.f; oc[i][3] = 0.f;
    }
    float mrow[2] = {-INFINITY, -INFINITY};
    float lsum[2] = {0.f, 0.f};

    const int NT = SEQ / AKV;
    const float K1 = 0.125f * 1.4426950408889634f;   // log2(e)/8

    // prefetch KV tile 0
    {
        const __half* kp = tokbase + (size_t)lrow * (3 * DMODEL) + 64 + lhf * 32;
        const uint32_t sk = sB + KV_OFF + lrow * ASTRB + lhf * 64;
        #pragma unroll
        for (int s = 0; s < 4; ++s) cpasync16(sk + s * 16, kp + s * 8);
        const uint32_t sv = sk + 18432;
        #pragma unroll
        for (int s = 0; s < 4; ++s) cpasync16(sv + s * 16, kp + 64 + s * 8);
    }
    CP_COMMIT();

    for (int tI = 0; tI < NT; ++tI) {
        if (tI + 1 < NT) {
            const int kv1 = (tI + 1) * AKV;
            const __half* kp = tokbase + (size_t)(kv1 + lrow) * (3 * DMODEL) + 64 + lhf * 32;
            const uint32_t sk = sB + KV_OFF + ((tI + 1) & 1) * KV_STG + lrow * ASTRB + lhf * 64;
            #pragma unroll
            for (int s = 0; s < 4; ++s) cpasync16(sk + s * 16, kp + s * 8);
            const uint32_t sv = sk + 18432;
            #pragma unroll
            for (int s = 0; s < 4; ++s) cpasync16(sv + s * 16, kp + 64 + s * 8);
            CP_COMMIT();
            CP_WAIT1();
        } else {
            CP_WAIT0();
        }
        __syncthreads();

        const uint32_t ksB = sB + KV_OFF + (tI & 1) * KV_STG;
        const uint32_t vsB = ksB + 18432;

        // ---- S = Q K^T ----
        float sc[16][4];
        #pragma unroll
        for (int nt2 = 0; nt2 < 8; ++nt2) {
            #pragma unroll
            for (int q2 = 0; q2 < 4; ++q2) {
                sc[2 * nt2][q2] = 0.f; sc[2 * nt2 + 1][q2] = 0.f;
            }
            #pragma unroll
            for (int ks = 0; ks < 4; ++ks) {
                uint32_t bf[4];
                const uint32_t addr = ksB
                    + (uint32_t)(nt2 * 16 + (lane & 7) + ((lane >> 4) & 1) * 8) * ASTRB
                    + (uint32_t)(ks * 16 + ((lane >> 3) & 1) * 8) * 2;
                ldm4(bf, addr);
                mma_f16(sc[2 * nt2],     qf[ks], bf[0], bf[1]);
                mma_f16(sc[2 * nt2 + 1], qf[ks], bf[2], bf[3]);
            }
        }

        // ---- online softmax, exp via ex2.approx.f16x2 ----
        uint32_t pf[8][4];
        float alpha[2];
        #pragma unroll
        for (int r = 0; r < 2; ++r) {
            float mx = -INFINITY;
            #pragma unroll
            for (int nt = 0; nt < 16; ++nt)
                mx = fmaxf(mx, fmaxf(sc[nt][2 * r], sc[nt][2 * r + 1]));
            mx = fmaxf(mx, __shfl_xor_sync(0xffffffffu, mx, 1));
            mx = fmaxf(mx, __shfl_xor_sync(0xffffffffu, mx, 2));
            const float mn = fmaxf(mrow[r], mx);
            alpha[r] = __expf((mrow[r] - mn) * 0.125f);
            mrow[r] = mn;
            const float c2 = -mn * K1;
            float rs = 0.f;
            #pragma unroll
            for (int nt = 0; nt < 16; ++nt) {
                const float t0 = fmaf(sc[nt][2 * r],     K1, c2);
                const float t1 = fmaf(sc[nt][2 * r + 1], K1, c2);
                const uint32_t pe = ex2_h2(pack_h2(t0, t1));
                pf[nt >> 1][((nt & 1) << 1) + r] = pe;
                const float2 f2 = __half22float2(*(const __half2*)&pe);
                rs += f2.x + f2.y;
            }
            rs += __shfl_xor_sync(0xffffffffu, rs, 1);
            rs += __shfl_xor_sync(0xffffffffu, rs, 2);
            lsum[r] = lsum[r] * alpha[r] + rs;
        }
        #pragma unroll
        for (int dt = 0; dt < 8; ++dt) {
            oc[dt][0] *= alpha[0]; oc[dt][1] *= alpha[0];
            oc[dt][2] *= alpha[1]; oc[dt][3] *= alpha[1];
        }

        // ---- O += P V ----
        #pragma unroll
        for (int ks = 0; ks < 8; ++ks) {
            #pragma unroll
            for (int dt2 = 0; dt2 < 4; ++dt2) {
                uint32_t bv[4];
                const uint32_t addr = vsB
                    + (uint32_t)(ks * 16 + (lane & 7) + ((lane >> 3) & 1) * 8) * ASTRB
                    + (uint32_t)(dt2 * 16 + ((lane >> 4) & 1) * 8) * 2;
                ldm4t(bv, addr);
                mma_f16(oc[2 * dt2],     pf[ks], bv[0], bv[1]);
                mma_f16(oc[2 * dt2 + 1], pf[ks], bv[2], bv[3]);
            }
        }
        __syncthreads();
    }

    // ---- normalize + write fp16 ----
    #pragma unroll
    for (int r = 0; r < 2; ++r) {
        const float inv = 1.0f / lsum[r];
        const int row = q0 + w * 16 + g + r * 8;
        const size_t base = (size_t)(b * SEQ + row) * DMODEL + h * HD + t * 2;
        #pragma unroll
        for (int dt = 0; dt < 8; ++dt) {
            *(uint32_t*)(oh + base + dt * 8) =
                pack_h2(oc[dt][2 * r] * inv, oc[dt][2 * r + 1] * inv);
        }
    }
}

// ==================== launch ====================
extern "C" void kernel_launch(void* const* d_in, const int* in_sizes, int n_in,
                              void* d_out, int out_size)
{
    (void)in_sizes; (void)n_in; (void)out_size;
    const float* x    = (const float*)d_in[0];
    const float* g1   = (const float*)d_in[1];
    const float* b1   = (const float*)d_in[2];
    const float* Wqkv = (const float*)d_in[3];
    const float* bqkv = (const float*)d_in[4];
    const float* Wo   = (const float*)d_in[5];
    const float* bo   = (const float*)d_in[6];
    const float* g2   = (const float*)d_in[7];
    const float* b2   = (const float*)d_in[8];
    const float* W1   = (const float*)d_in[9];
    const float* b1m  = (const float*)d_in[10];
    const float* W2   = (const float*)d_in[11];
    const float* b2m  = (const float*)d_in[12];
    float* out = (float*)d_out;

    float* x1;
    __half *qkvh, *hh, *ah, *fh, *wh;
    cudaGetSymbolAddress((void**)&x1,   g_x1);
    cudaGetSymbolAddress((void**)&qkvh, g_qkvh);
    cudaGetSymbolAddress((void**)&hh,   g_hh);
    cudaGetSymbolAddress((void**)&ah,   g_ah);
    cudaGetSymbolAddress((void**)&fh,   g_fh);
    cudaGetSymbolAddress((void**)&wh,   g_wh);

    cudaFuncSetAttribute(gemm_mma<false, false, true>,
                         cudaFuncAttributeMaxDynamicSharedMemorySize, GEMM_SMEM);
    cudaFuncSetAttribute(gemm_mma<false, true, false>,
                         cudaFuncAttributeMaxDynamicSharedMemorySize, GEMM_SMEM);
    cudaFuncSetAttribute(gemm_mma<true, false, true>,
                         cudaFuncAttributeMaxDynamicSharedMemorySize, GEMM_SMEM);
    cudaFuncSetAttribute(attn_mma,
                         cudaFuncAttributeMaxDynamicSharedMemorySize, ATTN_SMEM);

    // 0) weight prep (fp16 convert, all four weights)
    conv_kernel<<<(3 * DMODEL * DMODEL / 4 + 255) / 256, 256>>>(
        (const float4*)Wqkv, (uint2*)(wh + WQKV_OFF), 3 * DMODEL * DMODEL / 4);
    conv_kernel<<<(DMODEL * DMODEL / 4 + 255) / 256, 256>>>(
        (const float4*)Wo, (uint2*)(wh + WO_OFF), DMODEL * DMODEL / 4);
    conv_kernel<<<(FFD * DMODEL / 4 + 255) / 256, 256>>>(
        (const float4*)W1, (uint2*)(wh + W1_OFF), FFD * DMODEL / 4);
    conv_kernel<<<(DMODEL * FFD / 4 + 255) / 256, 256>>>(
        (const float4*)W2, (uint2*)(wh + W2_OFF), DMODEL * FFD / 4);

    // 1) h = LN1(x)
    ln_kernel<<<TOK, 256>>>(x, g1, b1, hh);
    // 2) qkv = h @ Wqkv^T + bqkv (fp16 out)
    gemm_mma<false, false, true><<<dim3(3 * DMODEL / 128, TOK / 128), 256, GEMM_SMEM>>>(
        hh, wh + WQKV_OFF, bqkv, nullptr,
        nullptr, qkvh, TOK, 3 * DMODEL, DMODEL);
    // 3) attention
    attn_mma<<<dim3(SEQ / AQ, NH, NB), 256, ATTN_SMEM>>>(qkvh, ah);
    // 4) x1 = x + att @ Wo^T + bo (fp32 out)
    gemm_mma<false, true, false><<<dim3(DMODEL / 128, TOK / 128), 256, GEMM_SMEM>>>(
        ah, wh + WO_OFF, bo, x,
        x1, nullptr, TOK, DMODEL, DMODEL);
    // 5) h = LN2(x1)
    ln_kernel<<<TOK, 256>>>(x1, g2, b2, hh);
    // 6) ffh = gelu(h @ W1^T + b1m) (fp16 out)
    gemm_mma<true, false, true><<<dim3(FFD / 128, TOK / 128), 256, GEMM_SMEM>>>(
        hh, wh + W1_OFF, b1m, nullptr,
        nullptr, fh, TOK, FFD, DMODEL);
    // 7) out = x1 + ffh @ W2^T + b2m (fp32 out)
    gemm_mma<false, true, false><<<dim3(DMODEL / 128, TOK / 128), 256, GEMM_SMEM>>>(
        fh, wh + W2_OFF, b2m, x1,
        out, nullptr, TOK, DMODEL, FFD);
}

// round 9
// speedup vs baseline: 5.6671x; 1.0607x over previous
#include <cuda_runtime.h>
#include <cuda_fp16.h>
#include <stdint.h>
#include <math.h>

// ---------------- problem constants ----------------
#define NB     2
#define SEQ    2048
#define TOK    4096
#define DMODEL 1024
#define NH     16
#define HD     64
#define FFD    4096
#define LN_EPS 1e-5f

// ---------------- scratch (device globals; no allocation) ----------------
__device__ float  g_x1 [TOK * DMODEL];          // post-attn residual (fp32)
__device__ __half g_qkvh[TOK * 3 * DMODEL];     // QKV (fp16)
__device__ __half g_hh [TOK * DMODEL];          // LN output (fp16)
__device__ __half g_ah [TOK * DMODEL];          // attention output (fp16)
__device__ __half g_fh [TOK * FFD];             // MLP hidden (fp16)
#define WTOT (12 * 1024 * 1024)
__device__ __half g_wh[WTOT];                   // all weights fp16

#define WQKV_OFF 0
#define WO_OFF   3145728
#define W1_OFF   4194304
#define W2_OFF   8388608

// ==================== helpers ====================
static __device__ __forceinline__ uint32_t smem_u32(const void* p) {
    uint32_t a;
    asm("{ .reg .u64 t; cvta.to.shared.u64 t, %1; cvt.u32.u64 %0, t; }"
        : "=r"(a) : "l"(p));
    return a;
}

static __device__ __forceinline__ void cpasync16(uint32_t s, const void* g) {
    asm volatile(
        "{ .reg .u64 p; cvta.to.global.u64 p, %1; "
        "cp.async.cg.shared.global [%0], [p], 16; }"
        :: "r"(s), "l"(g) : "memory");
}
#define CP_COMMIT() asm volatile("cp.async.commit_group;" ::: "memory")
#define CP_WAIT1()  asm volatile("cp.async.wait_group 1;" ::: "memory")
#define CP_WAIT0()  asm volatile("cp.async.wait_group 0;" ::: "memory")

static __device__ __forceinline__ void ldm4(uint32_t* r, uint32_t addr) {
    asm volatile("ldmatrix.sync.aligned.m8n8.x4.shared.b16 {%0,%1,%2,%3}, [%4];"
        : "=r"(r[0]), "=r"(r[1]), "=r"(r[2]), "=r"(r[3]) : "r"(addr));
}
static __device__ __forceinline__ void ldm4t(uint32_t* r, uint32_t addr) {
    asm volatile("ldmatrix.sync.aligned.m8n8.x4.trans.shared.b16 {%0,%1,%2,%3}, [%4];"
        : "=r"(r[0]), "=r"(r[1]), "=r"(r[2]), "=r"(r[3]) : "r"(addr));
}

static __device__ __forceinline__ void mma_f16(float* c, const uint32_t* a,
                                               uint32_t b0, uint32_t b1) {
    asm volatile(
        "mma.sync.aligned.m16n8k16.row.col.f32.f16.f16.f32 "
        "{%0,%1,%2,%3}, {%4,%5,%6,%7}, {%8,%9}, {%0,%1,%2,%3};"
        : "+f"(c[0]), "+f"(c[1]), "+f"(c[2]), "+f"(c[3])
        : "r"(a[0]), "r"(a[1]), "r"(a[2]), "r"(a[3]), "r"(b0), "r"(b1));
}

// pack two fp32 -> f16x2 register (first arg -> low half)
static __device__ __forceinline__ uint32_t pack_h2(float lo, float hi) {
    uint32_t r;
    asm("cvt.rn.f16x2.f32 %0, %1, %2;" : "=r"(r) : "f"(hi), "f"(lo));
    return r;
}
static __device__ __forceinline__ uint32_t ex2_h2(uint32_t x) {
    uint32_t r;
    asm("ex2.approx.f16x2 %0, %1;" : "=r"(r) : "r"(x));
    return r;
}

// ==================== weight conversion (fp32 -> fp16) ====================
__global__ __launch_bounds__(256) void conv_kernel(
    const float4* __restrict__ w, uint2* __restrict__ hi, int n4)
{
    int i = blockIdx.x * 256 + threadIdx.x;
    if (i < n4) {
        const float4 v = w[i];
        uint2 o;
        o.x = pack_h2(v.x, v.y);
        o.y = pack_h2(v.z, v.w);
        hi[i] = o;
    }
}

// ==================== LayerNorm -> fp16 ====================
__global__ __launch_bounds__(256) void ln_kernel(
    const float* __restrict__ x, const float* __restrict__ g,
    const float* __restrict__ b, __half* __restrict__ y)
{
    __shared__ float red[8];
    __shared__ float bc[2];
    const int r = blockIdx.x, tid = threadIdx.x;
    const int wid = tid >> 5, lane = tid & 31;

    const float4 v = ((const float4*)(x + (size_t)r * DMODEL))[tid];

    float s = v.x + v.y + v.z + v.w;
    #pragma unroll
    for (int o = 16; o; o >>= 1) s += __shfl_xor_sync(0xffffffffu, s, o);
    if (lane == 0) red[wid] = s;
    __syncthreads();
    if (tid == 0) {
        float t = 0.f;
        #pragma unroll
        for (int i = 0; i < 8; ++i) t += red[i];
        bc[0] = t * (1.0f / DMODEL);
    }
    __syncthreads();
    const float mean = bc[0];

    const float dx = v.x - mean, dy = v.y - mean, dz = v.z - mean, dw = v.w - mean;
    float ss = dx * dx + dy * dy + dz * dz + dw * dw;
    #pragma unroll
    for (int o = 16; o; o >>= 1) ss += __shfl_xor_sync(0xffffffffu, ss, o);
    if (lane == 0) red[wid] = ss;
    __syncthreads();
    if (tid == 0) {
        float t = 0.f;
        #pragma unroll
        for (int i = 0; i < 8; ++i) t += red[i];
        bc[1] = rsqrtf(t * (1.0f / DMODEL) + LN_EPS);
    }
    __syncthreads();
    const float rs = bc[1];

    const float4 gv = ((const float4*)g)[tid];
    const float4 bv = ((const float4*)b)[tid];
    uint2 o2;
    o2.x = pack_h2(dx * rs * gv.x + bv.x, dy * rs * gv.y + bv.y);
    o2.y = pack_h2(dz * rs * gv.z + bv.z, dw * rs * gv.w + bv.w);
    *(uint2*)(y + (size_t)r * DMODEL + tid * 4) = o2;
}

// ==================== mma.sync GEMM (NT, fp16, single term) ====================
// CTA tile 128x128, BK=64, 256 threads (8 warps 2x4), warp tile 64x32.
// 3-stage cp.async ring; smem tile rows padded to 144 B (conflict-free ldmatrix).
#define TILE_B   18432              // 128 * 144
#define STAGE_B  (2 * TILE_B)       // A + B  = 36864
#define GEMM_SMEM (3 * STAGE_B)     // 110592

static __device__ __forceinline__ void stage_load(
    uint32_t s0, const __half* gA, const __half* gB,
    int m0, int n0, int K, int kt, int tid)
{
    // 2 tiles x 128 rows x 8 segments(16B) = 2048 cp.async / 256 threads
    #pragma unroll
    for (int q = 0; q < 4; ++q) {
        const int u   = tid + q * 256;        // 0..1023
        const int row = u >> 3;
        const int seg = u & 7;
        const uint32_t soff = row * 144 + seg * 16;
        const size_t ga = (size_t)(m0 + row) * K + kt + seg * 8;
        const size_t gb = (size_t)(n0 + row) * K + kt + seg * 8;
        cpasync16(s0 +          soff, gA + ga);
        cpasync16(s0 + TILE_B + soff, gB + gb);
    }
}

template<bool GELU_F, bool RES_F, bool OUTH_F>
__global__ __launch_bounds__(256, 2)
void gemm_mma(
    const __half* __restrict__ A, const __half* __restrict__ B,
    const float* __restrict__ bias, const float* __restrict__ res,
    float* __restrict__ Cf, __half* __restrict__ Ch,
    int M, int N, int K)
{
    extern __shared__ char dsm[];
    const uint32_t sb = smem_u32(dsm);

    const int tid  = threadIdx.x;
    const int wid  = tid >> 5, lane = tid & 31;
    const int wm   = wid & 1;
    const int wn   = wid >> 1;
    const int m0   = blockIdx.y << 7;
    const int n0   = blockIdx.x << 7;

    float acc[4][4][4];
    #pragma unroll
    for (int i = 0; i < 4; ++i)
        #pragma unroll
        for (int j = 0; j < 4; ++j) {
            acc[i][j][0] = 0.f; acc[i][j][1] = 0.f;
            acc[i][j][2] = 0.f; acc[i][j][3] = 0.f;
        }

    const int lr   = lane & 15;
    const int cof  = (lane >> 4) << 3;
    const uint32_t aRowByte = (uint32_t)(wm * 64 + lr) * 144;
    const uint32_t bRowByte = (uint32_t)(wn * 32 + lr) * 144;

    const int NC = K >> 6;   // chunks of 64 (K = 1024 or 4096 -> NC = 16 / 64)

    // prefetch stages 0 and 1
    stage_load(sb,           A, B, m0, n0, K, 0,  tid);
    CP_COMMIT();
    stage_load(sb + STAGE_B, A, B, m0, n0, K, 64, tid);
    CP_COMMIT();

    for (int c = 0; c < NC; ++c) {
        // issue stage c+2 (buffer (c+2)%3 == (c-1)%3, freed by the trailing
        // sync of iteration c-1); empty commit at the tail keeps the
        // wait-group counting uniform.
        if (c + 2 < NC)
            stage_load(sb + ((c + 2) % 3) * STAGE_B, A, B,
                       m0, n0, K, (c + 2) << 6, tid);
        CP_COMMIT();
        CP_WAIT1();          // commits so far = c+3; <=1 in flight -> stage c done
        __syncthreads();

        const uint32_t s0 = sb + (c % 3) * STAGE_B;
        const uint32_t aA = s0;
        const uint32_t aB = s0 + TILE_B;

        #pragma unroll
        for (int ks = 0; ks < 4; ++ks) {
            const uint32_t kbyte = (uint32_t)(ks * 16 + cof) * 2;

            uint32_t af[4][4];
            #pragma unroll
            for (int mi = 0; mi < 4; ++mi)
                ldm4(af[mi], aA + aRowByte + (uint32_t)(mi * 16) * 144 + kbyte);

            uint32_t bf[2][4];
            #pragma unroll
            for (int nt = 0; nt < 2; ++nt)
                ldm4(bf[nt], aB + bRowByte + (uint32_t)(nt * 16) * 144 + kbyte);

            #pragma unroll
            for (int mi = 0; mi < 4; ++mi)
                #pragma unroll
                for (int ni = 0; ni < 4; ++ni)
                    mma_f16(acc[mi][ni], af[mi],
                            bf[ni >> 1][ni & 1], bf[ni >> 1][2 + (ni & 1)]);
        }
        __syncthreads();
    }

    const int tr = lane >> 2;
    const int tc = (lane & 3) << 1;
    #pragma unroll
    for (int mi = 0; mi < 4; ++mi) {
        #pragma unroll
        for (int ni = 0; ni < 4; ++ni) {
            const int col = n0 + wn * 32 + ni * 8 + tc;
            #pragma unroll
            for (int half_ = 0; half_ < 2; ++half_) {
                const int row = m0 + wm * 64 + mi * 16 + tr + half_ * 8;
                float vx = acc[mi][ni][half_ * 2 + 0] + bias[col + 0];
                float vy = acc[mi][ni][half_ * 2 + 1] + bias[col + 1];
                if (RES_F) {
                    const float2 rv = *(const float2*)&res[(size_t)row * N + col];
                    vx += rv.x; vy += rv.y;
                }
                if (GELU_F) {
                    vx = 0.5f * vx * (1.0f + erff(vx * 0.70710678f));
                    vy = 0.5f * vy * (1.0f + erff(vy * 0.70710678f));
                }
                const size_t off = (size_t)row * N + col;
                if (OUTH_F) {
                    *(uint32_t*)(Ch + off) = pack_h2(vx, vy);
                } else {
                    float2 o; o.x = vx; o.y = vy;
                    *(float2*)&Cf[off] = o;
                }
            }
        }
    }
}

// ==================== Tensor-core flash attention (fp16, cp.async) ====================
#define AQ    128
#define AKV   128
#define ASTRB 144
#define Q_OFF 0
#define KV_OFF 18432
#define KV_STG 36864
#define ATTN_SMEM (KV_OFF + 2 * KV_STG)   // 92160

__global__ __launch_bounds__(256) void attn_mma(
    const __half* __restrict__ qkv, __half* __restrict__ oh)
{
    extern __shared__ char asm_[];
    const uint32_t sB = smem_u32(asm_);

    const int tid = threadIdx.x;
    const int w = tid >> 5, lane = tid & 31;
    const int g = lane >> 2, t = lane & 3;
    const int b = blockIdx.z, h = blockIdx.y;
    const int q0 = blockIdx.x * AQ;

    const int lrow = tid >> 1;
    const int lhf  = tid & 1;

    const __half* tokbase = qkv + (size_t)(b * SEQ) * (3 * DMODEL) + h * 192;

    // ---- stage Q via cp.async ----
    {
        const __half* qp = tokbase + (size_t)(q0 + lrow) * (3 * DMODEL) + lhf * 32;
        const uint32_t sq = sB + Q_OFF + lrow * ASTRB + lhf * 64;
        #pragma unroll
        for (int s = 0; s < 4; ++s)
            cpasync16(sq + s * 16, qp + s * 8);
    }
    CP_COMMIT();
    CP_WAIT0();
    __syncthreads();

    uint32_t qf[4][4];
    {
        const uint32_t rb = sB + Q_OFF + (uint32_t)(w * 16 + (lane & 15)) * ASTRB
                          + (uint32_t)(((lane >> 4) & 1) * 8) * 2;
        #pragma unroll
        for (int ks = 0; ks < 4; ++ks)
            ldm4(qf[ks], rb + ks * 32);
    }
    __syncthreads();

    float oc[8][4];
    #pragma unroll
    for (int i = 0; i < 8; ++i) {
        oc[i][0] = 0.f; oc[i][1] = 0.f; oc[i][2] = 0.f; oc[i][3] = 0.f;
    }
    float mrow[2] = {-INFINITY, -INFINITY};
    float lsum[2] = {0.f, 0.f};

    const int NT = SEQ / AKV;
    const float K1 = 0.125f * 1.4426950408889634f;   // log2(e)/8

    // prefetch KV tile 0
    {
        const __half* kp = tokbase + (size_t)lrow * (3 * DMODEL) + 64 + lhf * 32;
        const uint32_t sk = sB + KV_OFF + lrow * ASTRB + lhf * 64;
        #pragma unroll
        for (int s = 0; s < 4; ++s) cpasync16(sk + s * 16, kp + s * 8);
        const uint32_t sv = sk + 18432;
        #pragma unroll
        for (int s = 0; s < 4; ++s) cpasync16(sv + s * 16, kp + 64 + s * 8);
    }
    CP_COMMIT();

    for (int tI = 0; tI < NT; ++tI) {
        if (tI + 1 < NT) {
            const int kv1 = (tI + 1) * AKV;
            const __half* kp = tokbase + (size_t)(kv1 + lrow) * (3 * DMODEL) + 64 + lhf * 32;
            const uint32_t sk = sB + KV_OFF + ((tI + 1) & 1) * KV_STG + lrow * ASTRB + lhf * 64;
            #pragma unroll
            for (int s = 0; s < 4; ++s) cpasync16(sk + s * 16, kp + s * 8);
            const uint32_t sv = sk + 18432;
            #pragma unroll
            for (int s = 0; s < 4; ++s) cpasync16(sv + s * 16, kp + 64 + s * 8);
            CP_COMMIT();
            CP_WAIT1();
        } else {
            CP_WAIT0();
        }
        __syncthreads();

        const uint32_t ksB = sB + KV_OFF + (tI & 1) * KV_STG;
        const uint32_t vsB = ksB + 18432;

        // ---- S = Q K^T ----
        float sc[16][4];
        #pragma unroll
        for (int nt2 = 0; nt2 < 8; ++nt2) {
            #pragma unroll
            for (int q2 = 0; q2 < 4; ++q2) {
                sc[2 * nt2][q2] = 0.f; sc[2 * nt2 + 1][q2] = 0.f;
            }
            #pragma unroll
            for (int ks = 0; ks < 4; ++ks) {
                uint32_t bf[4];
                const uint32_t addr = ksB
                    + (uint32_t)(nt2 * 16 + (lane & 7) + ((lane >> 4) & 1) * 8) * ASTRB
                    + (uint32_t)(ks * 16 + ((lane >> 3) & 1) * 8) * 2;
                ldm4(bf, addr);
                mma_f16(sc[2 * nt2],     qf[ks], bf[0], bf[1]);
                mma_f16(sc[2 * nt2 + 1], qf[ks], bf[2], bf[3]);
            }
        }

        // ---- online softmax, exp via ex2.approx.f16x2 ----
        uint32_t pf[8][4];
        float alpha[2];
        #pragma unroll
        for (int r = 0; r < 2; ++r) {
            float mx = -INFINITY;
            #pragma unroll
            for (int nt = 0; nt < 16; ++nt)
                mx = fmaxf(mx, fmaxf(sc[nt][2 * r], sc[nt][2 * r + 1]));
            mx = fmaxf(mx, __shfl_xor_sync(0xffffffffu, mx, 1));
            mx = fmaxf(mx, __shfl_xor_sync(0xffffffffu, mx, 2));
            const float mn = fmaxf(mrow[r], mx);
            alpha[r] = __expf((mrow[r] - mn) * 0.125f);
            mrow[r] = mn;
            const float c2 = -mn * K1;
            float rs = 0.f;
            #pragma unroll
            for (int nt = 0; nt < 16; ++nt) {
                const float t0 = fmaf(sc[nt][2 * r],     K1, c2);
                const float t1 = fmaf(sc[nt][2 * r + 1], K1, c2);
                const uint32_t pe = ex2_h2(pack_h2(t0, t1));
                pf[nt >> 1][((nt & 1) << 1) + r] = pe;
                const float2 f2 = __half22float2(*(const __half2*)&pe);
                rs += f2.x + f2.y;
            }
            rs += __shfl_xor_sync(0xffffffffu, rs, 1);
            rs += __shfl_xor_sync(0xffffffffu, rs, 2);
            lsum[r] = lsum[r] * alpha[r] + rs;
        }
        #pragma unroll
        for (int dt = 0; dt < 8; ++dt) {
            oc[dt][0] *= alpha[0]; oc[dt][1] *= alpha[0];
            oc[dt][2] *= alpha[1]; oc[dt][3] *= alpha[1];
        }

        // ---- O += P V ----
        #pragma unroll
        for (int ks = 0; ks < 8; ++ks) {
            #pragma unroll
            for (int dt2 = 0; dt2 < 4; ++dt2) {
                uint32_t bv[4];
                const uint32_t addr = vsB
                    + (uint32_t)(ks * 16 + (lane & 7) + ((lane >> 3) & 1) * 8) * ASTRB
                    + (uint32_t)(dt2 * 16 + ((lane >> 4) & 1) * 8) * 2;
                ldm4t(bv, addr);
                mma_f16(oc[2 * dt2],     pf[ks], bv[0], bv[1]);
                mma_f16(oc[2 * dt2 + 1], pf[ks], bv[2], bv[3]);
            }
        }
        __syncthreads();
    }

    // ---- normalize + write fp16 ----
    #pragma unroll
    for (int r = 0; r < 2; ++r) {
        const float inv = 1.0f / lsum[r];
        const int row = q0 + w * 16 + g + r * 8;
        const size_t base = (size_t)(b * SEQ + row) * DMODEL + h * HD + t * 2;
        #pragma unroll
        for (int dt = 0; dt < 8; ++dt) {
            *(uint32_t*)(oh + base + dt * 8) =
                pack_h2(oc[dt][2 * r] * inv, oc[dt][2 * r + 1] * inv);
        }
    }
}

// ==================== launch ====================
extern "C" void kernel_launch(void* const* d_in, const int* in_sizes, int n_in,
                              void* d_out, int out_size)
{
    (void)in_sizes; (void)n_in; (void)out_size;
    const float* x    = (const float*)d_in[0];
    const float* g1   = (const float*)d_in[1];
    const float* b1   = (const float*)d_in[2];
    const float* Wqkv = (const float*)d_in[3];
    const float* bqkv = (const float*)d_in[4];
    const float* Wo   = (const float*)d_in[5];
    const float* bo   = (const float*)d_in[6];
    const float* g2   = (const float*)d_in[7];
    const float* b2   = (const float*)d_in[8];
    const float* W1   = (const float*)d_in[9];
    const float* b1m  = (const float*)d_in[10];
    const float* W2   = (const float*)d_in[11];
    const float* b2m  = (const float*)d_in[12];
    float* out = (float*)d_out;

    float* x1;
    __half *qkvh, *hh, *ah, *fh, *wh;
    cudaGetSymbolAddress((void**)&x1,   g_x1);
    cudaGetSymbolAddress((void**)&qkvh, g_qkvh);
    cudaGetSymbolAddress((void**)&hh,   g_hh);
    cudaGetSymbolAddress((void**)&ah,   g_ah);
    cudaGetSymbolAddress((void**)&fh,   g_fh);
    cudaGetSymbolAddress((void**)&wh,   g_wh);

    cudaFuncSetAttribute(gemm_mma<false, false, true>,
                         cudaFuncAttributeMaxDynamicSharedMemorySize, GEMM_SMEM);
    cudaFuncSetAttribute(gemm_mma<false, true, false>,
                         cudaFuncAttributeMaxDynamicSharedMemorySize, GEMM_SMEM);
    cudaFuncSetAttribute(gemm_mma<true, false, true>,
                         cudaFuncAttributeMaxDynamicSharedMemorySize, GEMM_SMEM);
    cudaFuncSetAttribute(attn_mma,
                         cudaFuncAttributeMaxDynamicSharedMemorySize, ATTN_SMEM);

    // 0) weight prep (fp16 convert)
    conv_kernel<<<(3 * DMODEL * DMODEL / 4 + 255) / 256, 256>>>(
        (const float4*)Wqkv, (uint2*)(wh + WQKV_OFF), 3 * DMODEL * DMODEL / 4);
    conv_kernel<<<(DMODEL * DMODEL / 4 + 255) / 256, 256>>>(
        (const float4*)Wo, (uint2*)(wh + WO_OFF), DMODEL * DMODEL / 4);
    conv_kernel<<<(FFD * DMODEL / 4 + 255) / 256, 256>>>(
        (const float4*)W1, (uint2*)(wh + W1_OFF), FFD * DMODEL / 4);
    conv_kernel<<<(DMODEL * FFD / 4 + 255) / 256, 256>>>(
        (const float4*)W2, (uint2*)(wh + W2_OFF), DMODEL * FFD / 4);

    // 1) h = LN1(x)
    ln_kernel<<<TOK, 256>>>(x, g1, b1, hh);
    // 2) qkv = h @ Wqkv^T + bqkv (fp16 out)
    gemm_mma<false, false, true><<<dim3(3 * DMODEL / 128, TOK / 128), 256, GEMM_SMEM>>>(
        hh, wh + WQKV_OFF, bqkv, nullptr,
        nullptr, qkvh, TOK, 3 * DMODEL, DMODEL);
    // 3) attention
    attn_mma<<<dim3(SEQ / AQ, NH, NB), 256, ATTN_SMEM>>>(qkvh, ah);
    // 4) x1 = x + att @ Wo^T + bo (fp32 out)
    gemm_mma<false, true, false><<<dim3(DMODEL / 128, TOK / 128), 256, GEMM_SMEM>>>(
        ah, wh + WO_OFF, bo, x,
        x1, nullptr, TOK, DMODEL, DMODEL);
    // 5) h = LN2(x1)
    ln_kernel<<<TOK, 256>>>(x1, g2, b2, hh);
    // 6) ffh = gelu(h @ W1^T + b1m) (fp16 out)
    gemm_mma<true, false, true><<<dim3(FFD / 128, TOK / 128), 256, GEMM_SMEM>>>(
        hh, wh + W1_OFF, b1m, nullptr,
        nullptr, fh, TOK, FFD, DMODEL);
    // 7) out = x1 + ffh @ W2^T + b2m (fp32 out)
    gemm_mma<false, true, false><<<dim3(DMODEL / 128, TOK / 128), 256, GEMM_SMEM>>>(
        fh, wh + W2_OFF, b2m, x1,
        out, nullptr, TOK, DMODEL, FFD);
}

// round 10
// speedup vs baseline: 5.8758x; 1.0368x over previous
#include <cuda_runtime.h>
#include <cuda_fp16.h>
#include <stdint.h>
#include <math.h>

// ---------------- problem constants ----------------
#define NB     2
#define SEQ    2048
#define TOK    4096
#define DMODEL 1024
#define NH     16
#define HD     64
#define FFD    4096
#define LN_EPS 1e-5f

// ---------------- scratch (device globals; no allocation) ----------------
__device__ float  g_x1 [TOK * DMODEL];          // post-attn residual (fp32)
__device__ __half g_qkvh[TOK * 3 * DMODEL];     // QKV (fp16)
__device__ __half g_hh [TOK * DMODEL];          // LN output (fp16)
__device__ __half g_ah [TOK * DMODEL];          // attention output (fp16)
__device__ __half g_fh [TOK * FFD];             // MLP hidden (fp16)
#define WTOT (12 * 1024 * 1024)
__device__ __half g_wh[WTOT];                   // all weights fp16

#define WQKV_OFF 0
#define WO_OFF   3145728
#define W1_OFF   4194304
#define W2_OFF   8388608

// ==================== helpers ====================
static __device__ __forceinline__ uint32_t smem_u32(const void* p) {
    uint32_t a;
    asm("{ .reg .u64 t; cvta.to.shared.u64 t, %1; cvt.u32.u64 %0, t; }"
        : "=r"(a) : "l"(p));
    return a;
}

static __device__ __forceinline__ void cpasync16(uint32_t s, const void* g) {
    asm volatile(
        "{ .reg .u64 p; cvta.to.global.u64 p, %1; "
        "cp.async.cg.shared.global [%0], [p], 16; }"
        :: "r"(s), "l"(g) : "memory");
}
#define CP_COMMIT() asm volatile("cp.async.commit_group;" ::: "memory")
#define CP_WAIT1()  asm volatile("cp.async.wait_group 1;" ::: "memory")
#define CP_WAIT0()  asm volatile("cp.async.wait_group 0;" ::: "memory")

static __device__ __forceinline__ void ldm4(uint32_t* r, uint32_t addr) {
    asm volatile("ldmatrix.sync.aligned.m8n8.x4.shared.b16 {%0,%1,%2,%3}, [%4];"
        : "=r"(r[0]), "=r"(r[1]), "=r"(r[2]), "=r"(r[3]) : "r"(addr));
}
static __device__ __forceinline__ void ldm4t(uint32_t* r, uint32_t addr) {
    asm volatile("ldmatrix.sync.aligned.m8n8.x4.trans.shared.b16 {%0,%1,%2,%3}, [%4];"
        : "=r"(r[0]), "=r"(r[1]), "=r"(r[2]), "=r"(r[3]) : "r"(addr));
}

static __device__ __forceinline__ void mma_f16(float* c, const uint32_t* a,
                                               uint32_t b0, uint32_t b1) {
    asm volatile(
        "mma.sync.aligned.m16n8k16.row.col.f32.f16.f16.f32 "
        "{%0,%1,%2,%3}, {%4,%5,%6,%7}, {%8,%9}, {%0,%1,%2,%3};"
        : "+f"(c[0]), "+f"(c[1]), "+f"(c[2]), "+f"(c[3])
        : "r"(a[0]), "r"(a[1]), "r"(a[2]), "r"(a[3]), "r"(b0), "r"(b1));
}

// fp16-accumulated variant: D/C are 2 f16x2 regs (rows g / g+8, cols 2t,2t+1)
static __device__ __forceinline__ void mma_f16_hacc(uint32_t* c, const uint32_t* a,
                                                    uint32_t b0, uint32_t b1) {
    asm volatile(
        "mma.sync.aligned.m16n8k16.row.col.f16.f16.f16.f16 "
        "{%0,%1}, {%2,%3,%4,%5}, {%6,%7}, {%0,%1};"
        : "+r"(c[0]), "+r"(c[1])
        : "r"(a[0]), "r"(a[1]), "r"(a[2]), "r"(a[3]), "r"(b0), "r"(b1));
}

// pack two fp32 -> f16x2 register (first arg -> low half)
static __device__ __forceinline__ uint32_t pack_h2(float lo, float hi) {
    uint32_t r;
    asm("cvt.rn.f16x2.f32 %0, %1, %2;" : "=r"(r) : "f"(hi), "f"(lo));
    return r;
}
static __device__ __forceinline__ uint32_t ex2_h2(uint32_t x) {
    uint32_t r;
    asm("ex2.approx.f16x2 %0, %1;" : "=r"(r) : "r"(x));
    return r;
}

// ==================== weight conversion (fp32 -> fp16) ====================
__global__ __launch_bounds__(256) void conv_kernel(
    const float4* __restrict__ w, uint2* __restrict__ hi, int n4)
{
    int i = blockIdx.x * 256 + threadIdx.x;
    if (i < n4) {
        const float4 v = w[i];
        uint2 o;
        o.x = pack_h2(v.x, v.y);
        o.y = pack_h2(v.z, v.w);
        hi[i] = o;
    }
}

// ==================== LayerNorm -> fp16 ====================
__global__ __launch_bounds__(256) void ln_kernel(
    const float* __restrict__ x, const float* __restrict__ g,
    const float* __restrict__ b, __half* __restrict__ y)
{
    __shared__ float red[8];
    __shared__ float bc[2];
    const int r = blockIdx.x, tid = threadIdx.x;
    const int wid = tid >> 5, lane = tid & 31;

    const float4 v = ((const float4*)(x + (size_t)r * DMODEL))[tid];

    float s = v.x + v.y + v.z + v.w;
    #pragma unroll
    for (int o = 16; o; o >>= 1) s += __shfl_xor_sync(0xffffffffu, s, o);
    if (lane == 0) red[wid] = s;
    __syncthreads();
    if (tid == 0) {
        float t = 0.f;
        #pragma unroll
        for (int i = 0; i < 8; ++i) t += red[i];
        bc[0] = t * (1.0f / DMODEL);
    }
    __syncthreads();
    const float mean = bc[0];

    const float dx = v.x - mean, dy = v.y - mean, dz = v.z - mean, dw = v.w - mean;
    float ss = dx * dx + dy * dy + dz * dz + dw * dw;
    #pragma unroll
    for (int o = 16; o; o >>= 1) ss += __shfl_xor_sync(0xffffffffu, ss, o);
    if (lane == 0) red[wid] = ss;
    __syncthreads();
    if (tid == 0) {
        float t = 0.f;
        #pragma unroll
        for (int i = 0; i < 8; ++i) t += red[i];
        bc[1] = rsqrtf(t * (1.0f / DMODEL) + LN_EPS);
    }
    __syncthreads();
    const float rs = bc[1];

    const float4 gv = ((const float4*)g)[tid];
    const float4 bv = ((const float4*)b)[tid];
    uint2 o2;
    o2.x = pack_h2(dx * rs * gv.x + bv.x, dy * rs * gv.y + bv.y);
    o2.y = pack_h2(dz * rs * gv.z + bv.z, dw * rs * gv.w + bv.w);
    *(uint2*)(y + (size_t)r * DMODEL + tid * 4) = o2;
}

// ==================== mma.sync GEMM (NT, fp16, single term) ====================
// CTA tile 128x128, BK=64, 256 threads (8 warps 2x4), warp tile 64x32.
// 3-stage cp.async ring; smem tile rows padded to 144 B (conflict-free ldmatrix).
#define TILE_B   18432              // 128 * 144
#define STAGE_B  (2 * TILE_B)       // A + B  = 36864
#define GEMM_SMEM (3 * STAGE_B)     // 110592

static __device__ __forceinline__ void stage_load(
    uint32_t s0, const __half* gA, const __half* gB,
    int m0, int n0, int K, int kt, int tid)
{
    #pragma unroll
    for (int q = 0; q < 4; ++q) {
        const int u   = tid + q * 256;        // 0..1023
        const int row = u >> 3;
        const int seg = u & 7;
        const uint32_t soff = row * 144 + seg * 16;
        const size_t ga = (size_t)(m0 + row) * K + kt + seg * 8;
        const size_t gb = (size_t)(n0 + row) * K + kt + seg * 8;
        cpasync16(s0 +          soff, gA + ga);
        cpasync16(s0 + TILE_B + soff, gB + gb);
    }
}

template<bool GELU_F, bool RES_F, bool OUTH_F>
__global__ __launch_bounds__(256, 2)
void gemm_mma(
    const __half* __restrict__ A, const __half* __restrict__ B,
    const float* __restrict__ bias, const float* __restrict__ res,
    float* __restrict__ Cf, __half* __restrict__ Ch,
    int M, int N, int K)
{
    extern __shared__ char dsm[];
    const uint32_t sb = smem_u32(dsm);

    const int tid  = threadIdx.x;
    const int wid  = tid >> 5, lane = tid & 31;
    const int wm   = wid & 1;
    const int wn   = wid >> 1;
    const int m0   = blockIdx.y << 7;
    const int n0   = blockIdx.x << 7;

    float acc[4][4][4];
    #pragma unroll
    for (int i = 0; i < 4; ++i)
        #pragma unroll
        for (int j = 0; j < 4; ++j) {
            acc[i][j][0] = 0.f; acc[i][j][1] = 0.f;
            acc[i][j][2] = 0.f; acc[i][j][3] = 0.f;
        }

    const int lr   = lane & 15;
    const int cof  = (lane >> 4) << 3;
    const uint32_t aRowByte = (uint32_t)(wm * 64 + lr) * 144;
    const uint32_t bRowByte = (uint32_t)(wn * 32 + lr) * 144;

    const int NC = K >> 6;

    stage_load(sb,           A, B, m0, n0, K, 0,  tid);
    CP_COMMIT();
    stage_load(sb + STAGE_B, A, B, m0, n0, K, 64, tid);
    CP_COMMIT();

    for (int c = 0; c < NC; ++c) {
        if (c + 2 < NC)
            stage_load(sb + ((c + 2) % 3) * STAGE_B, A, B,
                       m0, n0, K, (c + 2) << 6, tid);
        CP_COMMIT();
        CP_WAIT1();
        __syncthreads();

        const uint32_t s0 = sb + (c % 3) * STAGE_B;
        const uint32_t aA = s0;
        const uint32_t aB = s0 + TILE_B;

        #pragma unroll
        for (int ks = 0; ks < 4; ++ks) {
            const uint32_t kbyte = (uint32_t)(ks * 16 + cof) * 2;

            uint32_t af[4][4];
            #pragma unroll
            for (int mi = 0; mi < 4; ++mi)
                ldm4(af[mi], aA + aRowByte + (uint32_t)(mi * 16) * 144 + kbyte);

            uint32_t bf[2][4];
            #pragma unroll
            for (int nt = 0; nt < 2; ++nt)
                ldm4(bf[nt], aB + bRowByte + (uint32_t)(nt * 16) * 144 + kbyte);

            #pragma unroll
            for (int mi = 0; mi < 4; ++mi)
                #pragma unroll
                for (int ni = 0; ni < 4; ++ni)
                    mma_f16(acc[mi][ni], af[mi],
                            bf[ni >> 1][ni & 1], bf[ni >> 1][2 + (ni & 1)]);
        }
        __syncthreads();
    }

    const int tr = lane >> 2;
    const int tc = (lane & 3) << 1;
    #pragma unroll
    for (int mi = 0; mi < 4; ++mi) {
        #pragma unroll
        for (int ni = 0; ni < 4; ++ni) {
            const int col = n0 + wn * 32 + ni * 8 + tc;
            #pragma unroll
            for (int half_ = 0; half_ < 2; ++half_) {
                const int row = m0 + wm * 64 + mi * 16 + tr + half_ * 8;
                float vx = acc[mi][ni][half_ * 2 + 0] + bias[col + 0];
                float vy = acc[mi][ni][half_ * 2 + 1] + bias[col + 1];
                if (RES_F) {
                    const float2 rv = *(const float2*)&res[(size_t)row * N + col];
                    vx += rv.x; vy += rv.y;
                }
                if (GELU_F) {
                    vx = 0.5f * vx * (1.0f + erff(vx * 0.70710678f));
                    vy = 0.5f * vy * (1.0f + erff(vy * 0.70710678f));
                }
                const size_t off = (size_t)row * N + col;
                if (OUTH_F) {
                    *(uint32_t*)(Ch + off) = pack_h2(vx, vy);
                } else {
                    float2 o; o.x = vx; o.y = vy;
                    *(float2*)&Cf[off] = o;
                }
            }
        }
    }
}

// ==================== Tensor-core flash attention (fp16, cp.async) ====================
// fp16-accumulated S; exp applied in place; S C-fragment reused as PV A-fragment.
#define AQ    128
#define AKV   128
#define ASTRB 144
#define Q_OFF 0
#define KV_OFF 18432
#define KV_STG 36864
#define ATTN_SMEM (KV_OFF + 2 * KV_STG)   // 92160

__global__ __launch_bounds__(256, 2) void attn_mma(
    const __half* __restrict__ qkv, __half* __restrict__ oh)
{
    extern __shared__ char asm_[];
    const uint32_t sB = smem_u32(asm_);

    const int tid = threadIdx.x;
    const int w = tid >> 5, lane = tid & 31;
    const int g = lane >> 2, t = lane & 3;
    const int b = blockIdx.z, h = blockIdx.y;
    const int q0 = blockIdx.x * AQ;

    const int lrow = tid >> 1;
    const int lhf  = tid & 1;

    const __half* tokbase = qkv + (size_t)(b * SEQ) * (3 * DMODEL) + h * 192;

    // ---- stage Q via cp.async ----
    {
        const __half* qp = tokbase + (size_t)(q0 + lrow) * (3 * DMODEL) + lhf * 32;
        const uint32_t sq = sB + Q_OFF + lrow * ASTRB + lhf * 64;
        #pragma unroll
        for (int s = 0; s < 4; ++s)
            cpasync16(sq + s * 16, qp + s * 8);
    }
    CP_COMMIT();
    CP_WAIT0();
    __syncthreads();

    uint32_t qf[4][4];
    {
        const uint32_t rb = sB + Q_OFF + (uint32_t)(w * 16 + (lane & 15)) * ASTRB
                          + (uint32_t)(((lane >> 4) & 1) * 8) * 2;
        #pragma unroll
        for (int ks = 0; ks < 4; ++ks)
            ldm4(qf[ks], rb + ks * 32);
    }
    __syncthreads();

    float oc[8][4];
    #pragma unroll
    for (int i = 0; i < 8; ++i) {
        oc[i][0] = 0.f; oc[i][1] = 0.f; oc[i][2] = 0.f; oc[i][3] = 0.f;
    }
    float mrow[2] = {-INFINITY, -INFINITY};
    float lsum[2] = {0.f, 0.f};

    const int NT = SEQ / AKV;
    const float K1 = 0.125f * 1.4426950408889634f;   // log2(e)/8
    const __half2 k1h = __float2half2_rn(K1);

    // prefetch KV tile 0
    {
        const __half* kp = tokbase + (size_t)lrow * (3 * DMODEL) + 64 + lhf * 32;
        const uint32_t sk = sB + KV_OFF + lrow * ASTRB + lhf * 64;
        #pragma unroll
        for (int s = 0; s < 4; ++s) cpasync16(sk + s * 16, kp + s * 8);
        const uint32_t sv = sk + 18432;
        #pragma unroll
        for (int s = 0; s < 4; ++s) cpasync16(sv + s * 16, kp + 64 + s * 8);
    }
    CP_COMMIT();

    for (int tI = 0; tI < NT; ++tI) {
        if (tI + 1 < NT) {
            const int kv1 = (tI + 1) * AKV;
            const __half* kp = tokbase + (size_t)(kv1 + lrow) * (3 * DMODEL) + 64 + lhf * 32;
            const uint32_t sk = sB + KV_OFF + ((tI + 1) & 1) * KV_STG + lrow * ASTRB + lhf * 64;
            #pragma unroll
            for (int s = 0; s < 4; ++s) cpasync16(sk + s * 16, kp + s * 8);
            const uint32_t sv = sk + 18432;
            #pragma unroll
            for (int s = 0; s < 4; ++s) cpasync16(sv + s * 16, kp + 64 + s * 8);
            CP_COMMIT();
            CP_WAIT1();
        } else {
            CP_WAIT0();
        }
        __syncthreads();

        const uint32_t ksB = sB + KV_OFF + (tI & 1) * KV_STG;
        const uint32_t vsB = ksB + 18432;

        // ---- S = Q K^T (fp16 accumulate; 2 regs per 8-wide tile) ----
        uint32_t sch[16][2];
        #pragma unroll
        for (int nt2 = 0; nt2 < 8; ++nt2) {
            sch[2 * nt2][0] = 0u; sch[2 * nt2][1] = 0u;
            sch[2 * nt2 + 1][0] = 0u; sch[2 * nt2 + 1][1] = 0u;
            #pragma unroll
            for (int ks = 0; ks < 4; ++ks) {
                uint32_t bf[4];
                const uint32_t addr = ksB
                    + (uint32_t)(nt2 * 16 + (lane & 7) + ((lane >> 4) & 1) * 8) * ASTRB
                    + (uint32_t)(ks * 16 + ((lane >> 3) & 1) * 8) * 2;
                ldm4(bf, addr);
                mma_f16_hacc(sch[2 * nt2],     qf[ks], bf[0], bf[1]);
                mma_f16_hacc(sch[2 * nt2 + 1], qf[ks], bf[2], bf[3]);
            }
        }

        // ---- online softmax in h2, exp in place (sch becomes P A-fragments) ----
        float alpha[2];
        #pragma unroll
        for (int r = 0; r < 2; ++r) {
            __half2 m2 = *(__half2*)&sch[0][r];
            #pragma unroll
            for (int nt = 1; nt < 16; ++nt)
                m2 = __hmax2(m2, *(__half2*)&sch[nt][r]);
            float mx = fmaxf(__low2float(m2), __high2float(m2));
            mx = fmaxf(mx, __shfl_xor_sync(0xffffffffu, mx, 1));
            mx = fmaxf(mx, __shfl_xor_sync(0xffffffffu, mx, 2));
            const float mn = fmaxf(mrow[r], mx);
            alpha[r] = __expf((mrow[r] - mn) * 0.125f);
            mrow[r] = mn;
            const __half2 c2h = __float2half2_rn(-mn * K1);
            __half2 s2 = __float2half2_rn(0.f);
            #pragma unroll
            for (int nt = 0; nt < 16; ++nt) {
                __half2 arg = __hfma2(*(__half2*)&sch[nt][r], k1h, c2h);
                const uint32_t pe = ex2_h2(*(uint32_t*)&arg);
                sch[nt][r] = pe;
                s2 = __hadd2(s2, *(const __half2*)&pe);
            }
            const float2 f2 = __half22float2(s2);
            float rs = f2.x + f2.y;
            rs += __shfl_xor_sync(0xffffffffu, rs, 1);
            rs += __shfl_xor_sync(0xffffffffu, rs, 2);
            lsum[r] = lsum[r] * alpha[r] + rs;
        }
        #pragma unroll
        for (int dt = 0; dt < 8; ++dt) {
            oc[dt][0] *= alpha[0]; oc[dt][1] *= alpha[0];
            oc[dt][2] *= alpha[1]; oc[dt][3] *= alpha[1];
        }

        // ---- O += P V (P fragments = transformed sch, zero-copy) ----
        #pragma unroll
        for (int ks = 0; ks < 8; ++ks) {
            const uint32_t pa[4] = {sch[2 * ks][0], sch[2 * ks][1],
                                    sch[2 * ks + 1][0], sch[2 * ks + 1][1]};
            #pragma unroll
            for (int dt2 = 0; dt2 < 4; ++dt2) {
                uint32_t bv[4];
                const uint32_t addr = vsB
                    + (uint32_t)(ks * 16 + (lane & 7) + ((lane >> 3) & 1) * 8) * ASTRB
                    + (uint32_t)(dt2 * 16 + ((lane >> 4) & 1) * 8) * 2;
                ldm4t(bv, addr);
                mma_f16(oc[2 * dt2],     pa, bv[0], bv[1]);
                mma_f16(oc[2 * dt2 + 1], pa, bv[2], bv[3]);
            }
        }
        __syncthreads();
    }

    // ---- normalize + write fp16 ----
    #pragma unroll
    for (int r = 0; r < 2; ++r) {
        const float inv = 1.0f / lsum[r];
        const int row = q0 + w * 16 + g + r * 8;
        const size_t base = (size_t)(b * SEQ + row) * DMODEL + h * HD + t * 2;
        #pragma unroll
        for (int dt = 0; dt < 8; ++dt) {
            *(uint32_t*)(oh + base + dt * 8) =
                pack_h2(oc[dt][2 * r] * inv, oc[dt][2 * r + 1] * inv);
        }
    }
}

// ==================== launch ====================
extern "C" void kernel_launch(void* const* d_in, const int* in_sizes, int n_in,
                              void* d_out, int out_size)
{
    (void)in_sizes; (void)n_in; (void)out_size;
    const float* x    = (const float*)d_in[0];
    const float* g1   = (const float*)d_in[1];
    const float* b1   = (const float*)d_in[2];
    const float* Wqkv = (const float*)d_in[3];
    const float* bqkv = (const float*)d_in[4];
    const float* Wo   = (const float*)d_in[5];
    const float* bo   = (const float*)d_in[6];
    const float* g2   = (const float*)d_in[7];
    const float* b2   = (const float*)d_in[8];
    const float* W1   = (const float*)d_in[9];
    const float* b1m  = (const float*)d_in[10];
    const float* W2   = (const float*)d_in[11];
    const float* b2m  = (const float*)d_in[12];
    float* out = (float*)d_out;

    float* x1;
    __half *qkvh, *hh, *ah, *fh, *wh;
    cudaGetSymbolAddress((void**)&x1,   g_x1);
    cudaGetSymbolAddress((void**)&qkvh, g_qkvh);
    cudaGetSymbolAddress((void**)&hh,   g_hh);
    cudaGetSymbolAddress((void**)&ah,   g_ah);
    cudaGetSymbolAddress((void**)&fh,   g_fh);
    cudaGetSymbolAddress((void**)&wh,   g_wh);

    cudaFuncSetAttribute(gemm_mma<false, false, true>,
                         cudaFuncAttributeMaxDynamicSharedMemorySize, GEMM_SMEM);
    cudaFuncSetAttribute(gemm_mma<false, true, false>,
                         cudaFuncAttributeMaxDynamicSharedMemorySize, GEMM_SMEM);
    cudaFuncSetAttribute(gemm_mma<true, false, true>,
                         cudaFuncAttributeMaxDynamicSharedMemorySize, GEMM_SMEM);
    cudaFuncSetAttribute(attn_mma,
                         cudaFuncAttributeMaxDynamicSharedMemorySize, ATTN_SMEM);

    // 0) weight prep (fp16 convert)
    conv_kernel<<<(3 * DMODEL * DMODEL / 4 + 255) / 256, 256>>>(
        (const float4*)Wqkv, (uint2*)(wh + WQKV_OFF), 3 * DMODEL * DMODEL / 4);
    conv_kernel<<<(DMODEL * DMODEL / 4 + 255) / 256, 256>>>(
        (const float4*)Wo, (uint2*)(wh + WO_OFF), DMODEL * DMODEL / 4);
    conv_kernel<<<(FFD * DMODEL / 4 + 255) / 256, 256>>>(
        (const float4*)W1, (uint2*)(wh + W1_OFF), FFD * DMODEL / 4);
    conv_kernel<<<(DMODEL * FFD / 4 + 255) / 256, 256>>>(
        (const float4*)W2, (uint2*)(wh + W2_OFF), DMODEL * FFD / 4);

    // 1) h = LN1(x)
    ln_kernel<<<TOK, 256>>>(x, g1, b1, hh);
    // 2) qkv = h @ Wqkv^T + bqkv (fp16 out)
    gemm_mma<false, false, true><<<dim3(3 * DMODEL / 128, TOK / 128), 256, GEMM_SMEM>>>(
        hh, wh + WQKV_OFF, bqkv, nullptr,
        nullptr, qkvh, TOK, 3 * DMODEL, DMODEL);
    // 3) attention
    attn_mma<<<dim3(SEQ / AQ, NH, NB), 256, ATTN_SMEM>>>(qkvh, ah);
    // 4) x1 = x + att @ Wo^T + bo (fp32 out)
    gemm_mma<false, true, false><<<dim3(DMODEL / 128, TOK / 128), 256, GEMM_SMEM>>>(
        ah, wh + WO_OFF, bo, x,
        x1, nullptr, TOK, DMODEL, DMODEL);
    // 5) h = LN2(x1)
    ln_kernel<<<TOK, 256>>>(x1, g2, b2, hh);
    // 6) ffh = gelu(h @ W1^T + b1m) (fp16 out)
    gemm_mma<true, false, true><<<dim3(FFD / 128, TOK / 128), 256, GEMM_SMEM>>>(
        hh, wh + W1_OFF, b1m, nullptr,
        nullptr, fh, TOK, FFD, DMODEL);
    // 7) out = x1 + ffh @ W2^T + b2m (fp32 out)
    gemm_mma<false, true, false><<<dim3(DMODEL / 128, TOK / 128), 256, GEMM_SMEM>>>(
        fh, wh + W2_OFF, b2m, x1,
        out, nullptr, TOK, DMODEL, FFD);
}

// round 11
// speedup vs baseline: 6.0826x; 1.0352x over previous
#include <cuda_runtime.h>
#include <cuda_fp16.h>
#include <stdint.h>
#include <math.h>

// ---------------- problem constants ----------------
#define NB     2
#define SEQ    2048
#define TOK    4096
#define DMODEL 1024
#define NH     16
#define HD     64
#define FFD    4096
#define LN_EPS 1e-5f

// ---------------- scratch (device globals; no allocation) ----------------
__device__ float  g_x1 [TOK * DMODEL];          // post-attn residual (fp32)
__device__ __half g_qkvh[TOK * 3 * DMODEL];     // QKV (fp16)
__device__ __half g_hh [TOK * DMODEL];          // LN output (fp16)
__device__ __half g_ah [TOK * DMODEL];          // attention output (fp16)
__device__ __half g_fh [TOK * FFD];             // MLP hidden (fp16)
#define WTOT (12 * 1024 * 1024)
__device__ __half g_wh[WTOT];                   // all weights fp16

#define WQKV_OFF 0
#define WO_OFF   3145728
#define W1_OFF   4194304
#define W2_OFF   8388608

// ==================== helpers ====================
static __device__ __forceinline__ uint32_t smem_u32(const void* p) {
    uint32_t a;
    asm("{ .reg .u64 t; cvta.to.shared.u64 t, %1; cvt.u32.u64 %0, t; }"
        : "=r"(a) : "l"(p));
    return a;
}

static __device__ __forceinline__ void cpasync16(uint32_t s, const void* g) {
    asm volatile(
        "{ .reg .u64 p; cvta.to.global.u64 p, %1; "
        "cp.async.cg.shared.global [%0], [p], 16; }"
        :: "r"(s), "l"(g) : "memory");
}
#define CP_COMMIT() asm volatile("cp.async.commit_group;" ::: "memory")
#define CP_WAIT1()  asm volatile("cp.async.wait_group 1;" ::: "memory")
#define CP_WAIT0()  asm volatile("cp.async.wait_group 0;" ::: "memory")

static __device__ __forceinline__ void ldm4(uint32_t* r, uint32_t addr) {
    asm volatile("ldmatrix.sync.aligned.m8n8.x4.shared.b16 {%0,%1,%2,%3}, [%4];"
        : "=r"(r[0]), "=r"(r[1]), "=r"(r[2]), "=r"(r[3]) : "r"(addr));
}
static __device__ __forceinline__ void ldm4t(uint32_t* r, uint32_t addr) {
    asm volatile("ldmatrix.sync.aligned.m8n8.x4.trans.shared.b16 {%0,%1,%2,%3}, [%4];"
        : "=r"(r[0]), "=r"(r[1]), "=r"(r[2]), "=r"(r[3]) : "r"(addr));
}

static __device__ __forceinline__ void mma_f16(float* c, const uint32_t* a,
                                               uint32_t b0, uint32_t b1) {
    asm volatile(
        "mma.sync.aligned.m16n8k16.row.col.f32.f16.f16.f32 "
        "{%0,%1,%2,%3}, {%4,%5,%6,%7}, {%8,%9}, {%0,%1,%2,%3};"
        : "+f"(c[0]), "+f"(c[1]), "+f"(c[2]), "+f"(c[3])
        : "r"(a[0]), "r"(a[1]), "r"(a[2]), "r"(a[3]), "r"(b0), "r"(b1));
}

// fp16-accumulated variant: D/C are 2 f16x2 regs (rows g / g+8, cols 2t,2t+1)
static __device__ __forceinline__ void mma_f16_hacc(uint32_t* c, const uint32_t* a,
                                                    uint32_t b0, uint32_t b1) {
    asm volatile(
        "mma.sync.aligned.m16n8k16.row.col.f16.f16.f16.f16 "
        "{%0,%1}, {%2,%3,%4,%5}, {%6,%7}, {%0,%1};"
        : "+r"(c[0]), "+r"(c[1])
        : "r"(a[0]), "r"(a[1]), "r"(a[2]), "r"(a[3]), "r"(b0), "r"(b1));
}

// pack two fp32 -> f16x2 register (first arg -> low half)
static __device__ __forceinline__ uint32_t pack_h2(float lo, float hi) {
    uint32_t r;
    asm("cvt.rn.f16x2.f32 %0, %1, %2;" : "=r"(r) : "f"(hi), "f"(lo));
    return r;
}
static __device__ __forceinline__ uint32_t ex2_h2(uint32_t x) {
    uint32_t r;
    asm("ex2.approx.f16x2 %0, %1;" : "=r"(r) : "r"(x));
    return r;
}

// ==================== weight conversion (fp32 -> fp16) ====================
__global__ __launch_bounds__(256) void conv_kernel(
    const float4* __restrict__ w, uint2* __restrict__ hi, int n4)
{
    int i = blockIdx.x * 256 + threadIdx.x;
    if (i < n4) {
        const float4 v = w[i];
        uint2 o;
        o.x = pack_h2(v.x, v.y);
        o.y = pack_h2(v.z, v.w);
        hi[i] = o;
    }
}

// ==================== LayerNorm -> fp16 ====================
__global__ __launch_bounds__(256) void ln_kernel(
    const float* __restrict__ x, const float* __restrict__ g,
    const float* __restrict__ b, __half* __restrict__ y)
{
    __shared__ float red[8];
    __shared__ float bc[2];
    const int r = blockIdx.x, tid = threadIdx.x;
    const int wid = tid >> 5, lane = tid & 31;

    const float4 v = ((const float4*)(x + (size_t)r * DMODEL))[tid];

    float s = v.x + v.y + v.z + v.w;
    #pragma unroll
    for (int o = 16; o; o >>= 1) s += __shfl_xor_sync(0xffffffffu, s, o);
    if (lane == 0) red[wid] = s;
    __syncthreads();
    if (tid == 0) {
        float t = 0.f;
        #pragma unroll
        for (int i = 0; i < 8; ++i) t += red[i];
        bc[0] = t * (1.0f / DMODEL);
    }
    __syncthreads();
    const float mean = bc[0];

    const float dx = v.x - mean, dy = v.y - mean, dz = v.z - mean, dw = v.w - mean;
    float ss = dx * dx + dy * dy + dz * dz + dw * dw;
    #pragma unroll
    for (int o = 16; o; o >>= 1) ss += __shfl_xor_sync(0xffffffffu, ss, o);
    if (lane == 0) red[wid] = ss;
    __syncthreads();
    if (tid == 0) {
        float t = 0.f;
        #pragma unroll
        for (int i = 0; i < 8; ++i) t += red[i];
        bc[1] = rsqrtf(t * (1.0f / DMODEL) + LN_EPS);
    }
    __syncthreads();
    const float rs = bc[1];

    const float4 gv = ((const float4*)g)[tid];
    const float4 bv = ((const float4*)b)[tid];
    uint2 o2;
    o2.x = pack_h2(dx * rs * gv.x + bv.x, dy * rs * gv.y + bv.y);
    o2.y = pack_h2(dz * rs * gv.z + bv.z, dw * rs * gv.w + bv.w);
    *(uint2*)(y + (size_t)r * DMODEL + tid * 4) = o2;
}

// ==================== mma.sync GEMM (NT, fp16, single term) ====================
// CTA tile 128x128, BK=64, 256 threads (8 warps 2x4), warp tile 64x32.
// 3-stage cp.async ring; smem tile rows padded to 144 B (conflict-free ldmatrix).
#define TILE_B   18432              // 128 * 144
#define STAGE_B  (2 * TILE_B)       // A + B  = 36864
#define GEMM_SMEM (3 * STAGE_B)     // 110592

static __device__ __forceinline__ void stage_load(
    uint32_t s0, const __half* gA, const __half* gB,
    int m0, int n0, int K, int kt, int tid)
{
    #pragma unroll
    for (int q = 0; q < 4; ++q) {
        const int u   = tid + q * 256;        // 0..1023
        const int row = u >> 3;
        const int seg = u & 7;
        const uint32_t soff = row * 144 + seg * 16;
        const size_t ga = (size_t)(m0 + row) * K + kt + seg * 8;
        const size_t gb = (size_t)(n0 + row) * K + kt + seg * 8;
        cpasync16(s0 +          soff, gA + ga);
        cpasync16(s0 + TILE_B + soff, gB + gb);
    }
}

template<bool GELU_F, bool RES_F, bool OUTH_F>
__global__ __launch_bounds__(256, 2)
void gemm_mma(
    const __half* __restrict__ A, const __half* __restrict__ B,
    const float* __restrict__ bias, const float* __restrict__ res,
    float* __restrict__ Cf, __half* __restrict__ Ch,
    int M, int N, int K)
{
    extern __shared__ char dsm[];
    const uint32_t sb = smem_u32(dsm);

    const int tid  = threadIdx.x;
    const int wid  = tid >> 5, lane = tid & 31;
    const int wm   = wid & 1;
    const int wn   = wid >> 1;
    const int m0   = blockIdx.y << 7;
    const int n0   = blockIdx.x << 7;

    float acc[4][4][4];
    #pragma unroll
    for (int i = 0; i < 4; ++i)
        #pragma unroll
        for (int j = 0; j < 4; ++j) {
            acc[i][j][0] = 0.f; acc[i][j][1] = 0.f;
            acc[i][j][2] = 0.f; acc[i][j][3] = 0.f;
        }

    const int lr   = lane & 15;
    const int cof  = (lane >> 4) << 3;
    const uint32_t aRowByte = (uint32_t)(wm * 64 + lr) * 144;
    const uint32_t bRowByte = (uint32_t)(wn * 32 + lr) * 144;

    const int NC = K >> 6;

    stage_load(sb,           A, B, m0, n0, K, 0,  tid);
    CP_COMMIT();
    stage_load(sb + STAGE_B, A, B, m0, n0, K, 64, tid);
    CP_COMMIT();

    for (int c = 0; c < NC; ++c) {
        if (c + 2 < NC)
            stage_load(sb + ((c + 2) % 3) * STAGE_B, A, B,
                       m0, n0, K, (c + 2) << 6, tid);
        CP_COMMIT();
        CP_WAIT1();
        __syncthreads();

        const uint32_t s0 = sb + (c % 3) * STAGE_B;
        const uint32_t aA = s0;
        const uint32_t aB = s0 + TILE_B;

        #pragma unroll
        for (int ks = 0; ks < 4; ++ks) {
            const uint32_t kbyte = (uint32_t)(ks * 16 + cof) * 2;

            uint32_t af[4][4];
            #pragma unroll
            for (int mi = 0; mi < 4; ++mi)
                ldm4(af[mi], aA + aRowByte + (uint32_t)(mi * 16) * 144 + kbyte);

            uint32_t bf[2][4];
            #pragma unroll
            for (int nt = 0; nt < 2; ++nt)
                ldm4(bf[nt], aB + bRowByte + (uint32_t)(nt * 16) * 144 + kbyte);

            #pragma unroll
            for (int mi = 0; mi < 4; ++mi)
                #pragma unroll
                for (int ni = 0; ni < 4; ++ni)
                    mma_f16(acc[mi][ni], af[mi],
                            bf[ni >> 1][ni & 1], bf[ni >> 1][2 + (ni & 1)]);
        }
        __syncthreads();
    }

    const int tr = lane >> 2;
    const int tc = (lane & 3) << 1;
    #pragma unroll
    for (int mi = 0; mi < 4; ++mi) {
        #pragma unroll
        for (int ni = 0; ni < 4; ++ni) {
            const int col = n0 + wn * 32 + ni * 8 + tc;
            #pragma unroll
            for (int half_ = 0; half_ < 2; ++half_) {
                const int row = m0 + wm * 64 + mi * 16 + tr + half_ * 8;
                float vx = acc[mi][ni][half_ * 2 + 0] + bias[col + 0];
                float vy = acc[mi][ni][half_ * 2 + 1] + bias[col + 1];
                if (RES_F) {
                    const float2 rv = *(const float2*)&res[(size_t)row * N + col];
                    vx += rv.x; vy += rv.y;
                }
                if (GELU_F) {
                    vx = 0.5f * vx * (1.0f + erff(vx * 0.70710678f));
                    vy = 0.5f * vy * (1.0f + erff(vy * 0.70710678f));
                }
                const size_t off = (size_t)row * N + col;
                if (OUTH_F) {
                    *(uint32_t*)(Ch + off) = pack_h2(vx, vy);
                } else {
                    float2 o; o.x = vx; o.y = vy;
                    *(float2*)&Cf[off] = o;
                }
            }
        }
    }
}

// ==================== Tensor-core flash attention ====================
// fp16-acc S, in-place exp, zero-copy P. 32 q-rows/warp (two m16 halves):
// K/V fragments are warp-invariant, so doubling q-rows per warp halves the
// smem bytes per MAC (0.125 -> 0.0625 B/MAC) -> tensor-bound.
// CTA: 256 q-rows, 8 warps, 256 threads, 1 CTA/SM. grid (SEQ/256, NH, NB).
#define AQ    256
#define AKV   128
#define ASTRB 144
#define Q_OFF 0
#define Q_BYTES (256 * ASTRB)             // 36864
#define KV_OFF  Q_BYTES
#define KV_STG  36864                     // K tile + V tile
#define ATTN_SMEM (KV_OFF + 2 * KV_STG)   // 110592

__global__ __launch_bounds__(256, 1) void attn_mma(
    const __half* __restrict__ qkv, __half* __restrict__ oh)
{
    extern __shared__ char asm_[];
    const uint32_t sB = smem_u32(asm_);

    const int tid = threadIdx.x;
    const int w = tid >> 5, lane = tid & 31;
    const int g = lane >> 2, t = lane & 3;
    const int b = blockIdx.z, h = blockIdx.y;
    const int q0 = blockIdx.x * AQ;

    const int lrow = tid >> 1;        // 0..127 (KV load row)
    const int lhf  = tid & 1;

    const __half* tokbase = qkv + (size_t)(b * SEQ) * (3 * DMODEL) + h * 192;

    // ---- stage Q (256 rows, one thread per row) ----
    {
        const __half* qp = tokbase + (size_t)(q0 + tid) * (3 * DMODEL);
        const uint32_t sq = sB + Q_OFF + tid * ASTRB;
        #pragma unroll
        for (int s = 0; s < 8; ++s)
            cpasync16(sq + s * 16, qp + s * 8);
    }
    CP_COMMIT();
    CP_WAIT0();
    __syncthreads();

    // qf[mh][ks][4]: two m16 groups per warp (rows w*32 + mh*16 + ...)
    uint32_t qf[2][4][4];
    #pragma unroll
    for (int mh = 0; mh < 2; ++mh) {
        const uint32_t rb = sB + Q_OFF
            + (uint32_t)(w * 32 + mh * 16 + (lane & 15)) * ASTRB
            + (uint32_t)(((lane >> 4) & 1) * 8) * 2;
        #pragma unroll
        for (int ks = 0; ks < 4; ++ks)
            ldm4(qf[mh][ks], rb + ks * 32);
    }
    __syncthreads();

    float oc[2][8][4];
    #pragma unroll
    for (int mh = 0; mh < 2; ++mh)
        #pragma unroll
        for (int i = 0; i < 8; ++i) {
            oc[mh][i][0] = 0.f; oc[mh][i][1] = 0.f;
            oc[mh][i][2] = 0.f; oc[mh][i][3] = 0.f;
        }
    float mrow[2][2] = {{-INFINITY, -INFINITY}, {-INFINITY, -INFINITY}};
    float lsum[2][2] = {{0.f, 0.f}, {0.f, 0.f}};

    const int NT = SEQ / AKV;   // 16
    const float K1 = 0.125f * 1.4426950408889634f;   // log2(e)/8
    const __half2 k1h = __float2half2_rn(K1);

    // prefetch KV tile 0
    {
        const __half* kp = tokbase + (size_t)lrow * (3 * DMODEL) + 64 + lhf * 32;
        const uint32_t sk = sB + KV_OFF + lrow * ASTRB + lhf * 64;
        #pragma unroll
        for (int s = 0; s < 4; ++s) cpasync16(sk + s * 16, kp + s * 8);
        const uint32_t sv = sk + 18432;
        #pragma unroll
        for (int s = 0; s < 4; ++s) cpasync16(sv + s * 16, kp + 64 + s * 8);
    }
    CP_COMMIT();

    for (int tI = 0; tI < NT; ++tI) {
        if (tI + 1 < NT) {
            const int kv1 = (tI + 1) * AKV;
            const __half* kp = tokbase + (size_t)(kv1 + lrow) * (3 * DMODEL) + 64 + lhf * 32;
            const uint32_t sk = sB + KV_OFF + ((tI + 1) & 1) * KV_STG + lrow * ASTRB + lhf * 64;
            #pragma unroll
            for (int s = 0; s < 4; ++s) cpasync16(sk + s * 16, kp + s * 8);
            const uint32_t sv = sk + 18432;
            #pragma unroll
            for (int s = 0; s < 4; ++s) cpasync16(sv + s * 16, kp + 64 + s * 8);
            CP_COMMIT();
            CP_WAIT1();
        } else {
            CP_WAIT0();
        }
        __syncthreads();

        const uint32_t ksB = sB + KV_OFF + (tI & 1) * KV_STG;
        const uint32_t vsB = ksB + 18432;

        // ---- S = Q K^T for both m-halves under ONE K read ----
        uint32_t sch[2][16][2];
        #pragma unroll
        for (int mh = 0; mh < 2; ++mh)
            #pragma unroll
            for (int nt = 0; nt < 16; ++nt) {
                sch[mh][nt][0] = 0u; sch[mh][nt][1] = 0u;
            }
        #pragma unroll
        for (int nt2 = 0; nt2 < 8; ++nt2) {
            #pragma unroll
            for (int ks = 0; ks < 4; ++ks) {
                uint32_t bf[4];
                const uint32_t addr = ksB
                    + (uint32_t)(nt2 * 16 + (lane & 7) + ((lane >> 4) & 1) * 8) * ASTRB
                    + (uint32_t)(ks * 16 + ((lane >> 3) & 1) * 8) * 2;
                ldm4(bf, addr);
                #pragma unroll
                for (int mh = 0; mh < 2; ++mh) {
                    mma_f16_hacc(sch[mh][2 * nt2],     qf[mh][ks], bf[0], bf[1]);
                    mma_f16_hacc(sch[mh][2 * nt2 + 1], qf[mh][ks], bf[2], bf[3]);
                }
            }
        }

        // ---- online softmax in h2, exp in place ----
        #pragma unroll
        for (int mh = 0; mh < 2; ++mh) {
            float alpha[2];
            #pragma unroll
            for (int r = 0; r < 2; ++r) {
                __half2 m2 = *(__half2*)&sch[mh][0][r];
                #pragma unroll
                for (int nt = 1; nt < 16; ++nt)
                    m2 = __hmax2(m2, *(__half2*)&sch[mh][nt][r]);
                float mx = fmaxf(__low2float(m2), __high2float(m2));
                mx = fmaxf(mx, __shfl_xor_sync(0xffffffffu, mx, 1));
                mx = fmaxf(mx, __shfl_xor_sync(0xffffffffu, mx, 2));
                const float mn = fmaxf(mrow[mh][r], mx);
                alpha[r] = __expf((mrow[mh][r] - mn) * 0.125f);
                mrow[mh][r] = mn;
                const __half2 c2h = __float2half2_rn(-mn * K1);
                __half2 s2 = __float2half2_rn(0.f);
                #pragma unroll
                for (int nt = 0; nt < 16; ++nt) {
                    __half2 arg = __hfma2(*(__half2*)&sch[mh][nt][r], k1h, c2h);
                    const uint32_t pe = ex2_h2(*(uint32_t*)&arg);
                    sch[mh][nt][r] = pe;
                    s2 = __hadd2(s2, *(const __half2*)&pe);
                }
                const float2 f2 = __half22float2(s2);
                float rs = f2.x + f2.y;
                rs += __shfl_xor_sync(0xffffffffu, rs, 1);
                rs += __shfl_xor_sync(0xffffffffu, rs, 2);
                lsum[mh][r] = lsum[mh][r] * alpha[r] + rs;
            }
            #pragma unroll
            for (int dt = 0; dt < 8; ++dt) {
                oc[mh][dt][0] *= alpha[0]; oc[mh][dt][1] *= alpha[0];
                oc[mh][dt][2] *= alpha[1]; oc[mh][dt][3] *= alpha[1];
            }
        }

        // ---- O += P V for both m-halves under ONE V read ----
        #pragma unroll
        for (int ks = 0; ks < 8; ++ks) {
            #pragma unroll
            for (int dt2 = 0; dt2 < 4; ++dt2) {
                uint32_t bv[4];
                const uint32_t addr = vsB
                    + (uint32_t)(ks * 16 + (lane & 7) + ((lane >> 3) & 1) * 8) * ASTRB
                    + (uint32_t)(dt2 * 16 + ((lane >> 4) & 1) * 8) * 2;
                ldm4t(bv, addr);
                #pragma unroll
                for (int mh = 0; mh < 2; ++mh) {
                    const uint32_t pa[4] = {sch[mh][2 * ks][0], sch[mh][2 * ks][1],
                                            sch[mh][2 * ks + 1][0], sch[mh][2 * ks + 1][1]};
                    mma_f16(oc[mh][2 * dt2],     pa, bv[0], bv[1]);
                    mma_f16(oc[mh][2 * dt2 + 1], pa, bv[2], bv[3]);
                }
            }
        }
        __syncthreads();
    }

    // ---- normalize + write fp16 ----
    #pragma unroll
    for (int mh = 0; mh < 2; ++mh)
        #pragma unroll
        for (int r = 0; r < 2; ++r) {
            const float inv = 1.0f / lsum[mh][r];
            const int row = q0 + w * 32 + mh * 16 + g + r * 8;
            const size_t base = (size_t)(b * SEQ + row) * DMODEL + h * HD + t * 2;
            #pragma unroll
            for (int dt = 0; dt < 8; ++dt) {
                *(uint32_t*)(oh + base + dt * 8) =
                    pack_h2(oc[mh][dt][2 * r] * inv, oc[mh][dt][2 * r + 1] * inv);
            }
        }
}

// ==================== launch ====================
extern "C" void kernel_launch(void* const* d_in, const int* in_sizes, int n_in,
                              void* d_out, int out_size)
{
    (void)in_sizes; (void)n_in; (void)out_size;
    const float* x    = (const float*)d_in[0];
    const float* g1   = (const float*)d_in[1];
    const float* b1   = (const float*)d_in[2];
    const float* Wqkv = (const float*)d_in[3];
    const float* bqkv = (const float*)d_in[4];
    const float* Wo   = (const float*)d_in[5];
    const float* bo   = (const float*)d_in[6];
    const float* g2   = (const float*)d_in[7];
    const float* b2   = (const float*)d_in[8];
    const float* W1   = (const float*)d_in[9];
    const float* b1m  = (const float*)d_in[10];
    const float* W2   = (const float*)d_in[11];
    const float* b2m  = (const float*)d_in[12];
    float* out = (float*)d_out;

    float* x1;
    __half *qkvh, *hh, *ah, *fh, *wh;
    cudaGetSymbolAddress((void**)&x1,   g_x1);
    cudaGetSymbolAddress((void**)&qkvh, g_qkvh);
    cudaGetSymbolAddress((void**)&hh,   g_hh);
    cudaGetSymbolAddress((void**)&ah,   g_ah);
    cudaGetSymbolAddress((void**)&fh,   g_fh);
    cudaGetSymbolAddress((void**)&wh,   g_wh);

    cudaFuncSetAttribute(gemm_mma<false, false, true>,
                         cudaFuncAttributeMaxDynamicSharedMemorySize, GEMM_SMEM);
    cudaFuncSetAttribute(gemm_mma<false, true, false>,
                         cudaFuncAttributeMaxDynamicSharedMemorySize, GEMM_SMEM);
    cudaFuncSetAttribute(gemm_mma<true, false, true>,
                         cudaFuncAttributeMaxDynamicSharedMemorySize, GEMM_SMEM);
    cudaFuncSetAttribute(attn_mma,
                         cudaFuncAttributeMaxDynamicSharedMemorySize, ATTN_SMEM);

    // 0) weight prep (fp16 convert)
    conv_kernel<<<(3 * DMODEL * DMODEL / 4 + 255) / 256, 256>>>(
        (const float4*)Wqkv, (uint2*)(wh + WQKV_OFF), 3 * DMODEL * DMODEL / 4);
    conv_kernel<<<(DMODEL * DMODEL / 4 + 255) / 256, 256>>>(
        (const float4*)Wo, (uint2*)(wh + WO_OFF), DMODEL * DMODEL / 4);
    conv_kernel<<<(FFD * DMODEL / 4 + 255) / 256, 256>>>(
        (const float4*)W1, (uint2*)(wh + W1_OFF), FFD * DMODEL / 4);
    conv_kernel<<<(DMODEL * FFD / 4 + 255) / 256, 256>>>(
        (const float4*)W2, (uint2*)(wh + W2_OFF), DMODEL * FFD / 4);

    // 1) h = LN1(x)
    ln_kernel<<<TOK, 256>>>(x, g1, b1, hh);
    // 2) qkv = h @ Wqkv^T + bqkv (fp16 out)
    gemm_mma<false, false, true><<<dim3(3 * DMODEL / 128, TOK / 128), 256, GEMM_SMEM>>>(
        hh, wh + WQKV_OFF, bqkv, nullptr,
        nullptr, qkvh, TOK, 3 * DMODEL, DMODEL);
    // 3) attention
    attn_mma<<<dim3(SEQ / AQ, NH, NB), 256, ATTN_SMEM>>>(qkvh, ah);
    // 4) x1 = x + att @ Wo^T + bo (fp32 out)
    gemm_mma<false, true, false><<<dim3(DMODEL / 128, TOK / 128), 256, GEMM_SMEM>>>(
        ah, wh + WO_OFF, bo, x,
        x1, nullptr, TOK, DMODEL, DMODEL);
    // 5) h = LN2(x1)
    ln_kernel<<<TOK, 256>>>(x1, g2, b2, hh);
    // 6) ffh = gelu(h @ W1^T + b1m) (fp16 out)
    gemm_mma<true, false, true><<<dim3(FFD / 128, TOK / 128), 256, GEMM_SMEM>>>(
        hh, wh + W1_OFF, b1m, nullptr,
        nullptr, fh, TOK, FFD, DMODEL);
    // 7) out = x1 + ffh @ W2^T + b2m (fp32 out)
    gemm_mma<false, true, false><<<dim3(DMODEL / 128, TOK / 128), 256, GEMM_SMEM>>>(
        fh, wh + W2_OFF, b2m, x1,
        out, nullptr, TOK, DMODEL, FFD);
}

// round 12
// speedup vs baseline: 6.2478x; 1.0272x over previous
#include <cuda_runtime.h>
#include <cuda_fp16.h>
#include <stdint.h>
#include <math.h>

// ---------------- problem constants ----------------
#define NB     2
#define SEQ    2048
#define TOK    4096
#define DMODEL 1024
#define NH     16
#define HD     64
#define FFD    4096
#define LN_EPS 1e-5f

// ---------------- scratch (device globals; no allocation) ----------------
__device__ float  g_x1 [TOK * DMODEL];          // post-attn residual (fp32)
__device__ __half g_qkvh[TOK * 3 * DMODEL];     // QKV (fp16)
__device__ __half g_hh [TOK * DMODEL];          // LN output (fp16)
__device__ __half g_ah [TOK * DMODEL];          // attention output (fp16)
__device__ __half g_fh [TOK * FFD];             // MLP hidden (fp16)
#define WTOT (12 * 1024 * 1024)
__device__ __half g_wh[WTOT];                   // all weights fp16

#define WQKV_OFF 0
#define WO_OFF   3145728
#define W1_OFF   4194304
#define W2_OFF   8388608

// ==================== helpers ====================
static __device__ __forceinline__ uint32_t smem_u32(const void* p) {
    uint32_t a;
    asm("{ .reg .u64 t; cvta.to.shared.u64 t, %1; cvt.u32.u64 %0, t; }"
        : "=r"(a) : "l"(p));
    return a;
}

static __device__ __forceinline__ void cpasync16(uint32_t s, const void* g) {
    asm volatile(
        "{ .reg .u64 p; cvta.to.global.u64 p, %1; "
        "cp.async.cg.shared.global [%0], [p], 16; }"
        :: "r"(s), "l"(g) : "memory");
}
#define CP_COMMIT() asm volatile("cp.async.commit_group;" ::: "memory")
#define CP_WAIT1()  asm volatile("cp.async.wait_group 1;" ::: "memory")
#define CP_WAIT0()  asm volatile("cp.async.wait_group 0;" ::: "memory")

static __device__ __forceinline__ void ldm4(uint32_t* r, uint32_t addr) {
    asm volatile("ldmatrix.sync.aligned.m8n8.x4.shared.b16 {%0,%1,%2,%3}, [%4];"
        : "=r"(r[0]), "=r"(r[1]), "=r"(r[2]), "=r"(r[3]) : "r"(addr));
}
static __device__ __forceinline__ void ldm4t(uint32_t* r, uint32_t addr) {
    asm volatile("ldmatrix.sync.aligned.m8n8.x4.trans.shared.b16 {%0,%1,%2,%3}, [%4];"
        : "=r"(r[0]), "=r"(r[1]), "=r"(r[2]), "=r"(r[3]) : "r"(addr));
}

static __device__ __forceinline__ void mma_f16(float* c, const uint32_t* a,
                                               uint32_t b0, uint32_t b1) {
    asm volatile(
        "mma.sync.aligned.m16n8k16.row.col.f32.f16.f16.f32 "
        "{%0,%1,%2,%3}, {%4,%5,%6,%7}, {%8,%9}, {%0,%1,%2,%3};"
        : "+f"(c[0]), "+f"(c[1]), "+f"(c[2]), "+f"(c[3])
        : "r"(a[0]), "r"(a[1]), "r"(a[2]), "r"(a[3]), "r"(b0), "r"(b1));
}

// fp16-accumulated variant: D/C are 2 f16x2 regs (rows g / g+8, cols 2t,2t+1)
static __device__ __forceinline__ void mma_f16_hacc(uint32_t* c, const uint32_t* a,
                                                    uint32_t b0, uint32_t b1) {
    asm volatile(
        "mma.sync.aligned.m16n8k16.row.col.f16.f16.f16.f16 "
        "{%0,%1}, {%2,%3,%4,%5}, {%6,%7}, {%0,%1};"
        : "+r"(c[0]), "+r"(c[1])
        : "r"(a[0]), "r"(a[1]), "r"(a[2]), "r"(a[3]), "r"(b0), "r"(b1));
}

// pack two fp32 -> f16x2 register (first arg -> low half)
static __device__ __forceinline__ uint32_t pack_h2(float lo, float hi) {
    uint32_t r;
    asm("cvt.rn.f16x2.f32 %0, %1, %2;" : "=r"(r) : "f"(hi), "f"(lo));
    return r;
}
static __device__ __forceinline__ uint32_t ex2_h2(uint32_t x) {
    uint32_t r;
    asm("ex2.approx.f16x2 %0, %1;" : "=r"(r) : "r"(x));
    return r;
}

// ==================== merged weight conversion (fp32 -> fp16, 4 regions) ====================
#define N4_QKV 786432
#define N4_WO  262144
#define N4_W1  1048576
#define N4_W2  1048576
#define N4_TOT (N4_QKV + N4_WO + N4_W1 + N4_W2)   // 3145728

__global__ __launch_bounds__(256) void conv4_kernel(
    const float4* __restrict__ w0, const float4* __restrict__ w1,
    const float4* __restrict__ w2, const float4* __restrict__ w3,
    uint2* __restrict__ o0, uint2* __restrict__ o1,
    uint2* __restrict__ o2, uint2* __restrict__ o3)
{
    int i = blockIdx.x * 256 + threadIdx.x;
    const float4* src; uint2* dst; int idx;
    if (i < N4_QKV)                  { src = w0; dst = o0; idx = i; }
    else if (i < N4_QKV + N4_WO)     { src = w1; dst = o1; idx = i - N4_QKV; }
    else if (i < N4_QKV + N4_WO + N4_W1)
                                     { src = w2; dst = o2; idx = i - N4_QKV - N4_WO; }
    else                             { src = w3; dst = o3; idx = i - N4_QKV - N4_WO - N4_W1; }
    const float4 v = src[idx];
    uint2 o;
    o.x = pack_h2(v.x, v.y);
    o.y = pack_h2(v.z, v.w);
    dst[idx] = o;
}

// ==================== LayerNorm -> fp16 ====================
__global__ __launch_bounds__(256) void ln_kernel(
    const float* __restrict__ x, const float* __restrict__ g,
    const float* __restrict__ b, __half* __restrict__ y)
{
    __shared__ float red[8];
    __shared__ float bc[2];
    const int r = blockIdx.x, tid = threadIdx.x;
    const int wid = tid >> 5, lane = tid & 31;

    const float4 v = ((const float4*)(x + (size_t)r * DMODEL))[tid];

    float s = v.x + v.y + v.z + v.w;
    #pragma unroll
    for (int o = 16; o; o >>= 1) s += __shfl_xor_sync(0xffffffffu, s, o);
    if (lane == 0) red[wid] = s;
    __syncthreads();
    if (tid == 0) {
        float t = 0.f;
        #pragma unroll
        for (int i = 0; i < 8; ++i) t += red[i];
        bc[0] = t * (1.0f / DMODEL);
    }
    __syncthreads();
    const float mean = bc[0];

    const float dx = v.x - mean, dy = v.y - mean, dz = v.z - mean, dw = v.w - mean;
    float ss = dx * dx + dy * dy + dz * dz + dw * dw;
    #pragma unroll
    for (int o = 16; o; o >>= 1) ss += __shfl_xor_sync(0xffffffffu, ss, o);
    if (lane == 0) red[wid] = ss;
    __syncthreads();
    if (tid == 0) {
        float t = 0.f;
        #pragma unroll
        for (int i = 0; i < 8; ++i) t += red[i];
        bc[1] = rsqrtf(t * (1.0f / DMODEL) + LN_EPS);
    }
    __syncthreads();
    const float rs = bc[1];

    const float4 gv = ((const float4*)g)[tid];
    const float4 bv = ((const float4*)b)[tid];
    uint2 o2;
    o2.x = pack_h2(dx * rs * gv.x + bv.x, dy * rs * gv.y + bv.y);
    o2.y = pack_h2(dz * rs * gv.z + bv.z, dw * rs * gv.w + bv.w);
    *(uint2*)(y + (size_t)r * DMODEL + tid * 4) = o2;
}

// ==================== mma.sync GEMM (NT, fp16, single term) ====================
// CTA tile 128x128, BK=64, 256 threads (8 warps 2x4), warp tile 64x32.
// 3-stage cp.async ring, ONE barrier per chunk (issue-after-sync ordering:
// writing stage (c+2)%3 is safe because the sync certifies compute of c-1,
// the last user of that buffer, has finished in every warp).
#define TILE_B   18432              // 128 * 144
#define STAGE_B  (2 * TILE_B)       // A + B  = 36864
#define GEMM_SMEM (3 * STAGE_B)     // 110592

static __device__ __forceinline__ void stage_load(
    uint32_t s0, const __half* gA, const __half* gB,
    int m0, int n0, int K, int kt, int tid)
{
    #pragma unroll
    for (int q = 0; q < 4; ++q) {
        const int u   = tid + q * 256;        // 0..1023
        const int row = u >> 3;
        const int seg = u & 7;
        const uint32_t soff = row * 144 + seg * 16;
        const size_t ga = (size_t)(m0 + row) * K + kt + seg * 8;
        const size_t gb = (size_t)(n0 + row) * K + kt + seg * 8;
        cpasync16(s0 +          soff, gA + ga);
        cpasync16(s0 + TILE_B + soff, gB + gb);
    }
}

template<bool GELU_F, bool RES_F, bool OUTH_F>
__global__ __launch_bounds__(256, 2)
void gemm_mma(
    const __half* __restrict__ A, const __half* __restrict__ B,
    const float* __restrict__ bias, const float* __restrict__ res,
    float* __restrict__ Cf, __half* __restrict__ Ch,
    int M, int N, int K)
{
    extern __shared__ char dsm[];
    const uint32_t sb = smem_u32(dsm);

    const int tid  = threadIdx.x;
    const int wid  = tid >> 5, lane = tid & 31;
    const int wm   = wid & 1;
    const int wn   = wid >> 1;
    const int m0   = blockIdx.y << 7;
    const int n0   = blockIdx.x << 7;

    float acc[4][4][4];
    #pragma unroll
    for (int i = 0; i < 4; ++i)
        #pragma unroll
        for (int j = 0; j < 4; ++j) {
            acc[i][j][0] = 0.f; acc[i][j][1] = 0.f;
            acc[i][j][2] = 0.f; acc[i][j][3] = 0.f;
        }

    const int lr   = lane & 15;
    const int cof  = (lane >> 4) << 3;
    const uint32_t aRowByte = (uint32_t)(wm * 64 + lr) * 144;
    const uint32_t bRowByte = (uint32_t)(wn * 32 + lr) * 144;

    const int NC = K >> 6;

    stage_load(sb,           A, B, m0, n0, K, 0,  tid);
    CP_COMMIT();
    stage_load(sb + STAGE_B, A, B, m0, n0, K, 64, tid);
    CP_COMMIT();

    for (int c = 0; c < NC; ++c) {
        CP_WAIT1();          // commits = c+2 so far; <=1 in flight -> stage c done
        __syncthreads();     // data visible cross-thread; compute of c-1 finished
        if (c + 2 < NC)
            stage_load(sb + ((c + 2) % 3) * STAGE_B, A, B,
                       m0, n0, K, (c + 2) << 6, tid);
        CP_COMMIT();         // uniform commit (possibly empty at tail)

        const uint32_t s0 = sb + (c % 3) * STAGE_B;
        const uint32_t aA = s0;
        const uint32_t aB = s0 + TILE_B;

        #pragma unroll
        for (int ks = 0; ks < 4; ++ks) {
            const uint32_t kbyte = (uint32_t)(ks * 16 + cof) * 2;

            uint32_t af[4][4];
            #pragma unroll
            for (int mi = 0; mi < 4; ++mi)
                ldm4(af[mi], aA + aRowByte + (uint32_t)(mi * 16) * 144 + kbyte);

            uint32_t bf[2][4];
            #pragma unroll
            for (int nt = 0; nt < 2; ++nt)
                ldm4(bf[nt], aB + bRowByte + (uint32_t)(nt * 16) * 144 + kbyte);

            #pragma unroll
            for (int mi = 0; mi < 4; ++mi)
                #pragma unroll
                for (int ni = 0; ni < 4; ++ni)
                    mma_f16(acc[mi][ni], af[mi],
                            bf[ni >> 1][ni & 1], bf[ni >> 1][2 + (ni & 1)]);
        }
    }

    const int tr = lane >> 2;
    const int tc = (lane & 3) << 1;
    #pragma unroll
    for (int mi = 0; mi < 4; ++mi) {
        #pragma unroll
        for (int ni = 0; ni < 4; ++ni) {
            const int col = n0 + wn * 32 + ni * 8 + tc;
            #pragma unroll
            for (int half_ = 0; half_ < 2; ++half_) {
                const int row = m0 + wm * 64 + mi * 16 + tr + half_ * 8;
                float vx = acc[mi][ni][half_ * 2 + 0] + bias[col + 0];
                float vy = acc[mi][ni][half_ * 2 + 1] + bias[col + 1];
                if (RES_F) {
                    const float2 rv = *(const float2*)&res[(size_t)row * N + col];
                    vx += rv.x; vy += rv.y;
                }
                if (GELU_F) {
                    vx = 0.5f * vx * (1.0f + erff(vx * 0.70710678f));
                    vy = 0.5f * vy * (1.0f + erff(vy * 0.70710678f));
                }
                const size_t off = (size_t)row * N + col;
                if (OUTH_F) {
                    *(uint32_t*)(Ch + off) = pack_h2(vx, vy);
                } else {
                    float2 o; o.x = vx; o.y = vy;
                    *(float2*)&Cf[off] = o;
                }
            }
        }
    }
}

// ==================== Tensor-core flash attention ====================
// fp16-acc S, in-place exp, zero-copy P, 32 q-rows/warp.
// 3-stage KV ring with ONE barrier per tile (same issue-after-sync argument).
// CTA: 256 q-rows, 8 warps, 1 CTA/SM. grid (SEQ/256, NH, NB).
#define AQ    256
#define AKV   128
#define ASTRB 144
#define Q_OFF 0
#define Q_BYTES (256 * ASTRB)             // 36864
#define KV_OFF  Q_BYTES
#define KV_STG  36864                     // K tile + V tile
#define ATTN_SMEM (KV_OFF + 3 * KV_STG)   // 147456

__global__ __launch_bounds__(256, 1) void attn_mma(
    const __half* __restrict__ qkv, __half* __restrict__ oh)
{
    extern __shared__ char asm_[];
    const uint32_t sB = smem_u32(asm_);

    const int tid = threadIdx.x;
    const int w = tid >> 5, lane = tid & 31;
    const int g = lane >> 2, t = lane & 3;
    const int b = blockIdx.z, h = blockIdx.y;
    const int q0 = blockIdx.x * AQ;

    const int lrow = tid >> 1;        // 0..127 (KV load row)
    const int lhf  = tid & 1;

    const __half* tokbase = qkv + (size_t)(b * SEQ) * (3 * DMODEL) + h * 192;

    // KV tile loader (tile index -> ring stage)
    auto load_kv = [&](int tile, int stg) {
        const __half* kp = tokbase + (size_t)(tile * AKV + lrow) * (3 * DMODEL) + 64 + lhf * 32;
        const uint32_t sk = sB + KV_OFF + (uint32_t)stg * KV_STG + lrow * ASTRB + lhf * 64;
        #pragma unroll
        for (int s = 0; s < 4; ++s) cpasync16(sk + s * 16, kp + s * 8);
        const uint32_t sv = sk + 18432;
        #pragma unroll
        for (int s = 0; s < 4; ++s) cpasync16(sv + s * 16, kp + 64 + s * 8);
    };

    // ---- stage Q (256 rows, one thread per row) ----
    {
        const __half* qp = tokbase + (size_t)(q0 + tid) * (3 * DMODEL);
        const uint32_t sq = sB + Q_OFF + tid * ASTRB;
        #pragma unroll
        for (int s = 0; s < 8; ++s)
            cpasync16(sq + s * 16, qp + s * 8);
    }
    CP_COMMIT();
    CP_WAIT0();
    __syncthreads();

    // qf[mh][ks][4]: two m16 groups per warp
    uint32_t qf[2][4][4];
    #pragma unroll
    for (int mh = 0; mh < 2; ++mh) {
        const uint32_t rb = sB + Q_OFF
            + (uint32_t)(w * 32 + mh * 16 + (lane & 15)) * ASTRB
            + (uint32_t)(((lane >> 4) & 1) * 8) * 2;
        #pragma unroll
        for (int ks = 0; ks < 4; ++ks)
            ldm4(qf[mh][ks], rb + ks * 32);
    }

    float oc[2][8][4];
    #pragma unroll
    for (int mh = 0; mh < 2; ++mh)
        #pragma unroll
        for (int i = 0; i < 8; ++i) {
            oc[mh][i][0] = 0.f; oc[mh][i][1] = 0.f;
            oc[mh][i][2] = 0.f; oc[mh][i][3] = 0.f;
        }
    float mrow[2][2] = {{-INFINITY, -INFINITY}, {-INFINITY, -INFINITY}};
    float lsum[2][2] = {{0.f, 0.f}, {0.f, 0.f}};

    const int NT = SEQ / AKV;   // 16
    const float K1 = 0.125f * 1.4426950408889634f;   // log2(e)/8
    const __half2 k1h = __float2half2_rn(K1);

    // prefetch KV tiles 0, 1
    load_kv(0, 0); CP_COMMIT();
    load_kv(1, 1); CP_COMMIT();

    for (int tI = 0; tI < NT; ++tI) {
        CP_WAIT1();          // tile tI complete
        __syncthreads();     // visibility + compute of tI-1 done in all warps
        if (tI + 2 < NT)
            load_kv(tI + 2, (tI + 2) % 3);
        CP_COMMIT();         // uniform

        const uint32_t ksB = sB + KV_OFF + (uint32_t)(tI % 3) * KV_STG;
        const uint32_t vsB = ksB + 18432;

        // ---- S = Q K^T for both m-halves under ONE K read ----
        uint32_t sch[2][16][2];
        #pragma unroll
        for (int mh = 0; mh < 2; ++mh)
            #pragma unroll
            for (int nt = 0; nt < 16; ++nt) {
                sch[mh][nt][0] = 0u; sch[mh][nt][1] = 0u;
            }
        #pragma unroll
        for (int nt2 = 0; nt2 < 8; ++nt2) {
            #pragma unroll
            for (int ks = 0; ks < 4; ++ks) {
                uint32_t bf[4];
                const uint32_t addr = ksB
                    + (uint32_t)(nt2 * 16 + (lane & 7) + ((lane >> 4) & 1) * 8) * ASTRB
                    + (uint32_t)(ks * 16 + ((lane >> 3) & 1) * 8) * 2;
                ldm4(bf, addr);
                #pragma unroll
                for (int mh = 0; mh < 2; ++mh) {
                    mma_f16_hacc(sch[mh][2 * nt2],     qf[mh][ks], bf[0], bf[1]);
                    mma_f16_hacc(sch[mh][2 * nt2 + 1], qf[mh][ks], bf[2], bf[3]);
                }
            }
        }

        // ---- online softmax in h2, exp in place ----
        #pragma unroll
        for (int mh = 0; mh < 2; ++mh) {
            float alpha[2];
            #pragma unroll
            for (int r = 0; r < 2; ++r) {
                __half2 m2 = *(__half2*)&sch[mh][0][r];
                #pragma unroll
                for (int nt = 1; nt < 16; ++nt)
                    m2 = __hmax2(m2, *(__half2*)&sch[mh][nt][r]);
                float mx = fmaxf(__low2float(m2), __high2float(m2));
                mx = fmaxf(mx, __shfl_xor_sync(0xffffffffu, mx, 1));
                mx = fmaxf(mx, __shfl_xor_sync(0xffffffffu, mx, 2));
                const float mn = fmaxf(mrow[mh][r], mx);
                alpha[r] = __expf((mrow[mh][r] - mn) * 0.125f);
                mrow[mh][r] = mn;
                const __half2 c2h = __float2half2_rn(-mn * K1);
                __half2 s2 = __float2half2_rn(0.f);
                #pragma unroll
                for (int nt = 0; nt < 16; ++nt) {
                    __half2 arg = __hfma2(*(__half2*)&sch[mh][nt][r], k1h, c2h);
                    const uint32_t pe = ex2_h2(*(uint32_t*)&arg);
                    sch[mh][nt][r] = pe;
                    s2 = __hadd2(s2, *(const __half2*)&pe);
                }
                const float2 f2 = __half22float2(s2);
                float rs = f2.x + f2.y;
                rs += __shfl_xor_sync(0xffffffffu, rs, 1);
                rs += __shfl_xor_sync(0xffffffffu, rs, 2);
                lsum[mh][r] = lsum[mh][r] * alpha[r] + rs;
            }
            #pragma unroll
            for (int dt = 0; dt < 8; ++dt) {
                oc[mh][dt][0] *= alpha[0]; oc[mh][dt][1] *= alpha[0];
                oc[mh][dt][2] *= alpha[1]; oc[mh][dt][3] *= alpha[1];
            }
        }

        // ---- O += P V for both m-halves under ONE V read ----
        #pragma unroll
        for (int ks = 0; ks < 8; ++ks) {
            #pragma unroll
            for (int dt2 = 0; dt2 < 4; ++dt2) {
                uint32_t bv[4];
                const uint32_t addr = vsB
                    + (uint32_t)(ks * 16 + (lane & 7) + ((lane >> 3) & 1) * 8) * ASTRB
                    + (uint32_t)(dt2 * 16 + ((lane >> 4) & 1) * 8) * 2;
                ldm4t(bv, addr);
                #pragma unroll
                for (int mh = 0; mh < 2; ++mh) {
                    const uint32_t pa[4] = {sch[mh][2 * ks][0], sch[mh][2 * ks][1],
                                            sch[mh][2 * ks + 1][0], sch[mh][2 * ks + 1][1]};
                    mma_f16(oc[mh][2 * dt2],     pa, bv[0], bv[1]);
                    mma_f16(oc[mh][2 * dt2 + 1], pa, bv[2], bv[3]);
                }
            }
        }
    }

    // ---- normalize + write fp16 ----
    #pragma unroll
    for (int mh = 0; mh < 2; ++mh)
        #pragma unroll
        for (int r = 0; r < 2; ++r) {
            const float inv = 1.0f / lsum[mh][r];
            const int row = q0 + w * 32 + mh * 16 + g + r * 8;
            const size_t base = (size_t)(b * SEQ + row) * DMODEL + h * HD + t * 2;
            #pragma unroll
            for (int dt = 0; dt < 8; ++dt) {
                *(uint32_t*)(oh + base + dt * 8) =
                    pack_h2(oc[mh][dt][2 * r] * inv, oc[mh][dt][2 * r + 1] * inv);
            }
        }
}

// ==================== launch ====================
extern "C" void kernel_launch(void* const* d_in, const int* in_sizes, int n_in,
                              void* d_out, int out_size)
{
    (void)in_sizes; (void)n_in; (void)out_size;
    const float* x    = (const float*)d_in[0];
    const float* g1   = (const float*)d_in[1];
    const float* b1   = (const float*)d_in[2];
    const float* Wqkv = (const float*)d_in[3];
    const float* bqkv = (const float*)d_in[4];
    const float* Wo   = (const float*)d_in[5];
    const float* bo   = (const float*)d_in[6];
    const float* g2   = (const float*)d_in[7];
    const float* b2   = (const float*)d_in[8];
    const float* W1   = (const float*)d_in[9];
    const float* b1m  = (const float*)d_in[10];
    const float* W2   = (const float*)d_in[11];
    const float* b2m  = (const float*)d_in[12];
    float* out = (float*)d_out;

    float* x1;
    __half *qkvh, *hh, *ah, *fh, *wh;
    cudaGetSymbolAddress((void**)&x1,   g_x1);
    cudaGetSymbolAddress((void**)&qkvh, g_qkvh);
    cudaGetSymbolAddress((void**)&hh,   g_hh);
    cudaGetSymbolAddress((void**)&ah,   g_ah);
    cudaGetSymbolAddress((void**)&fh,   g_fh);
    cudaGetSymbolAddress((void**)&wh,   g_wh);

    cudaFuncSetAttribute(gemm_mma<false, false, true>,
                         cudaFuncAttributeMaxDynamicSharedMemorySize, GEMM_SMEM);
    cudaFuncSetAttribute(gemm_mma<false, true, false>,
                         cudaFuncAttributeMaxDynamicSharedMemorySize, GEMM_SMEM);
    cudaFuncSetAttribute(gemm_mma<true, false, true>,
                         cudaFuncAttributeMaxDynamicSharedMemorySize, GEMM_SMEM);
    cudaFuncSetAttribute(attn_mma,
                         cudaFuncAttributeMaxDynamicSharedMemorySize, ATTN_SMEM);

    // 0) weight prep (single merged fp16 convert)
    conv4_kernel<<<N4_TOT / 256, 256>>>(
        (const float4*)Wqkv, (const float4*)Wo, (const float4*)W1, (const float4*)W2,
        (uint2*)(wh + WQKV_OFF), (uint2*)(wh + WO_OFF),
        (uint2*)(wh + W1_OFF),   (uint2*)(wh + W2_OFF));

    // 1) h = LN1(x)
    ln_kernel<<<TOK, 256>>>(x, g1, b1, hh);
    // 2) qkv = h @ Wqkv^T + bqkv (fp16 out)
    gemm_mma<false, false, true><<<dim3(3 * DMODEL / 128, TOK / 128), 256, GEMM_SMEM>>>(
        hh, wh + WQKV_OFF, bqkv, nullptr,
        nullptr, qkvh, TOK, 3 * DMODEL, DMODEL);
    // 3) attention
    attn_mma<<<dim3(SEQ / AQ, NH, NB), 256, ATTN_SMEM>>>(qkvh, ah);
    // 4) x1 = x + att @ Wo^T + bo (fp32 out)
    gemm_mma<false, true, false><<<dim3(DMODEL / 128, TOK / 128), 256, GEMM_SMEM>>>(
        ah, wh + WO_OFF, bo, x,
        x1, nullptr, TOK, DMODEL, DMODEL);
    // 5) h = LN2(x1)
    ln_kernel<<<TOK, 256>>>(x1, g2, b2, hh);
    // 6) ffh = gelu(h @ W1^T + b1m) (fp16 out)
    gemm_mma<true, false, true><<<dim3(FFD / 128, TOK / 128), 256, GEMM_SMEM>>>(
        hh, wh + W1_OFF, b1m, nullptr,
        nullptr, fh, TOK, FFD, DMODEL);
    // 7) out = x1 + ffh @ W2^T + b2m (fp32 out)
    gemm_mma<false, true, false><<<dim3(DMODEL / 128, TOK / 128), 256, GEMM_SMEM>>>(
        fh, wh + W2_OFF, b2m, x1,
        out, nullptr, TOK, DMODEL, FFD);
}

// round 13
// speedup vs baseline: 6.3908x; 1.0229x over previous
#include <cuda_runtime.h>
#include <cuda_fp16.h>
#include <stdint.h>
#include <math.h>

// ---------------- problem constants ----------------
#define NB     2
#define SEQ    2048
#define TOK    4096
#define DMODEL 1024
#define NH     16
#define HD     64
#define FFD    4096
#define LN_EPS 1e-5f

// ---------------- scratch (device globals; no allocation) ----------------
__device__ float  g_x1 [TOK * DMODEL];          // post-attn residual (fp32)
__device__ __half g_qkvh[TOK * 3 * DMODEL];     // QKV (fp16)
__device__ __half g_hh [TOK * DMODEL];          // LN output (fp16)
__device__ __half g_ah [TOK * DMODEL];          // attention output (fp16)
__device__ __half g_fh [TOK * FFD];             // MLP hidden (fp16)
#define WTOT (12 * 1024 * 1024)
__device__ __half g_wh[WTOT];                   // all weights fp16

#define WQKV_OFF 0
#define WO_OFF   3145728
#define W1_OFF   4194304
#define W2_OFF   8388608

// ==================== helpers ====================
static __device__ __forceinline__ uint32_t smem_u32(const void* p) {
    uint32_t a;
    asm("{ .reg .u64 t; cvta.to.shared.u64 t, %1; cvt.u32.u64 %0, t; }"
        : "=r"(a) : "l"(p));
    return a;
}

static __device__ __forceinline__ void cpasync16(uint32_t s, const void* g) {
    asm volatile(
        "{ .reg .u64 p; cvta.to.global.u64 p, %1; "
        "cp.async.cg.shared.global [%0], [p], 16; }"
        :: "r"(s), "l"(g) : "memory");
}
#define CP_COMMIT() asm volatile("cp.async.commit_group;" ::: "memory")
#define CP_WAIT1()  asm volatile("cp.async.wait_group 1;" ::: "memory")
#define CP_WAIT0()  asm volatile("cp.async.wait_group 0;" ::: "memory")

static __device__ __forceinline__ void ldm4(uint32_t* r, uint32_t addr) {
    asm volatile("ldmatrix.sync.aligned.m8n8.x4.shared.b16 {%0,%1,%2,%3}, [%4];"
        : "=r"(r[0]), "=r"(r[1]), "=r"(r[2]), "=r"(r[3]) : "r"(addr));
}
static __device__ __forceinline__ void ldm4t(uint32_t* r, uint32_t addr) {
    asm volatile("ldmatrix.sync.aligned.m8n8.x4.trans.shared.b16 {%0,%1,%2,%3}, [%4];"
        : "=r"(r[0]), "=r"(r[1]), "=r"(r[2]), "=r"(r[3]) : "r"(addr));
}

static __device__ __forceinline__ void mma_f16(float* c, const uint32_t* a,
                                               uint32_t b0, uint32_t b1) {
    asm volatile(
        "mma.sync.aligned.m16n8k16.row.col.f32.f16.f16.f32 "
        "{%0,%1,%2,%3}, {%4,%5,%6,%7}, {%8,%9}, {%0,%1,%2,%3};"
        : "+f"(c[0]), "+f"(c[1]), "+f"(c[2]), "+f"(c[3])
        : "r"(a[0]), "r"(a[1]), "r"(a[2]), "r"(a[3]), "r"(b0), "r"(b1));
}

// fp16-accumulated variant: D/C are 2 f16x2 regs (rows g / g+8, cols 2t,2t+1)
static __device__ __forceinline__ void mma_f16_hacc(uint32_t* c, const uint32_t* a,
                                                    uint32_t b0, uint32_t b1) {
    asm volatile(
        "mma.sync.aligned.m16n8k16.row.col.f16.f16.f16.f16 "
        "{%0,%1}, {%2,%3,%4,%5}, {%6,%7}, {%0,%1};"
        : "+r"(c[0]), "+r"(c[1])
        : "r"(a[0]), "r"(a[1]), "r"(a[2]), "r"(a[3]), "r"(b0), "r"(b1));
}

// pack two fp32 -> f16x2 register (first arg -> low half)
static __device__ __forceinline__ uint32_t pack_h2(float lo, float hi) {
    uint32_t r;
    asm("cvt.rn.f16x2.f32 %0, %1, %2;" : "=r"(r) : "f"(hi), "f"(lo));
    return r;
}
static __device__ __forceinline__ uint32_t ex2_h2(uint32_t x) {
    uint32_t r;
    asm("ex2.approx.f16x2 %0, %1;" : "=r"(r) : "r"(x));
    return r;
}

// ==================== merged weight conversion (fp32 -> fp16, 4 regions) ====================
#define N4_QKV 786432
#define N4_WO  262144
#define N4_W1  1048576
#define N4_W2  1048576
#define N4_TOT (N4_QKV + N4_WO + N4_W1 + N4_W2)   // 3145728

__global__ __launch_bounds__(256) void conv4_kernel(
    const float4* __restrict__ w0, const float4* __restrict__ w1,
    const float4* __restrict__ w2, const float4* __restrict__ w3,
    uint2* __restrict__ o0, uint2* __restrict__ o1,
    uint2* __restrict__ o2, uint2* __restrict__ o3)
{
    int i = blockIdx.x * 256 + threadIdx.x;
    const float4* src; uint2* dst; int idx;
    if (i < N4_QKV)                  { src = w0; dst = o0; idx = i; }
    else if (i < N4_QKV + N4_WO)     { src = w1; dst = o1; idx = i - N4_QKV; }
    else if (i < N4_QKV + N4_WO + N4_W1)
                                     { src = w2; dst = o2; idx = i - N4_QKV - N4_WO; }
    else                             { src = w3; dst = o3; idx = i - N4_QKV - N4_WO - N4_W1; }
    const float4 v = src[idx];
    uint2 o;
    o.x = pack_h2(v.x, v.y);
    o.y = pack_h2(v.z, v.w);
    dst[idx] = o;
}

// ==================== LayerNorm -> fp16 ====================
__global__ __launch_bounds__(256) void ln_kernel(
    const float* __restrict__ x, const float* __restrict__ g,
    const float* __restrict__ b, __half* __restrict__ y)
{
    __shared__ float red[8];
    __shared__ float bc[2];
    const int r = blockIdx.x, tid = threadIdx.x;
    const int wid = tid >> 5, lane = tid & 31;

    const float4 v = ((const float4*)(x + (size_t)r * DMODEL))[tid];

    float s = v.x + v.y + v.z + v.w;
    #pragma unroll
    for (int o = 16; o; o >>= 1) s += __shfl_xor_sync(0xffffffffu, s, o);
    if (lane == 0) red[wid] = s;
    __syncthreads();
    if (tid == 0) {
        float t = 0.f;
        #pragma unroll
        for (int i = 0; i < 8; ++i) t += red[i];
        bc[0] = t * (1.0f / DMODEL);
    }
    __syncthreads();
    const float mean = bc[0];

    const float dx = v.x - mean, dy = v.y - mean, dz = v.z - mean, dw = v.w - mean;
    float ss = dx * dx + dy * dy + dz * dz + dw * dw;
    #pragma unroll
    for (int o = 16; o; o >>= 1) ss += __shfl_xor_sync(0xffffffffu, ss, o);
    if (lane == 0) red[wid] = ss;
    __syncthreads();
    if (tid == 0) {
        float t = 0.f;
        #pragma unroll
        for (int i = 0; i < 8; ++i) t += red[i];
        bc[1] = rsqrtf(t * (1.0f / DMODEL) + LN_EPS);
    }
    __syncthreads();
    const float rs = bc[1];

    const float4 gv = ((const float4*)g)[tid];
    const float4 bv = ((const float4*)b)[tid];
    uint2 o2;
    o2.x = pack_h2(dx * rs * gv.x + bv.x, dy * rs * gv.y + bv.y);
    o2.y = pack_h2(dz * rs * gv.z + bv.z, dw * rs * gv.w + bv.w);
    *(uint2*)(y + (size_t)r * DMODEL + tid * 4) = o2;
}

// ==================== mma.sync GEMM (NT, fp16, single term) ====================
// CTA tile 128x128, BK=64, 256 threads (8 warps 2x4), warp tile 64x32.
// 3-stage cp.async ring, ONE barrier per chunk.
#define TILE_B   18432              // 128 * 144
#define STAGE_B  (2 * TILE_B)       // A + B  = 36864
#define GEMM_SMEM (3 * STAGE_B)     // 110592

static __device__ __forceinline__ void stage_load(
    uint32_t s0, const __half* gA, const __half* gB,
    int m0, int n0, int K, int kt, int tid)
{
    #pragma unroll
    for (int q = 0; q < 4; ++q) {
        const int u   = tid + q * 256;        // 0..1023
        const int row = u >> 3;
        const int seg = u & 7;
        const uint32_t soff = row * 144 + seg * 16;
        const size_t ga = (size_t)(m0 + row) * K + kt + seg * 8;
        const size_t gb = (size_t)(n0 + row) * K + kt + seg * 8;
        cpasync16(s0 +          soff, gA + ga);
        cpasync16(s0 + TILE_B + soff, gB + gb);
    }
}

template<bool GELU_F, bool RES_F, bool OUTH_F>
__global__ __launch_bounds__(256, 2)
void gemm_mma(
    const __half* __restrict__ A, const __half* __restrict__ B,
    const float* __restrict__ bias, const float* __restrict__ res,
    float* __restrict__ Cf, __half* __restrict__ Ch,
    int M, int N, int K)
{
    extern __shared__ char dsm[];
    const uint32_t sb = smem_u32(dsm);

    const int tid  = threadIdx.x;
    const int wid  = tid >> 5, lane = tid & 31;
    const int wm   = wid & 1;
    const int wn   = wid >> 1;
    const int m0   = blockIdx.y << 7;
    const int n0   = blockIdx.x << 7;

    float acc[4][4][4];
    #pragma unroll
    for (int i = 0; i < 4; ++i)
        #pragma unroll
        for (int j = 0; j < 4; ++j) {
            acc[i][j][0] = 0.f; acc[i][j][1] = 0.f;
            acc[i][j][2] = 0.f; acc[i][j][3] = 0.f;
        }

    const int lr   = lane & 15;
    const int cof  = (lane >> 4) << 3;
    const uint32_t aRowByte = (uint32_t)(wm * 64 + lr) * 144;
    const uint32_t bRowByte = (uint32_t)(wn * 32 + lr) * 144;

    const int NC = K >> 6;

    stage_load(sb,           A, B, m0, n0, K, 0,  tid);
    CP_COMMIT();
    stage_load(sb + STAGE_B, A, B, m0, n0, K, 64, tid);
    CP_COMMIT();

    for (int c = 0; c < NC; ++c) {
        CP_WAIT1();
        __syncthreads();
        if (c + 2 < NC)
            stage_load(sb + ((c + 2) % 3) * STAGE_B, A, B,
                       m0, n0, K, (c + 2) << 6, tid);
        CP_COMMIT();

        const uint32_t s0 = sb + (c % 3) * STAGE_B;
        const uint32_t aA = s0;
        const uint32_t aB = s0 + TILE_B;

        #pragma unroll
        for (int ks = 0; ks < 4; ++ks) {
            const uint32_t kbyte = (uint32_t)(ks * 16 + cof) * 2;

            uint32_t af[4][4];
            #pragma unroll
            for (int mi = 0; mi < 4; ++mi)
                ldm4(af[mi], aA + aRowByte + (uint32_t)(mi * 16) * 144 + kbyte);

            uint32_t bf[2][4];
            #pragma unroll
            for (int nt = 0; nt < 2; ++nt)
                ldm4(bf[nt], aB + bRowByte + (uint32_t)(nt * 16) * 144 + kbyte);

            #pragma unroll
            for (int mi = 0; mi < 4; ++mi)
                #pragma unroll
                for (int ni = 0; ni < 4; ++ni)
                    mma_f16(acc[mi][ni], af[mi],
                            bf[ni >> 1][ni & 1], bf[ni >> 1][2 + (ni & 1)]);
        }
    }

    const int tr = lane >> 2;
    const int tc = (lane & 3) << 1;
    #pragma unroll
    for (int mi = 0; mi < 4; ++mi) {
        #pragma unroll
        for (int ni = 0; ni < 4; ++ni) {
            const int col = n0 + wn * 32 + ni * 8 + tc;
            #pragma unroll
            for (int half_ = 0; half_ < 2; ++half_) {
                const int row = m0 + wm * 64 + mi * 16 + tr + half_ * 8;
                float vx = acc[mi][ni][half_ * 2 + 0] + bias[col + 0];
                float vy = acc[mi][ni][half_ * 2 + 1] + bias[col + 1];
                if (RES_F) {
                    const float2 rv = *(const float2*)&res[(size_t)row * N + col];
                    vx += rv.x; vy += rv.y;
                }
                if (GELU_F) {
                    vx = 0.5f * vx * (1.0f + erff(vx * 0.70710678f));
                    vy = 0.5f * vy * (1.0f + erff(vy * 0.70710678f));
                }
                const size_t off = (size_t)row * N + col;
                if (OUTH_F) {
                    *(uint32_t*)(Ch + off) = pack_h2(vx, vy);
                } else {
                    float2 o; o.x = vx; o.y = vy;
                    *(float2*)&Cf[off] = o;
                }
            }
        }
    }
}

// ==================== Tensor-core flash attention ====================
// fp16-acc S AND O, in-place exp, zero-copy P, 32 q-rows/warp, AKV=64,
// 2-stage KV ring, one barrier per tile, 2 CTAs/SM (regs<=128, smem 73.7KB).
// grid (SEQ/256, NH, NB) = 256 CTAs -> all co-resident in ONE wave.
#define AQ    256
#define AKV   64
#define ASTRB 144
#define Q_OFF 0
#define Q_BYTES (256 * ASTRB)             // 36864
#define KV_OFF  Q_BYTES
#define KT_B    (64 * ASTRB)              // 9216 (one K tile)
#define KV_STG  (2 * KT_B)                // 18432 (K + V)
#define ATTN_SMEM (KV_OFF + 2 * KV_STG)   // 73728

__global__ __launch_bounds__(256, 2) void attn_mma(
    const __half* __restrict__ qkv, __half* __restrict__ oh)
{
    extern __shared__ char asm_[];
    const uint32_t sB = smem_u32(asm_);

    const int tid = threadIdx.x;
    const int w = tid >> 5, lane = tid & 31;
    const int g = lane >> 2, t = lane & 3;
    const int b = blockIdx.z, h = blockIdx.y;
    const int q0 = blockIdx.x * AQ;

    const __half* tokbase = qkv + (size_t)(b * SEQ) * (3 * DMODEL) + h * 192;

    // KV tile loader: 64 rows x (64 K + 64 V) halves; 2 segs per tensor per thread
    auto load_kv = [&](int tile, int stg) {
        const uint32_t s0 = sB + KV_OFF + (uint32_t)stg * KV_STG;
        #pragma unroll
        for (int q = 0; q < 2; ++q) {
            const int u   = tid + q * 256;  // 0..511
            const int row = u >> 3;
            const int seg = u & 7;
            const __half* gk = tokbase + (size_t)(tile * AKV + row) * (3 * DMODEL)
                             + 64 + seg * 8;
            const uint32_t soff = row * ASTRB + seg * 16;
            cpasync16(s0 +        soff, gk);
            cpasync16(s0 + KT_B + soff, gk + 64);
        }
    };

    // ---- stage Q (256 rows, one thread per row) ----
    {
        const __half* qp = tokbase + (size_t)(q0 + tid) * (3 * DMODEL);
        const uint32_t sq = sB + Q_OFF + tid * ASTRB;
        #pragma unroll
        for (int s = 0; s < 8; ++s)
            cpasync16(sq + s * 16, qp + s * 8);
    }
    CP_COMMIT();
    CP_WAIT0();
    __syncthreads();

    uint32_t qf[2][4][4];
    #pragma unroll
    for (int mh = 0; mh < 2; ++mh) {
        const uint32_t rb = sB + Q_OFF
            + (uint32_t)(w * 32 + mh * 16 + (lane & 15)) * ASTRB
            + (uint32_t)(((lane >> 4) & 1) * 8) * 2;
        #pragma unroll
        for (int ks = 0; ks < 4; ++ks)
            ldm4(qf[mh][ks], rb + ks * 32);
    }

    // O accumulators in fp16 (f16x2 per row-half r, 8 d-tiles, 2 m-halves)
    uint32_t oc[2][8][2];
    #pragma unroll
    for (int mh = 0; mh < 2; ++mh)
        #pragma unroll
        for (int i = 0; i < 8; ++i) { oc[mh][i][0] = 0u; oc[mh][i][1] = 0u; }
    float mrow[2][2] = {{-INFINITY, -INFINITY}, {-INFINITY, -INFINITY}};
    float lsum[2][2] = {{0.f, 0.f}, {0.f, 0.f}};

    const int NT = SEQ / AKV;   // 32
    const float K1 = 0.125f * 1.4426950408889634f;   // log2(e)/8
    const __half2 k1h = __float2half2_rn(K1);

    load_kv(0, 0);
    CP_COMMIT();

    for (int tI = 0; tI < NT; ++tI) {
        CP_WAIT0();          // stage tI loaded (issued one iteration ago)
        __syncthreads();     // visibility + compute of tI-1 done everywhere
        if (tI + 1 < NT) {
            load_kv(tI + 1, (tI + 1) & 1);   // buffer computed in tI-1: free
            CP_COMMIT();
        }

        const uint32_t ksB = sB + KV_OFF + (uint32_t)(tI & 1) * KV_STG;
        const uint32_t vsB = ksB + KT_B;

        // ---- S = Q K^T (64 kv cols = 4 n16 blocks), both m-halves per K read ----
        uint32_t sch[2][8][2];
        #pragma unroll
        for (int mh = 0; mh < 2; ++mh)
            #pragma unroll
            for (int nt = 0; nt < 8; ++nt) { sch[mh][nt][0] = 0u; sch[mh][nt][1] = 0u; }
        #pragma unroll
        for (int nt2 = 0; nt2 < 4; ++nt2) {
            #pragma unroll
            for (int ks = 0; ks < 4; ++ks) {
                uint32_t bf[4];
                const uint32_t addr = ksB
                    + (uint32_t)(nt2 * 16 + (lane & 7) + ((lane >> 4) & 1) * 8) * ASTRB
                    + (uint32_t)(ks * 16 + ((lane >> 3) & 1) * 8) * 2;
                ldm4(bf, addr);
                #pragma unroll
                for (int mh = 0; mh < 2; ++mh) {
                    mma_f16_hacc(sch[mh][2 * nt2],     qf[mh][ks], bf[0], bf[1]);
                    mma_f16_hacc(sch[mh][2 * nt2 + 1], qf[mh][ks], bf[2], bf[3]);
                }
            }
        }

        // ---- online softmax in h2, exp in place ----
        #pragma unroll
        for (int mh = 0; mh < 2; ++mh) {
            #pragma unroll
            for (int r = 0; r < 2; ++r) {
                __half2 m2 = *(__half2*)&sch[mh][0][r];
                #pragma unroll
                for (int nt = 1; nt < 8; ++nt)
                    m2 = __hmax2(m2, *(__half2*)&sch[mh][nt][r]);
                float mx = fmaxf(__low2float(m2), __high2float(m2));
                mx = fmaxf(mx, __shfl_xor_sync(0xffffffffu, mx, 1));
                mx = fmaxf(mx, __shfl_xor_sync(0xffffffffu, mx, 2));
                const float mn = fmaxf(mrow[mh][r], mx);
                const float alpha = __expf((mrow[mh][r] - mn) * 0.125f);
                mrow[mh][r] = mn;
                const __half2 c2h = __float2half2_rn(-mn * K1);
                __half2 s2 = __float2half2_rn(0.f);
                #pragma unroll
                for (int nt = 0; nt < 8; ++nt) {
                    __half2 arg = __hfma2(*(__half2*)&sch[mh][nt][r], k1h, c2h);
                    const uint32_t pe = ex2_h2(*(uint32_t*)&arg);
                    sch[mh][nt][r] = pe;
                    s2 = __hadd2(s2, *(const __half2*)&pe);
                }
                const float2 f2 = __half22float2(s2);
                float rs = f2.x + f2.y;
                rs += __shfl_xor_sync(0xffffffffu, rs, 1);
                rs += __shfl_xor_sync(0xffffffffu, rs, 2);
                lsum[mh][r] = lsum[mh][r] * alpha + rs;
                // rescale fp16 O accumulators for this row-half
                const __half2 a2 = __float2half2_rn(alpha);
                #pragma unroll
                for (int dt = 0; dt < 8; ++dt) {
                    __half2 o2 = __hmul2(*(__half2*)&oc[mh][dt][r], a2);
                    oc[mh][dt][r] = *(uint32_t*)&o2;
                }
            }
        }

        // ---- O += P V (fp16 accumulate), both m-halves per V read ----
        #pragma unroll
        for (int ks = 0; ks < 4; ++ks) {
            #pragma unroll
            for (int dt2 = 0; dt2 < 4; ++dt2) {
                uint32_t bv[4];
                const uint32_t addr = vsB
                    + (uint32_t)(ks * 16 + (lane & 7) + ((lane >> 3) & 1) * 8) * ASTRB
                    + (uint32_t)(dt2 * 16 + ((lane >> 4) & 1) * 8) * 2;
                ldm4t(bv, addr);
                #pragma unroll
                for (int mh = 0; mh < 2; ++mh) {
                    const uint32_t pa[4] = {sch[mh][2 * ks][0], sch[mh][2 * ks][1],
                                            sch[mh][2 * ks + 1][0], sch[mh][2 * ks + 1][1]};
                    mma_f16_hacc(oc[mh][2 * dt2],     pa, bv[0], bv[1]);
                    mma_f16_hacc(oc[mh][2 * dt2 + 1], pa, bv[2], bv[3]);
                }
            }
        }
    }

    // ---- normalize + write fp16 ----
    #pragma unroll
    for (int mh = 0; mh < 2; ++mh)
        #pragma unroll
        for (int r = 0; r < 2; ++r) {
            const float inv = 1.0f / lsum[mh][r];
            const int row = q0 + w * 32 + mh * 16 + g + r * 8;
            const size_t base = (size_t)(b * SEQ + row) * DMODEL + h * HD + t * 2;
            #pragma unroll
            for (int dt = 0; dt < 8; ++dt) {
                const float2 f2 = __half22float2(*(__half2*)&oc[mh][dt][r]);
                *(uint32_t*)(oh + base + dt * 8) = pack_h2(f2.x * inv, f2.y * inv);
            }
        }
}

// ==================== launch ====================
extern "C" void kernel_launch(void* const* d_in, const int* in_sizes, int n_in,
                              void* d_out, int out_size)
{
    (void)in_sizes; (void)n_in; (void)out_size;
    const float* x    = (const float*)d_in[0];
    const float* g1   = (const float*)d_in[1];
    const float* b1   = (const float*)d_in[2];
    const float* Wqkv = (const float*)d_in[3];
    const float* bqkv = (const float*)d_in[4];
    const float* Wo   = (const float*)d_in[5];
    const float* bo   = (const float*)d_in[6];
    const float* g2   = (const float*)d_in[7];
    const float* b2   = (const float*)d_in[8];
    const float* W1   = (const float*)d_in[9];
    const float* b1m  = (const float*)d_in[10];
    const float* W2   = (const float*)d_in[11];
    const float* b2m  = (const float*)d_in[12];
    float* out = (float*)d_out;

    float* x1;
    __half *qkvh, *hh, *ah, *fh, *wh;
    cudaGetSymbolAddress((void**)&x1,   g_x1);
    cudaGetSymbolAddress((void**)&qkvh, g_qkvh);
    cudaGetSymbolAddress((void**)&hh,   g_hh);
    cudaGetSymbolAddress((void**)&ah,   g_ah);
    cudaGetSymbolAddress((void**)&fh,   g_fh);
    cudaGetSymbolAddress((void**)&wh,   g_wh);

    cudaFuncSetAttribute(gemm_mma<false, false, true>,
                         cudaFuncAttributeMaxDynamicSharedMemorySize, GEMM_SMEM);
    cudaFuncSetAttribute(gemm_mma<false, true, false>,
                         cudaFuncAttributeMaxDynamicSharedMemorySize, GEMM_SMEM);
    cudaFuncSetAttribute(gemm_mma<true, false, true>,
                         cudaFuncAttributeMaxDynamicSharedMemorySize, GEMM_SMEM);
    cudaFuncSetAttribute(attn_mma,
                         cudaFuncAttributeMaxDynamicSharedMemorySize, ATTN_SMEM);

    // 0) weight prep (single merged fp16 convert)
    conv4_kernel<<<N4_TOT / 256, 256>>>(
        (const float4*)Wqkv, (const float4*)Wo, (const float4*)W1, (const float4*)W2,
        (uint2*)(wh + WQKV_OFF), (uint2*)(wh + WO_OFF),
        (uint2*)(wh + W1_OFF),   (uint2*)(wh + W2_OFF));

    // 1) h = LN1(x)
    ln_kernel<<<TOK, 256>>>(x, g1, b1, hh);
    // 2) qkv = h @ Wqkv^T + bqkv (fp16 out)
    gemm_mma<false, false, true><<<dim3(3 * DMODEL / 128, TOK / 128), 256, GEMM_SMEM>>>(
        hh, wh + WQKV_OFF, bqkv, nullptr,
        nullptr, qkvh, TOK, 3 * DMODEL, DMODEL);
    // 3) attention
    attn_mma<<<dim3(SEQ / AQ, NH, NB), 256, ATTN_SMEM>>>(qkvh, ah);
    // 4) x1 = x + att @ Wo^T + bo (fp32 out)
    gemm_mma<false, true, false><<<dim3(DMODEL / 128, TOK / 128), 256, GEMM_SMEM>>>(
        ah, wh + WO_OFF, bo, x,
        x1, nullptr, TOK, DMODEL, DMODEL);
    // 5) h = LN2(x1)
    ln_kernel<<<TOK, 256>>>(x1, g2, b2, hh);
    // 6) ffh = gelu(h @ W1^T + b1m) (fp16 out)
    gemm_mma<true, false, true><<<dim3(FFD / 128, TOK / 128), 256, GEMM_SMEM>>>(
        hh, wh + W1_OFF, b1m, nullptr,
        nullptr, fh, TOK, FFD, DMODEL);
    // 7) out = x1 + ffh @ W2^T + b2m (fp32 out)
    gemm_mma<false, true, false><<<dim3(DMODEL / 128, TOK / 128), 256, GEMM_SMEM>>>(
        fh, wh + W2_OFF, b2m, x1,
        out, nullptr, TOK, DMODEL, FFD);
}